// round 10
// baseline (speedup 1.0000x reference)
#include <cuda_runtime.h>
#include <cuda_bf16.h>
#include <mma.h>
#include <cstdint>

using namespace nvcuda;

// Problem constants
#define BB 2
#define NN 2048
#define NP 2000
#define NREL 8192
#define BNR 16384
#define NODES 4096
#define NF 128

// ---------------- scratch ---------------------------------------------------
__device__ float          g_pin_f[NODES*19];
__device__ __nv_bfloat16  g_pEnc[NODES*NF];
__device__ __nv_bfloat16  g_pEff[NODES*NF];
__device__ __nv_bfloat16  g_relE[BNR*NF];
__device__ __nv_bfloat16  g_aggH[NODES*NF];
__device__ int            g_rr[BNR];
__device__ int            g_rs[BNR];
__device__ __nv_bfloat16  g_wbuf[1504*128];

// weight row offsets inside g_wbuf
#define WO_PE0 0
#define WO_PE1 32
#define WO_PE2 160
#define WO_RE0 288
#define WO_RE1 352
#define WO_RE2 480
#define WO_PP  608
#define WO_RP  864
#define WO_NP0 1248
#define WO_NP1 1376
#define W_TOTAL_ROWS 1504

// ---------------- helpers ---------------------------------------------------
__device__ __forceinline__ uint32_t pack_bf2(float a, float b) {
    __nv_bfloat162 h = __floats2bfloat162_rn(a, b);
    return *reinterpret_cast<uint32_t*>(&h);
}
__device__ __forceinline__ float2 unpack_bf2(uint32_t u) {
    __nv_bfloat162 h = *reinterpret_cast<__nv_bfloat162*>(&u);
    return make_float2(__bfloat162float(h.x), __bfloat162float(h.y));
}
__device__ __forceinline__ void cpa16(uint32_t d, const void* s) {
    asm volatile("cp.async.cg.shared.global [%0], [%1], 16;" :: "r"(d), "l"(s));
}
__device__ __forceinline__ void cpa8(uint32_t d, const void* s) {
    asm volatile("cp.async.ca.shared.global [%0], [%1], 8;" :: "r"(d), "l"(s));
}
__device__ __forceinline__ void cpa4(uint32_t d, const void* s) {
    asm volatile("cp.async.ca.shared.global [%0], [%1], 4;" :: "r"(d), "l"(s));
}
__device__ __forceinline__ void cp_commit() {
    asm volatile("cp.async.commit_group;" ::: "memory");
}
__device__ __forceinline__ void cp_wait1() {
    asm volatile("cp.async.wait_group 1;" ::: "memory");
}
__device__ __forceinline__ void cp_wait0() {
    asm volatile("cp.async.wait_group 0;" ::: "memory");
}

// ---------------- weight conversion args ------------------------------------
struct WConvArgs {
    const float* src[10];
    int rowStart[10];
    int srcRows[10];
};

// =====================  prep kernel: convert + build_pin + extract ==========
// blocks 0..15: build_pin; blocks 16..203: convert_w; ALL blocks: extract.
__global__ void prep_k(const float* __restrict__ Rr, const float* __restrict__ Rs,
                       int* __restrict__ rr, int* __restrict__ rs,
                       const float* __restrict__ state, const float* __restrict__ attrs,
                       const float* __restrict__ action, const float* __restrict__ pden,
                       const float* __restrict__ phys, float* __restrict__ pf,
                       WConvArgs wa, __nv_bfloat16* __restrict__ wbuf) {
    int bid = blockIdx.x, tid = threadIdx.x;

    if (bid < 16) {
        // build_pin: NODES = 16*256 exact
        int i = bid * 256 + tid;
        int b = i / NN, n = i - b * NN;
        float o[19];
        o[0] = attrs[i * 2 + 0];
        o[1] = attrs[i * 2 + 1];
        float s[4][3];
#pragma unroll
        for (int t = 0; t < 4; t++)
#pragma unroll
            for (int k = 0; k < 3; k++)
                s[t][k] = state[((size_t)(b * 4 + t) * NN + n) * 3 + k];
#pragma unroll
        for (int t = 0; t < 3; t++)
#pragma unroll
            for (int k = 0; k < 3; k++)
                o[2 + t * 3 + k] = s[t + 1][k] - s[t][k];
#pragma unroll
        for (int k = 0; k < 3; k++) o[11 + k] = s[3][k];
        bool isP = (n < NP);
        o[14] = isP ? phys[b] : 0.f;
#pragma unroll
        for (int k = 0; k < 3; k++) o[15 + k] = action[(size_t)i * 3 + k];
        o[18] = isP ? pden[b] : 0.f;
#pragma unroll
        for (int k = 0; k < 19; k++) pf[(size_t)i * 19 + k] = o[k];
    } else if (bid < 204) {
        // convert_w: 1504*128 = 192512 = 188*1024 exact
        int base = (bid - 16) * 1024;
        for (int k = tid; k < 1024; k += 256) {
            int e = base + k;
            int row = e >> 7, col = e & 127;
            int seg = 0;
#pragma unroll
            for (int i = 1; i < 10; i++) if (row >= wa.rowStart[i]) seg = i;
            int r = row - wa.rowStart[seg];
            float v = (r < wa.srcRows[seg]) ? wa.src[seg][r * 128 + col] : 0.f;
            wbuf[row * 128 + col] = __float2bfloat16(v);
        }
    }

    // extract (all 4096 blocks x 8 warps = 32768 row-warps)
    int gw = bid * 8 + (tid >> 5);
    int lane = tid & 31;
    const float* src = (gw < BNR) ? Rr : Rs;
    int row = (gw < BNR) ? gw : gw - BNR;
    const float4* p = reinterpret_cast<const float4*>(src + (size_t)row * NN);
    int found = -1;
    for (int i = 0; i < NN / 128; i++) {
        float4 v = __ldcs(&p[i * 32 + lane]);
        int base = i * 128 + lane * 4;
        if (v.x != 0.f) found = base;
        if (v.y != 0.f) found = base + 1;
        if (v.z != 0.f) found = base + 2;
        if (v.w != 0.f) found = base + 3;
        if (__ballot_sync(0xffffffffu, found >= 0)) break;   // one-hot: done
    }
#pragma unroll
    for (int off = 16; off; off >>= 1)
        found = max(found, __shfl_xor_sync(0xffffffffu, found, off));
    if (lane == 0) {
        int b = row / NREL;
        ((gw < BNR) ? rr : rs)[row] = b * NN + found;
    }
}

// ============  fused 3-layer encoder MLP with inline A build  ===============
#define ENC_WROWS 320
#define ENC_W_BYTES (ENC_WROWS*136*2)              // 87040
#define ENC_BIAS_OFF ENC_W_BYTES
#define ENC_ACT_OFF (ENC_BIAS_OFF + 3*128*4)       // 88576
#define ENC_CS_OFF  (ENC_ACT_OFF + 64*136*2)       // 105984
#define ENC_SMEM    (ENC_CS_OFF + 64*132*4)        // 139776

struct EncArgs {
    const float *pf, *attrs, *pinst;
    const int *rr, *rs;
    const __nv_bfloat16* wbuf;
    const float *pe_b0, *pe_b1, *pe_b2, *re_b0, *re_b1, *re_b2;
    __nv_bfloat16 *pEnc, *pEff, *relE, *aggH;
};

__global__ void __launch_bounds__(256) encmlp_k(EncArgs a) {
    extern __shared__ char sm[];
    __nv_bfloat16* Wsm  = (__nv_bfloat16*)sm;
    float* biasm        = (float*)(sm + ENC_BIAS_OFF);
    __nv_bfloat16* Act  = (__nv_bfloat16*)(sm + ENC_ACT_OFF);
    float* Cs           = (float*)(sm + ENC_CS_OFF);
    int tid = threadIdx.x, wid = tid >> 5;
    int wm = wid & 3, wn = wid >> 2;
    int t = blockIdx.x;
    bool particle = (t < 64);
    int K0 = particle ? 32 : 64;
    int rowBase = particle ? t * 64 : (t - 64) * 64;

    {
        const __nv_bfloat16 *W0, *W1, *W2;
        const float *b0, *b1, *b2;
        if (particle) {
            W0 = a.wbuf + WO_PE0 * 128; W1 = a.wbuf + WO_PE1 * 128; W2 = a.wbuf + WO_PE2 * 128;
            b0 = a.pe_b0; b1 = a.pe_b1; b2 = a.pe_b2;
        } else {
            W0 = a.wbuf + WO_RE0 * 128; W1 = a.wbuf + WO_RE1 * 128; W2 = a.wbuf + WO_RE2 * 128;
            b0 = a.re_b0; b1 = a.re_b1; b2 = a.re_b2;
        }
        for (int idx = tid; idx < (K0 + 256) * 16; idx += 256) {
            int r = idx >> 4, c8 = (idx & 15) * 8;
            const __nv_bfloat16* src;
            if (r < K0)            src = W0 + (size_t)r * 128 + c8;
            else if (r < K0 + 128) src = W1 + (size_t)(r - K0) * 128 + c8;
            else                   src = W2 + (size_t)(r - K0 - 128) * 128 + c8;
            *(uint4*)&Wsm[r * 136 + c8] = *(const uint4*)src;
        }
        for (int i = tid; i < 128; i += 256) {
            biasm[i] = b0[i]; biasm[128 + i] = b1[i]; biasm[256 + i] = b2[i];
        }
    }

    // build A inline into Act
    if (particle) {
        for (int idx = tid; idx < 64 * 32; idx += 256) {
            int r = idx >> 5, k = idx & 31;
            float v = (k < 19) ? a.pf[(size_t)(rowBase + r) * 19 + k] : 0.f;
            Act[r * 136 + k] = __float2bfloat16(v);
        }
    } else {
        for (int idx = tid; idx < 64 * 64; idx += 256) {
            int r = idx >> 6, k = idx & 63;
            int e = rowBase + r;
            int gr = a.rr[e], gs = a.rs[e];
            float v;
            if (k < 19)       v = a.pf[(size_t)gr * 19 + k];
            else if (k < 38)  v = a.pf[(size_t)gs * 19 + (k - 19)];
            else if (k < 40)  v = a.attrs[gr * 2 + (k - 38)];
            else if (k < 42)  v = a.attrs[gs * 2 + (k - 40)];
            else if (k == 42) {
                int b = e / NREL;
                int ir = gr & (NN - 1), is_ = gs & (NN - 1);
                float gd = 0.f;
#pragma unroll
                for (int j = 0; j < 8; j++) {
                    float x = (ir < NP) ? a.pinst[((size_t)b * NP + ir) * 8 + j] : 0.f;
                    float c = (is_ < NP) ? a.pinst[((size_t)b * NP + is_) * 8 + j] : 0.f;
                    gd += fabsf(x - c);
                }
                v = gd;
            }
            else if (k < 55)  v = a.pf[(size_t)gr * 19 + 2 + (k - 43)]
                                - a.pf[(size_t)gs * 19 + 2 + (k - 43)];
            else if (k == 55) v = a.pf[(size_t)gr * 19 + 18] - a.pf[(size_t)gs * 19 + 18];
            else              v = 0.f;
            Act[r * 136 + k] = __float2bfloat16(v);
        }
    }
    __syncthreads();

    for (int L = 0; L < 3; L++) {
        int KL = (L == 0) ? K0 : 128;
        const __nv_bfloat16* WL = Wsm + (size_t)((L == 0) ? 0 : K0 + (L - 1) * 128) * 136;
        wmma::fragment<wmma::accumulator, 16, 16, 16, float> acc[4];
#pragma unroll
        for (int nf = 0; nf < 4; nf++) wmma::fill_fragment(acc[nf], 0.f);
        for (int kc = 0; kc < KL / 16; kc++) {
            wmma::fragment<wmma::matrix_a, 16, 16, 16, __nv_bfloat16, wmma::row_major> af;
            wmma::load_matrix_sync(af, Act + (wm * 16) * 136 + kc * 16, 136);
#pragma unroll
            for (int nf = 0; nf < 4; nf++) {
                wmma::fragment<wmma::matrix_b, 16, 16, 16, __nv_bfloat16, wmma::row_major> bf;
                wmma::load_matrix_sync(bf, WL + (kc * 16) * 136 + wn * 64 + nf * 16, 136);
                wmma::mma_sync(acc[nf], af, bf, acc[nf]);
            }
        }
#pragma unroll
        for (int nf = 0; nf < 4; nf++)
            wmma::store_matrix_sync(Cs + (wm * 16) * 132 + wn * 64 + nf * 16,
                                    acc[nf], 132, wmma::mem_row_major);
        __syncthreads();
        const float* bL = biasm + L * 128;
#pragma unroll
        for (int it = 0; it < 8; it++) {
            int e = tid + it * 256, row = e >> 5, c4 = (e & 31) * 4;
            float4 v = *(float4*)&Cs[row * 132 + c4];
            float4 b = *(const float4*)&bL[c4];
            v.x = fmaxf(v.x + b.x, 0.f); v.y = fmaxf(v.y + b.y, 0.f);
            v.z = fmaxf(v.z + b.z, 0.f); v.w = fmaxf(v.w + b.w, 0.f);
            uint2 o; o.x = pack_bf2(v.x, v.y); o.y = pack_bf2(v.z, v.w);
            if (L < 2) {
                *(uint2*)&Act[row * 136 + c4] = o;
            } else {
                size_t go = (size_t)(rowBase + row) * 128 + c4;
                if (particle) {
                    *(uint2*)&a.pEnc[go] = o;
                    *(uint2*)&a.pEff[go] = o;
                    *(uint2*)&a.aggH[go] = make_uint2(0u, 0u);
                } else {
                    *(uint2*)&a.relE[go] = o;
                }
            }
        }
        __syncthreads();
    }
}

// =============  relation propagator: N-split pipelined GEMM  ================
// Output tile = 64 x 64; blockIdx.x = tile*2 + half; grid 512.
// A = [relE | pEff[rr] | pEff[rs]] (K=384, read-only this launch);
// epi = relu(+bias) -> atomicAdd bf16x2 into aggH[rr], columns [half*64, +64).
// Halves are column-disjoint; no write/read hazard.
__global__ void __launch_bounds__(256) relprop_k(
    const __nv_bfloat16* __restrict__ relE,
    const __nv_bfloat16* __restrict__ pEff,
    const __nv_bfloat16* __restrict__ W,
    const float* __restrict__ bias,
    __nv_bfloat16* __restrict__ aggH,
    const int* __restrict__ rr, const int* __restrict__ rs)
{
    constexpr int WLD = 72;                  // Ws stride (64+8)
    constexpr int CLD = 68;                  // Cs stride (64+4)

    __shared__ union {
        struct {
            __nv_bfloat16 As[2][64 * 24];    // 6144 B
            __nv_bfloat16 Ws[2][16 * WLD];   // 4608 B
        } s;
        float Cs[64 * CLD];                  // 17408 B
    } u;
    __shared__ int   idxs[128];
    __shared__ float biasm[64];

    int tid = threadIdx.x, wid = tid >> 5;
    int wm = wid & 3, wn = wid >> 2;         // 4 row-warps x 2 col-warps
    int t = blockIdx.x >> 1, half = blockIdx.x & 1;
    int rowBase = t * 64;
    int colBase = half * 64;

    if (tid < 64)       idxs[tid] = rr[rowBase + tid];
    else if (tid < 128) idxs[tid] = rs[rowBase + tid - 64];
    if (tid < 64) biasm[tid] = bias[colBase + tid];

    int arow = tid >> 2, acol = (tid & 3) * 4;      // 64 x 16 A tile, 4 bf16/thr
    int wrow = tid >> 4, wcol = (tid & 15) * 4;     // 16 x 64 W tile, 4 bf16/thr

    uint32_t asB = (uint32_t)__cvta_generic_to_shared(&u.s.As[0][0]);
    uint32_t wsB = (uint32_t)__cvta_generic_to_shared(&u.s.Ws[0][0]);

    auto stage = [&](int kt, int buf) {
        int kg = kt * 16 + acol;
        const __nv_bfloat16* src;
        if (kg < 128)      src = relE + (size_t)(rowBase + arow) * 128 + kg;
        else if (kg < 256) src = pEff + (size_t)idxs[arow] * 128 + (kg - 128);
        else               src = pEff + (size_t)idxs[64 + arow] * 128 + (kg - 256);
        cpa8(asB + (uint32_t)(buf * 64 * 24 + arow * 24 + acol) * 2, src);
        cpa8(wsB + (uint32_t)(buf * 16 * WLD + wrow * WLD + wcol) * 2,
             W + (size_t)(kt * 16 + wrow) * 128 + colBase + wcol);
    };

    wmma::fragment<wmma::accumulator, 16, 16, 16, float> acc[2];
#pragma unroll
    for (int nf = 0; nf < 2; nf++) wmma::fill_fragment(acc[nf], 0.f);

    stage(0, 0); cp_commit();
    for (int kt = 0; kt < 24; kt++) {
        if (kt + 1 < 24) { stage(kt + 1, (kt + 1) & 1); cp_commit(); cp_wait1(); }
        else             { cp_wait0(); }
        __syncthreads();
        int buf = kt & 1;
        wmma::fragment<wmma::matrix_a, 16, 16, 16, __nv_bfloat16, wmma::row_major> af;
        wmma::load_matrix_sync(af, &u.s.As[buf][wm * 16 * 24], 24);
#pragma unroll
        for (int nf = 0; nf < 2; nf++) {
            wmma::fragment<wmma::matrix_b, 16, 16, 16, __nv_bfloat16, wmma::row_major> bf;
            wmma::load_matrix_sync(bf, &u.s.Ws[buf][wn * 32 + nf * 16], WLD);
            wmma::mma_sync(acc[nf], af, bf, acc[nf]);
        }
        __syncthreads();
    }

#pragma unroll
    for (int nf = 0; nf < 2; nf++)
        wmma::store_matrix_sync(&u.Cs[(wm * 16) * CLD + wn * 32 + nf * 16],
                                acc[nf], CLD, wmma::mem_row_major);
    __syncthreads();
#pragma unroll
    for (int it = 0; it < 4; it++) {
        int e = tid + it * 256, row = e >> 4, c4 = (e & 15) * 4;
        float4 v = *(float4*)&u.Cs[row * CLD + c4];
        float4 b = *(const float4*)&biasm[c4];
        __nv_bfloat162* dst =
            (__nv_bfloat162*)(aggH + (size_t)idxs[row] * 128 + colBase + c4);
        atomicAdd(dst,     __floats2bfloat162_rn(fmaxf(v.x + b.x, 0.f),
                                                 fmaxf(v.y + b.y, 0.f)));
        atomicAdd(dst + 1, __floats2bfloat162_rn(fmaxf(v.z + b.z, 0.f),
                                                 fmaxf(v.w + b.w, 0.f)));
    }
}

// =============  particle propagator (R7-proven, full N=128, BM=32) ==========
// A = [pEnc | aggH] (K=256); epi = relu(acc+bias+pEff[row]) -> pEff;
// re-zero aggH rows (row-exclusive: this block is the only reader/writer).
__global__ void __launch_bounds__(256) partprop_k(
    const __nv_bfloat16* __restrict__ pEnc,
    const __nv_bfloat16* __restrict__ aggIn,
    const __nv_bfloat16* __restrict__ W,
    const float* __restrict__ bias,
    __nv_bfloat16* __restrict__ pEff,
    __nv_bfloat16* __restrict__ aggZ)
{
    __shared__ union {
        struct {
            __nv_bfloat16 As[2][32 * 24];
            __nv_bfloat16 Ws[2][16 * 136];
        } s;
        float Cs[32 * 132];
    } u;
    __shared__ float biasm[128];

    int tid = threadIdx.x, wid = tid >> 5;
    int wm = wid & 1, wn = wid >> 1;         // 2 row-warps x 4 col-warps
    int rowBase = blockIdx.x * 32;

    if (tid < 128) biasm[tid] = bias[tid];

    int arow = tid >> 3, acol = (tid & 7) * 2;
    int wrow = tid >> 4, wcol = (tid & 15) * 8;

    uint32_t asB = (uint32_t)__cvta_generic_to_shared(&u.s.As[0][0]);
    uint32_t wsB = (uint32_t)__cvta_generic_to_shared(&u.s.Ws[0][0]);

    auto stage = [&](int kt, int buf) {
        int kg = kt * 16 + acol;
        const __nv_bfloat16* src;
        if (kg < 128) src = pEnc  + (size_t)(rowBase + arow) * 128 + kg;
        else          src = aggIn + (size_t)(rowBase + arow) * 128 + (kg - 128);
        cpa4(asB + (uint32_t)(buf * 32 * 24 + arow * 24 + acol) * 2, src);
        cpa16(wsB + (uint32_t)(buf * 16 * 136 + wrow * 136 + wcol) * 2,
              W + (size_t)(kt * 16 + wrow) * 128 + wcol);
    };

    wmma::fragment<wmma::accumulator, 16, 16, 16, float> acc[2];
#pragma unroll
    for (int nf = 0; nf < 2; nf++) wmma::fill_fragment(acc[nf], 0.f);

    stage(0, 0); cp_commit();
    for (int kt = 0; kt < 16; kt++) {
        if (kt + 1 < 16) { stage(kt + 1, (kt + 1) & 1); cp_commit(); cp_wait1(); }
        else             { cp_wait0(); }
        __syncthreads();
        int buf = kt & 1;
        wmma::fragment<wmma::matrix_a, 16, 16, 16, __nv_bfloat16, wmma::row_major> af;
        wmma::load_matrix_sync(af, &u.s.As[buf][wm * 16 * 24], 24);
#pragma unroll
        for (int nf = 0; nf < 2; nf++) {
            wmma::fragment<wmma::matrix_b, 16, 16, 16, __nv_bfloat16, wmma::row_major> bf;
            wmma::load_matrix_sync(bf, &u.s.Ws[buf][wn * 32 + nf * 16], 136);
            wmma::mma_sync(acc[nf], af, bf, acc[nf]);
        }
        __syncthreads();
    }

#pragma unroll
    for (int nf = 0; nf < 2; nf++)
        wmma::store_matrix_sync(&u.Cs[(wm * 16) * 132 + wn * 32 + nf * 16],
                                acc[nf], 132, wmma::mem_row_major);
    __syncthreads();
#pragma unroll
    for (int it = 0; it < 4; it++) {
        int e = tid + it * 256, row = e >> 5, c4 = (e & 31) * 4;
        size_t go = (size_t)(rowBase + row) * 128 + c4;
        float4 v = *(float4*)&u.Cs[row * 132 + c4];
        float4 b = *(const float4*)&biasm[c4];
        uint2 rv = *(const uint2*)&pEff[go];
        float2 r0 = unpack_bf2(rv.x), r1 = unpack_bf2(rv.y);
        v.x = fmaxf(v.x + b.x + r0.x, 0.f);
        v.y = fmaxf(v.y + b.y + r0.y, 0.f);
        v.z = fmaxf(v.z + b.z + r1.x, 0.f);
        v.w = fmaxf(v.w + b.w + r1.y, 0.f);
        uint2 o; o.x = pack_bf2(v.x, v.y); o.y = pack_bf2(v.z, v.w);
        *(uint2*)&pEff[go] = o;
        *(uint2*)&aggZ[go] = make_uint2(0u, 0u);   // re-zero for next step
    }
}

// =====================  fused head: np0 + np1 + np2 + clamp + add ===========
#define HD_BIAS_OFF (256*136*2)                    // 69632
#define HD_W2_OFF   (HD_BIAS_OFF + 2*128*4)        // 70656
#define HD_B2_OFF   (HD_W2_OFF + 384*4)            // 72192
#define HD_ACT_OFF  (HD_B2_OFF + 16)               // 72208
#define HD_CS_OFF   (HD_ACT_OFF + 64*136*2)        // 89616
#define HD_SMEM     (HD_CS_OFF + 64*132*4)         // 123408

__global__ void __launch_bounds__(256) head_k(
    const __nv_bfloat16* __restrict__ pEff,
    const __nv_bfloat16* __restrict__ W0, const __nv_bfloat16* __restrict__ W1,
    const float* __restrict__ b0, const float* __restrict__ b1,
    const float* __restrict__ W2, const float* __restrict__ b2,
    const float* __restrict__ state, float* __restrict__ out)
{
    extern __shared__ char smraw[];
    __nv_bfloat16* Wsm  = (__nv_bfloat16*)smraw;
    float* biasm        = (float*)(smraw + HD_BIAS_OFF);
    float* W2s          = (float*)(smraw + HD_W2_OFF);
    float* b2s          = (float*)(smraw + HD_B2_OFF);
    __nv_bfloat16* Act  = (__nv_bfloat16*)(smraw + HD_ACT_OFF);
    float* Cs           = (float*)(smraw + HD_CS_OFF);
    int tid = threadIdx.x, wid = tid >> 5, lane = tid & 31;
    int wm = wid & 3, wn = wid >> 2;
    int rowBase = blockIdx.x * 64;

    for (int idx = tid; idx < 256 * 16; idx += 256) {
        int r = idx >> 4, c8 = (idx & 15) * 8;
        const __nv_bfloat16* src = (r < 128) ? W0 + (size_t)r * 128 + c8
                                             : W1 + (size_t)(r - 128) * 128 + c8;
        *(uint4*)&Wsm[r * 136 + c8] = *(const uint4*)src;
    }
    for (int i = tid; i < 128; i += 256) { biasm[i] = b0[i]; biasm[128 + i] = b1[i]; }
    for (int i = tid; i < 384; i += 256) W2s[i] = W2[i];
    if (tid < 3) b2s[tid] = b2[tid];
    for (int idx = tid; idx < 64 * 16; idx += 256) {
        int r = idx >> 4, c8 = (idx & 15) * 8;
        *(uint4*)&Act[r * 136 + c8] =
            *(const uint4*)(pEff + (size_t)(rowBase + r) * 128 + c8);
    }
    __syncthreads();

    for (int L = 0; L < 2; L++) {
        const __nv_bfloat16* WL = Wsm + (size_t)L * 128 * 136;
        wmma::fragment<wmma::accumulator, 16, 16, 16, float> acc[4];
#pragma unroll
        for (int nf = 0; nf < 4; nf++) wmma::fill_fragment(acc[nf], 0.f);
#pragma unroll
        for (int kc = 0; kc < 8; kc++) {
            wmma::fragment<wmma::matrix_a, 16, 16, 16, __nv_bfloat16, wmma::row_major> af;
            wmma::load_matrix_sync(af, Act + (wm * 16) * 136 + kc * 16, 136);
#pragma unroll
            for (int nf = 0; nf < 4; nf++) {
                wmma::fragment<wmma::matrix_b, 16, 16, 16, __nv_bfloat16, wmma::row_major> bf;
                wmma::load_matrix_sync(bf, WL + (kc * 16) * 136 + wn * 64 + nf * 16, 136);
                wmma::mma_sync(acc[nf], af, bf, acc[nf]);
            }
        }
#pragma unroll
        for (int nf = 0; nf < 4; nf++)
            wmma::store_matrix_sync(Cs + (wm * 16) * 132 + wn * 64 + nf * 16,
                                    acc[nf], 132, wmma::mem_row_major);
        __syncthreads();
        const float* bL = biasm + L * 128;
#pragma unroll
        for (int it = 0; it < 8; it++) {
            int e = tid + it * 256, row = e >> 5, c4 = (e & 31) * 4;
            float4 v = *(float4*)&Cs[row * 132 + c4];
            float4 b = *(const float4*)&bL[c4];
            uint2 o;
            o.x = pack_bf2(fmaxf(v.x + b.x, 0.f), fmaxf(v.y + b.y, 0.f));
            o.y = pack_bf2(fmaxf(v.z + b.z, 0.f), fmaxf(v.w + b.w, 0.f));
            *(uint2*)&Act[row * 136 + c4] = o;
        }
        __syncthreads();
    }

    // final 128->3, clamp, add last position
#pragma unroll
    for (int i = 0; i < 8; i++) {
        int row = wid * 8 + i;
        int grow = rowBase + row;
        int b = grow >> 11, n = grow & (NN - 1);
        float hv[4];
#pragma unroll
        for (int j = 0; j < 4; j++)
            hv[j] = __bfloat162float(Act[row * 136 + lane + 32 * j]);
#pragma unroll
        for (int k = 0; k < 3; k++) {
            float sacc = 0.f;
#pragma unroll
            for (int j = 0; j < 4; j++)
                sacc += hv[j] * W2s[(lane + 32 * j) * 3 + k];
#pragma unroll
            for (int off = 16; off; off >>= 1)
                sacc += __shfl_xor_sync(0xffffffffu, sacc, off);
            if (lane == 0 && n < NP) {
                float m = fminf(fmaxf(sacc + b2s[k], -100.f), 100.f);
                out[((size_t)b * NP + n) * 3 + k] =
                    state[((size_t)(b * 4 + 3) * NN + n) * 3 + k] + m;
            }
        }
    }
}

// ---------------------------------------------------------------------------
extern "C" void kernel_launch(void* const* d_in, const int* in_sizes, int n_in,
                              void* d_out, int out_size) {
    const float* state  = (const float*)d_in[0];
    const float* attrs  = (const float*)d_in[1];
    const float* Rr     = (const float*)d_in[2];
    const float* Rs     = (const float*)d_in[3];
    const float* pinst  = (const float*)d_in[4];
    const float* action = (const float*)d_in[5];
    const float* pden   = (const float*)d_in[6];
    const float* phys   = (const float*)d_in[7];
    const float* pe_W0 = (const float*)d_in[8],  *pe_b0 = (const float*)d_in[9];
    const float* pe_W1 = (const float*)d_in[10], *pe_b1 = (const float*)d_in[11];
    const float* pe_W2 = (const float*)d_in[12], *pe_b2 = (const float*)d_in[13];
    const float* re_W0 = (const float*)d_in[14], *re_b0 = (const float*)d_in[15];
    const float* re_W1 = (const float*)d_in[16], *re_b1 = (const float*)d_in[17];
    const float* re_W2 = (const float*)d_in[18], *re_b2 = (const float*)d_in[19];
    const float* pp_W  = (const float*)d_in[20], *pp_b  = (const float*)d_in[21];
    const float* rp_W  = (const float*)d_in[22], *rp_b  = (const float*)d_in[23];
    const float* np_W0 = (const float*)d_in[24], *np_b0 = (const float*)d_in[25];
    const float* np_W1 = (const float*)d_in[26], *np_b1 = (const float*)d_in[27];
    const float* np_W2 = (const float*)d_in[28], *np_b2 = (const float*)d_in[29];
    float* out = (float*)d_out;

    float* pin_f;
    __nv_bfloat16 *pEnc, *pEff, *relE, *aggH, *wbuf;
    int *rr, *rs;
    cudaGetSymbolAddress((void**)&pin_f, g_pin_f);
    cudaGetSymbolAddress((void**)&pEnc,  g_pEnc);
    cudaGetSymbolAddress((void**)&pEff,  g_pEff);
    cudaGetSymbolAddress((void**)&relE,  g_relE);
    cudaGetSymbolAddress((void**)&aggH,  g_aggH);
    cudaGetSymbolAddress((void**)&rr,    g_rr);
    cudaGetSymbolAddress((void**)&rs,    g_rs);
    cudaGetSymbolAddress((void**)&wbuf,  g_wbuf);

    cudaFuncSetAttribute(encmlp_k, cudaFuncAttributeMaxDynamicSharedMemorySize, ENC_SMEM);
    cudaFuncSetAttribute(head_k,   cudaFuncAttributeMaxDynamicSharedMemorySize, HD_SMEM);

    WConvArgs wa;
    const float* srcs[10] = {pe_W0, pe_W1, pe_W2, re_W0, re_W1, re_W2,
                             pp_W, rp_W, np_W0, np_W1};
    const int starts[10]  = {WO_PE0, WO_PE1, WO_PE2, WO_RE0, WO_RE1, WO_RE2,
                             WO_PP, WO_RP, WO_NP0, WO_NP1};
    const int srows[10]   = {19, 128, 128, 56, 128, 128, 256, 384, 128, 128};
    for (int i = 0; i < 10; i++) {
        wa.src[i] = srcs[i]; wa.rowStart[i] = starts[i]; wa.srcRows[i] = srows[i];
    }

    // 1) convert weights + build particle features + extract indices
    prep_k<<<4096, 256>>>(Rr, Rs, rr, rs, state, attrs, action, pden, phys,
                          pin_f, wa, wbuf);

    // 2) fused 3-layer encoders with inline feature assembly
    EncArgs ea;
    ea.pf = pin_f; ea.attrs = attrs; ea.pinst = pinst;
    ea.rr = rr; ea.rs = rs; ea.wbuf = wbuf;
    ea.pe_b0 = pe_b0; ea.pe_b1 = pe_b1; ea.pe_b2 = pe_b2;
    ea.re_b0 = re_b0; ea.re_b1 = re_b1; ea.re_b2 = re_b2;
    ea.pEnc = pEnc; ea.pEff = pEff; ea.relE = relE; ea.aggH = aggH;
    encmlp_k<<<320, 256, ENC_SMEM>>>(ea);

    // 3) propagation: 3 steps (relprop N-split grid 512; partprop proven R7)
    for (int step = 0; step < 3; step++) {
        relprop_k<<<(BNR / 64) * 2, 256>>>(relE, pEff, wbuf + WO_RP * 128,
                                           rp_b, aggH, rr, rs);
        partprop_k<<<NODES / 32, 256>>>(pEnc, aggH, wbuf + WO_PP * 128,
                                        pp_b, pEff, aggH);
    }

    // 4) fused head
    head_k<<<NODES / 64, 256, HD_SMEM>>>(pEff, wbuf + WO_NP0 * 128,
                                         wbuf + WO_NP1 * 128, np_b0, np_b1,
                                         np_W2, np_b2, state, out);
}

// round 11
// speedup vs baseline: 1.0870x; 1.0870x over previous
#include <cuda_runtime.h>
#include <cuda_bf16.h>
#include <mma.h>
#include <cstdint>

using namespace nvcuda;

// Problem constants
#define BB 2
#define NN 2048
#define NP 2000
#define NREL 8192
#define BNR 16384
#define NODES 4096
#define NF 128

// ---------------- scratch ---------------------------------------------------
__device__ float          g_pin_f[NODES*19];
__device__ __nv_bfloat16  g_pEnc[NODES*NF];
__device__ __nv_bfloat16  g_pEff[NODES*NF];
__device__ __nv_bfloat16  g_relE[BNR*NF];
__device__ __nv_bfloat16  g_aggH[NODES*NF];
__device__ int            g_rr[BNR];
__device__ int            g_rs[BNR];
__device__ __nv_bfloat16  g_wbuf[1504*128];

// weight row offsets inside g_wbuf
#define WO_PE0 0
#define WO_PE1 32
#define WO_PE2 160
#define WO_RE0 288
#define WO_RE1 352
#define WO_RE2 480
#define WO_PP  608
#define WO_RP  864
#define WO_NP0 1248
#define WO_NP1 1376
#define W_TOTAL_ROWS 1504

// ---------------- helpers ---------------------------------------------------
__device__ __forceinline__ uint32_t pack_bf2(float a, float b) {
    __nv_bfloat162 h = __floats2bfloat162_rn(a, b);
    return *reinterpret_cast<uint32_t*>(&h);
}
__device__ __forceinline__ float2 unpack_bf2(uint32_t u) {
    __nv_bfloat162 h = *reinterpret_cast<__nv_bfloat162*>(&u);
    return make_float2(__bfloat162float(h.x), __bfloat162float(h.y));
}
__device__ __forceinline__ void cpa16(uint32_t d, const void* s) {
    asm volatile("cp.async.cg.shared.global [%0], [%1], 16;" :: "r"(d), "l"(s));
}
__device__ __forceinline__ void cp_commit() {
    asm volatile("cp.async.commit_group;" ::: "memory");
}
__device__ __forceinline__ void cp_wait0() {
    asm volatile("cp.async.wait_group 0;" ::: "memory");
}

// ---------------- weight conversion args ------------------------------------
struct WConvArgs {
    const float* src[10];
    int rowStart[10];
    int srcRows[10];
};

// =====================  prep kernel: convert + build_pin + extract ==========
__global__ void prep_k(const float* __restrict__ Rr, const float* __restrict__ Rs,
                       int* __restrict__ rr, int* __restrict__ rs,
                       const float* __restrict__ state, const float* __restrict__ attrs,
                       const float* __restrict__ action, const float* __restrict__ pden,
                       const float* __restrict__ phys, float* __restrict__ pf,
                       WConvArgs wa, __nv_bfloat16* __restrict__ wbuf) {
    int bid = blockIdx.x, tid = threadIdx.x;

    if (bid < 16) {
        int i = bid * 256 + tid;
        int b = i / NN, n = i - b * NN;
        float o[19];
        o[0] = attrs[i * 2 + 0];
        o[1] = attrs[i * 2 + 1];
        float s[4][3];
#pragma unroll
        for (int t = 0; t < 4; t++)
#pragma unroll
            for (int k = 0; k < 3; k++)
                s[t][k] = state[((size_t)(b * 4 + t) * NN + n) * 3 + k];
#pragma unroll
        for (int t = 0; t < 3; t++)
#pragma unroll
            for (int k = 0; k < 3; k++)
                o[2 + t * 3 + k] = s[t + 1][k] - s[t][k];
#pragma unroll
        for (int k = 0; k < 3; k++) o[11 + k] = s[3][k];
        bool isP = (n < NP);
        o[14] = isP ? phys[b] : 0.f;
#pragma unroll
        for (int k = 0; k < 3; k++) o[15 + k] = action[(size_t)i * 3 + k];
        o[18] = isP ? pden[b] : 0.f;
#pragma unroll
        for (int k = 0; k < 19; k++) pf[(size_t)i * 19 + k] = o[k];
    } else if (bid < 204) {
        int base = (bid - 16) * 1024;
        for (int k = tid; k < 1024; k += 256) {
            int e = base + k;
            int row = e >> 7, col = e & 127;
            int seg = 0;
#pragma unroll
            for (int i = 1; i < 10; i++) if (row >= wa.rowStart[i]) seg = i;
            int r = row - wa.rowStart[seg];
            float v = (r < wa.srcRows[seg]) ? wa.src[seg][r * 128 + col] : 0.f;
            wbuf[row * 128 + col] = __float2bfloat16(v);
        }
    }

    // extract (all 4096 blocks x 8 warps = 32768 row-warps)
    int gw = bid * 8 + (tid >> 5);
    int lane = tid & 31;
    const float* src = (gw < BNR) ? Rr : Rs;
    int row = (gw < BNR) ? gw : gw - BNR;
    const float4* p = reinterpret_cast<const float4*>(src + (size_t)row * NN);
    int found = -1;
    for (int i = 0; i < NN / 128; i++) {
        float4 v = __ldcs(&p[i * 32 + lane]);
        int base = i * 128 + lane * 4;
        if (v.x != 0.f) found = base;
        if (v.y != 0.f) found = base + 1;
        if (v.z != 0.f) found = base + 2;
        if (v.w != 0.f) found = base + 3;
        if (__ballot_sync(0xffffffffu, found >= 0)) break;   // one-hot: done
    }
#pragma unroll
    for (int off = 16; off; off >>= 1)
        found = max(found, __shfl_xor_sync(0xffffffffu, found, off));
    if (lane == 0) {
        int b = row / NREL;
        ((gw < BNR) ? rr : rs)[row] = b * NN + found;
    }
}

// ============  fused 3-layer encoder MLP with inline A build  ===============
#define ENC_WROWS 320
#define ENC_W_BYTES (ENC_WROWS*136*2)              // 87040
#define ENC_BIAS_OFF ENC_W_BYTES
#define ENC_ACT_OFF (ENC_BIAS_OFF + 3*128*4)       // 88576
#define ENC_CS_OFF  (ENC_ACT_OFF + 64*136*2)       // 105984
#define ENC_SMEM    (ENC_CS_OFF + 64*132*4)        // 139776

struct EncArgs {
    const float *pf, *attrs, *pinst;
    const int *rr, *rs;
    const __nv_bfloat16* wbuf;
    const float *pe_b0, *pe_b1, *pe_b2, *re_b0, *re_b1, *re_b2;
    __nv_bfloat16 *pEnc, *pEff, *relE, *aggH;
};

__global__ void __launch_bounds__(256) encmlp_k(EncArgs a) {
    extern __shared__ char sm[];
    __nv_bfloat16* Wsm  = (__nv_bfloat16*)sm;
    float* biasm        = (float*)(sm + ENC_BIAS_OFF);
    __nv_bfloat16* Act  = (__nv_bfloat16*)(sm + ENC_ACT_OFF);
    float* Cs           = (float*)(sm + ENC_CS_OFF);
    int tid = threadIdx.x, wid = tid >> 5;
    int wm = wid & 3, wn = wid >> 2;
    int t = blockIdx.x;
    bool particle = (t < 64);
    int K0 = particle ? 32 : 64;
    int rowBase = particle ? t * 64 : (t - 64) * 64;

    {
        const __nv_bfloat16 *W0, *W1, *W2;
        const float *b0, *b1, *b2;
        if (particle) {
            W0 = a.wbuf + WO_PE0 * 128; W1 = a.wbuf + WO_PE1 * 128; W2 = a.wbuf + WO_PE2 * 128;
            b0 = a.pe_b0; b1 = a.pe_b1; b2 = a.pe_b2;
        } else {
            W0 = a.wbuf + WO_RE0 * 128; W1 = a.wbuf + WO_RE1 * 128; W2 = a.wbuf + WO_RE2 * 128;
            b0 = a.re_b0; b1 = a.re_b1; b2 = a.re_b2;
        }
        for (int idx = tid; idx < (K0 + 256) * 16; idx += 256) {
            int r = idx >> 4, c8 = (idx & 15) * 8;
            const __nv_bfloat16* src;
            if (r < K0)            src = W0 + (size_t)r * 128 + c8;
            else if (r < K0 + 128) src = W1 + (size_t)(r - K0) * 128 + c8;
            else                   src = W2 + (size_t)(r - K0 - 128) * 128 + c8;
            *(uint4*)&Wsm[r * 136 + c8] = *(const uint4*)src;
        }
        for (int i = tid; i < 128; i += 256) {
            biasm[i] = b0[i]; biasm[128 + i] = b1[i]; biasm[256 + i] = b2[i];
        }
    }

    // build A inline into Act
    if (particle) {
        for (int idx = tid; idx < 64 * 32; idx += 256) {
            int r = idx >> 5, k = idx & 31;
            float v = (k < 19) ? a.pf[(size_t)(rowBase + r) * 19 + k] : 0.f;
            Act[r * 136 + k] = __float2bfloat16(v);
        }
    } else {
        for (int idx = tid; idx < 64 * 64; idx += 256) {
            int r = idx >> 6, k = idx & 63;
            int e = rowBase + r;
            int gr = a.rr[e], gs = a.rs[e];
            float v;
            if (k < 19)       v = a.pf[(size_t)gr * 19 + k];
            else if (k < 38)  v = a.pf[(size_t)gs * 19 + (k - 19)];
            else if (k < 40)  v = a.attrs[gr * 2 + (k - 38)];
            else if (k < 42)  v = a.attrs[gs * 2 + (k - 40)];
            else if (k == 42) {
                int b = e / NREL;
                int ir = gr & (NN - 1), is_ = gs & (NN - 1);
                float gd = 0.f;
#pragma unroll
                for (int j = 0; j < 8; j++) {
                    float x = (ir < NP) ? a.pinst[((size_t)b * NP + ir) * 8 + j] : 0.f;
                    float c = (is_ < NP) ? a.pinst[((size_t)b * NP + is_) * 8 + j] : 0.f;
                    gd += fabsf(x - c);
                }
                v = gd;
            }
            else if (k < 55)  v = a.pf[(size_t)gr * 19 + 2 + (k - 43)]
                                - a.pf[(size_t)gs * 19 + 2 + (k - 43)];
            else if (k == 55) v = a.pf[(size_t)gr * 19 + 18] - a.pf[(size_t)gs * 19 + 18];
            else              v = 0.f;
            Act[r * 136 + k] = __float2bfloat16(v);
        }
    }
    __syncthreads();

    for (int L = 0; L < 3; L++) {
        int KL = (L == 0) ? K0 : 128;
        const __nv_bfloat16* WL = Wsm + (size_t)((L == 0) ? 0 : K0 + (L - 1) * 128) * 136;
        wmma::fragment<wmma::accumulator, 16, 16, 16, float> acc[4];
#pragma unroll
        for (int nf = 0; nf < 4; nf++) wmma::fill_fragment(acc[nf], 0.f);
        for (int kc = 0; kc < KL / 16; kc++) {
            wmma::fragment<wmma::matrix_a, 16, 16, 16, __nv_bfloat16, wmma::row_major> af;
            wmma::load_matrix_sync(af, Act + (wm * 16) * 136 + kc * 16, 136);
#pragma unroll
            for (int nf = 0; nf < 4; nf++) {
                wmma::fragment<wmma::matrix_b, 16, 16, 16, __nv_bfloat16, wmma::row_major> bf;
                wmma::load_matrix_sync(bf, WL + (kc * 16) * 136 + wn * 64 + nf * 16, 136);
                wmma::mma_sync(acc[nf], af, bf, acc[nf]);
            }
        }
#pragma unroll
        for (int nf = 0; nf < 4; nf++)
            wmma::store_matrix_sync(Cs + (wm * 16) * 132 + wn * 64 + nf * 16,
                                    acc[nf], 132, wmma::mem_row_major);
        __syncthreads();
        const float* bL = biasm + L * 128;
#pragma unroll
        for (int it = 0; it < 8; it++) {
            int e = tid + it * 256, row = e >> 5, c4 = (e & 31) * 4;
            float4 v = *(float4*)&Cs[row * 132 + c4];
            float4 b = *(const float4*)&bL[c4];
            v.x = fmaxf(v.x + b.x, 0.f); v.y = fmaxf(v.y + b.y, 0.f);
            v.z = fmaxf(v.z + b.z, 0.f); v.w = fmaxf(v.w + b.w, 0.f);
            uint2 o; o.x = pack_bf2(v.x, v.y); o.y = pack_bf2(v.z, v.w);
            if (L < 2) {
                *(uint2*)&Act[row * 136 + c4] = o;
            } else {
                size_t go = (size_t)(rowBase + row) * 128 + c4;
                if (particle) {
                    *(uint2*)&a.pEnc[go] = o;
                    *(uint2*)&a.pEff[go] = o;
                    *(uint2*)&a.aggH[go] = make_uint2(0u, 0u);
                } else {
                    *(uint2*)&a.relE[go] = o;
                }
            }
        }
        __syncthreads();
    }
}

// =============  relation propagator v2: fully-resident, no mainloop syncs ===
// BM=128, grid 128, 512 threads. A = [relE | pEff[rr] | pEff[rs]] staged whole
// (128 x 392-stride), W (384x136) resident. One sync after load, pure MMA.
// Epilogue: Cs overlays A region; relu(+bias) -> atomicAdd bf16x2 aggH[rr].
#define RPA_LD 392
#define RP2_W_OFF   (128*RPA_LD*2)                 // 100352
#define RP2_IDX_OFF (RP2_W_OFF + 384*136*2)        // 204800
#define RP2_BIAS_OFF (RP2_IDX_OFF + 256*4)         // 205824
#define RP2_SMEM    (RP2_BIAS_OFF + 128*4)         // 206336

__global__ void __launch_bounds__(512) relprop_k(
    const __nv_bfloat16* __restrict__ relE,
    const __nv_bfloat16* __restrict__ pEff,
    const __nv_bfloat16* __restrict__ W,
    const float* __restrict__ bias,
    __nv_bfloat16* __restrict__ aggH,
    const int* __restrict__ rr, const int* __restrict__ rs)
{
    extern __shared__ char sm[];
    __nv_bfloat16* Asm = (__nv_bfloat16*)sm;
    __nv_bfloat16* Wsm = (__nv_bfloat16*)(sm + RP2_W_OFF);
    int*   idxs        = (int*)(sm + RP2_IDX_OFF);
    float* biasm       = (float*)(sm + RP2_BIAS_OFF);
    float* Cs          = (float*)sm;                 // overlay A post-mainloop

    int tid = threadIdx.x, wid = tid >> 5;
    int wm = wid & 7, wn = wid >> 3;                 // 8 row x 2 col warp groups
    int rowBase = blockIdx.x * 128;

    if (tid < 128)      idxs[tid]       = rr[rowBase + tid];
    else if (tid < 256) idxs[tid]       = rs[rowBase + tid - 128];
    if (tid < 128) biasm[tid] = bias[tid];
    __syncthreads();                                 // idxs visible for gather

    uint32_t asB = (uint32_t)__cvta_generic_to_shared(Asm);
    uint32_t wsB = (uint32_t)__cvta_generic_to_shared(Wsm);

    // stage A: 128 rows x 48 16B-chunks (segments: relE | pEff[rr] | pEff[rs])
    for (int c = tid; c < 128 * 48; c += 512) {
        int row = c / 48, ch = c % 48;
        int seg = ch >> 4, off = (ch & 15) * 8;
        const __nv_bfloat16* src;
        if (seg == 0)      src = relE + (size_t)(rowBase + row) * 128 + off;
        else if (seg == 1) src = pEff + (size_t)idxs[row] * 128 + off;
        else               src = pEff + (size_t)idxs[128 + row] * 128 + off;
        cpa16(asB + (uint32_t)(row * RPA_LD + seg * 128 + off) * 2, src);
    }
    // stage W: 384 rows x 16 chunks (stride 136)
    for (int c = tid; c < 384 * 16; c += 512) {
        int row = c >> 4, c8 = (c & 15) * 8;
        cpa16(wsB + (uint32_t)(row * 136 + c8) * 2, W + (size_t)row * 128 + c8);
    }
    cp_commit(); cp_wait0();
    __syncthreads();

    wmma::fragment<wmma::accumulator, 16, 16, 16, float> acc[4];
#pragma unroll
    for (int nf = 0; nf < 4; nf++) wmma::fill_fragment(acc[nf], 0.f);
    for (int kt = 0; kt < 24; kt++) {
        wmma::fragment<wmma::matrix_a, 16, 16, 16, __nv_bfloat16, wmma::row_major> af;
        wmma::load_matrix_sync(af, Asm + (wm * 16) * RPA_LD + kt * 16, RPA_LD);
#pragma unroll
        for (int nf = 0; nf < 4; nf++) {
            wmma::fragment<wmma::matrix_b, 16, 16, 16, __nv_bfloat16, wmma::row_major> bf;
            wmma::load_matrix_sync(bf, Wsm + (kt * 16) * 136 + wn * 64 + nf * 16, 136);
            wmma::mma_sync(acc[nf], af, bf, acc[nf]);
        }
    }
    __syncthreads();                                 // A reads done before overlay
#pragma unroll
    for (int nf = 0; nf < 4; nf++)
        wmma::store_matrix_sync(Cs + (wm * 16) * 132 + wn * 64 + nf * 16,
                                acc[nf], 132, wmma::mem_row_major);
    __syncthreads();
#pragma unroll
    for (int it = 0; it < 8; it++) {
        int e = tid + it * 512, row = e >> 5, c4 = (e & 31) * 4;
        float4 v = *(float4*)&Cs[row * 132 + c4];
        float4 b = *(const float4*)&biasm[c4];
        __nv_bfloat162* dst =
            (__nv_bfloat162*)(aggH + (size_t)idxs[row] * 128 + c4);
        atomicAdd(dst,     __floats2bfloat162_rn(fmaxf(v.x + b.x, 0.f),
                                                 fmaxf(v.y + b.y, 0.f)));
        atomicAdd(dst + 1, __floats2bfloat162_rn(fmaxf(v.z + b.z, 0.f),
                                                 fmaxf(v.w + b.w, 0.f)));
    }
}

// =============  particle propagator v2: fully-resident, no mainloop syncs ===
// BM=32, grid 128, 256 threads. A = [pEnc | aggH] (32x264), W (256x136).
// Epilogue: relu(acc+bias+pEff) -> pEff; re-zero aggH rows (row-exclusive).
#define PPA_LD 264
#define PP2_W_OFF   (32*PPA_LD*2)                  // 16896
#define PP2_BIAS_OFF (PP2_W_OFF + 256*136*2)       // 86528
#define PP2_SMEM    (PP2_BIAS_OFF + 128*4)         // 87040

__global__ void __launch_bounds__(256) partprop_k(
    const __nv_bfloat16* __restrict__ pEnc,
    const __nv_bfloat16* __restrict__ aggIn,
    const __nv_bfloat16* __restrict__ W,
    const float* __restrict__ bias,
    __nv_bfloat16* __restrict__ pEff,
    __nv_bfloat16* __restrict__ aggZ)
{
    extern __shared__ char sm[];
    __nv_bfloat16* Asm = (__nv_bfloat16*)sm;
    __nv_bfloat16* Wsm = (__nv_bfloat16*)(sm + PP2_W_OFF);
    float* biasm       = (float*)(sm + PP2_BIAS_OFF);
    float* Cs          = (float*)sm;                 // overlay A post-mainloop

    int tid = threadIdx.x, wid = tid >> 5;
    int wm = wid & 1, wn = wid >> 1;                 // 2 row x 4 col warp groups
    int rowBase = blockIdx.x * 32;

    if (tid < 128) biasm[tid] = bias[tid];

    uint32_t asB = (uint32_t)__cvta_generic_to_shared(Asm);
    uint32_t wsB = (uint32_t)__cvta_generic_to_shared(Wsm);

    // stage A: 32 rows x 32 16B-chunks ([pEnc | aggH])
    for (int c = tid; c < 32 * 32; c += 256) {
        int row = c >> 5, off = (c & 31) * 8;        // elem offset 0..248
        const __nv_bfloat16* src;
        if (off < 128) src = pEnc  + (size_t)(rowBase + row) * 128 + off;
        else           src = aggIn + (size_t)(rowBase + row) * 128 + (off - 128);
        cpa16(asB + (uint32_t)(row * PPA_LD + off) * 2, src);
    }
    // stage W: 256 rows x 16 chunks (stride 136)
    for (int c = tid; c < 256 * 16; c += 256) {
        int row = c >> 4, c8 = (c & 15) * 8;
        cpa16(wsB + (uint32_t)(row * 136 + c8) * 2, W + (size_t)row * 128 + c8);
    }
    cp_commit(); cp_wait0();
    __syncthreads();

    wmma::fragment<wmma::accumulator, 16, 16, 16, float> acc[2];
#pragma unroll
    for (int nf = 0; nf < 2; nf++) wmma::fill_fragment(acc[nf], 0.f);
    for (int kt = 0; kt < 16; kt++) {
        wmma::fragment<wmma::matrix_a, 16, 16, 16, __nv_bfloat16, wmma::row_major> af;
        wmma::load_matrix_sync(af, Asm + (wm * 16) * PPA_LD + kt * 16, PPA_LD);
#pragma unroll
        for (int nf = 0; nf < 2; nf++) {
            wmma::fragment<wmma::matrix_b, 16, 16, 16, __nv_bfloat16, wmma::row_major> bf;
            wmma::load_matrix_sync(bf, Wsm + (kt * 16) * 136 + wn * 32 + nf * 16, 136);
            wmma::mma_sync(acc[nf], af, bf, acc[nf]);
        }
    }
    __syncthreads();                                 // A reads done before overlay
#pragma unroll
    for (int nf = 0; nf < 2; nf++)
        wmma::store_matrix_sync(Cs + (wm * 16) * 132 + wn * 32 + nf * 16,
                                acc[nf], 132, wmma::mem_row_major);
    __syncthreads();
#pragma unroll
    for (int it = 0; it < 4; it++) {
        int e = tid + it * 256, row = e >> 5, c4 = (e & 31) * 4;
        size_t go = (size_t)(rowBase + row) * 128 + c4;
        float4 v = *(float4*)&Cs[row * 132 + c4];
        float4 b = *(const float4*)&biasm[c4];
        uint2 rv = *(const uint2*)&pEff[go];
        float2 r0 = unpack_bf2(rv.x), r1 = unpack_bf2(rv.y);
        v.x = fmaxf(v.x + b.x + r0.x, 0.f);
        v.y = fmaxf(v.y + b.y + r0.y, 0.f);
        v.z = fmaxf(v.z + b.z + r1.x, 0.f);
        v.w = fmaxf(v.w + b.w + r1.y, 0.f);
        uint2 o; o.x = pack_bf2(v.x, v.y); o.y = pack_bf2(v.z, v.w);
        *(uint2*)&pEff[go] = o;
        *(uint2*)&aggZ[go] = make_uint2(0u, 0u);     // re-zero for next step
    }
}

// =====================  fused head: np0 + np1 + np2 + clamp + add ===========
#define HD_BIAS_OFF (256*136*2)                    // 69632
#define HD_W2_OFF   (HD_BIAS_OFF + 2*128*4)        // 70656
#define HD_B2_OFF   (HD_W2_OFF + 384*4)            // 72192
#define HD_ACT_OFF  (HD_B2_OFF + 16)               // 72208
#define HD_CS_OFF   (HD_ACT_OFF + 64*136*2)        // 89616
#define HD_SMEM     (HD_CS_OFF + 64*132*4)         // 123408

__global__ void __launch_bounds__(256) head_k(
    const __nv_bfloat16* __restrict__ pEff,
    const __nv_bfloat16* __restrict__ W0, const __nv_bfloat16* __restrict__ W1,
    const float* __restrict__ b0, const float* __restrict__ b1,
    const float* __restrict__ W2, const float* __restrict__ b2,
    const float* __restrict__ state, float* __restrict__ out)
{
    extern __shared__ char smraw[];
    __nv_bfloat16* Wsm  = (__nv_bfloat16*)smraw;
    float* biasm        = (float*)(smraw + HD_BIAS_OFF);
    float* W2s          = (float*)(smraw + HD_W2_OFF);
    float* b2s          = (float*)(smraw + HD_B2_OFF);
    __nv_bfloat16* Act  = (__nv_bfloat16*)(smraw + HD_ACT_OFF);
    float* Cs           = (float*)(smraw + HD_CS_OFF);
    int tid = threadIdx.x, wid = tid >> 5, lane = tid & 31;
    int wm = wid & 3, wn = wid >> 2;
    int rowBase = blockIdx.x * 64;

    for (int idx = tid; idx < 256 * 16; idx += 256) {
        int r = idx >> 4, c8 = (idx & 15) * 8;
        const __nv_bfloat16* src = (r < 128) ? W0 + (size_t)r * 128 + c8
                                             : W1 + (size_t)(r - 128) * 128 + c8;
        *(uint4*)&Wsm[r * 136 + c8] = *(const uint4*)src;
    }
    for (int i = tid; i < 128; i += 256) { biasm[i] = b0[i]; biasm[128 + i] = b1[i]; }
    for (int i = tid; i < 384; i += 256) W2s[i] = W2[i];
    if (tid < 3) b2s[tid] = b2[tid];
    for (int idx = tid; idx < 64 * 16; idx += 256) {
        int r = idx >> 4, c8 = (idx & 15) * 8;
        *(uint4*)&Act[r * 136 + c8] =
            *(const uint4*)(pEff + (size_t)(rowBase + r) * 128 + c8);
    }
    __syncthreads();

    for (int L = 0; L < 2; L++) {
        const __nv_bfloat16* WL = Wsm + (size_t)L * 128 * 136;
        wmma::fragment<wmma::accumulator, 16, 16, 16, float> acc[4];
#pragma unroll
        for (int nf = 0; nf < 4; nf++) wmma::fill_fragment(acc[nf], 0.f);
#pragma unroll
        for (int kc = 0; kc < 8; kc++) {
            wmma::fragment<wmma::matrix_a, 16, 16, 16, __nv_bfloat16, wmma::row_major> af;
            wmma::load_matrix_sync(af, Act + (wm * 16) * 136 + kc * 16, 136);
#pragma unroll
            for (int nf = 0; nf < 4; nf++) {
                wmma::fragment<wmma::matrix_b, 16, 16, 16, __nv_bfloat16, wmma::row_major> bf;
                wmma::load_matrix_sync(bf, WL + (kc * 16) * 136 + wn * 64 + nf * 16, 136);
                wmma::mma_sync(acc[nf], af, bf, acc[nf]);
            }
        }
#pragma unroll
        for (int nf = 0; nf < 4; nf++)
            wmma::store_matrix_sync(Cs + (wm * 16) * 132 + wn * 64 + nf * 16,
                                    acc[nf], 132, wmma::mem_row_major);
        __syncthreads();
        const float* bL = biasm + L * 128;
#pragma unroll
        for (int it = 0; it < 8; it++) {
            int e = tid + it * 256, row = e >> 5, c4 = (e & 31) * 4;
            float4 v = *(float4*)&Cs[row * 132 + c4];
            float4 b = *(const float4*)&bL[c4];
            uint2 o;
            o.x = pack_bf2(fmaxf(v.x + b.x, 0.f), fmaxf(v.y + b.y, 0.f));
            o.y = pack_bf2(fmaxf(v.z + b.z, 0.f), fmaxf(v.w + b.w, 0.f));
            *(uint2*)&Act[row * 136 + c4] = o;
        }
        __syncthreads();
    }

    // final 128->3, clamp, add last position
#pragma unroll
    for (int i = 0; i < 8; i++) {
        int row = wid * 8 + i;
        int grow = rowBase + row;
        int b = grow >> 11, n = grow & (NN - 1);
        float hv[4];
#pragma unroll
        for (int j = 0; j < 4; j++)
            hv[j] = __bfloat162float(Act[row * 136 + lane + 32 * j]);
#pragma unroll
        for (int k = 0; k < 3; k++) {
            float sacc = 0.f;
#pragma unroll
            for (int j = 0; j < 4; j++)
                sacc += hv[j] * W2s[(lane + 32 * j) * 3 + k];
#pragma unroll
            for (int off = 16; off; off >>= 1)
                sacc += __shfl_xor_sync(0xffffffffu, sacc, off);
            if (lane == 0 && n < NP) {
                float m = fminf(fmaxf(sacc + b2s[k], -100.f), 100.f);
                out[((size_t)b * NP + n) * 3 + k] =
                    state[((size_t)(b * 4 + 3) * NN + n) * 3 + k] + m;
            }
        }
    }
}

// ---------------------------------------------------------------------------
extern "C" void kernel_launch(void* const* d_in, const int* in_sizes, int n_in,
                              void* d_out, int out_size) {
    const float* state  = (const float*)d_in[0];
    const float* attrs  = (const float*)d_in[1];
    const float* Rr     = (const float*)d_in[2];
    const float* Rs     = (const float*)d_in[3];
    const float* pinst  = (const float*)d_in[4];
    const float* action = (const float*)d_in[5];
    const float* pden   = (const float*)d_in[6];
    const float* phys   = (const float*)d_in[7];
    const float* pe_W0 = (const float*)d_in[8],  *pe_b0 = (const float*)d_in[9];
    const float* pe_W1 = (const float*)d_in[10], *pe_b1 = (const float*)d_in[11];
    const float* pe_W2 = (const float*)d_in[12], *pe_b2 = (const float*)d_in[13];
    const float* re_W0 = (const float*)d_in[14], *re_b0 = (const float*)d_in[15];
    const float* re_W1 = (const float*)d_in[16], *re_b1 = (const float*)d_in[17];
    const float* re_W2 = (const float*)d_in[18], *re_b2 = (const float*)d_in[19];
    const float* pp_W  = (const float*)d_in[20], *pp_b  = (const float*)d_in[21];
    const float* rp_W  = (const float*)d_in[22], *rp_b  = (const float*)d_in[23];
    const float* np_W0 = (const float*)d_in[24], *np_b0 = (const float*)d_in[25];
    const float* np_W1 = (const float*)d_in[26], *np_b1 = (const float*)d_in[27];
    const float* np_W2 = (const float*)d_in[28], *np_b2 = (const float*)d_in[29];
    float* out = (float*)d_out;

    float* pin_f;
    __nv_bfloat16 *pEnc, *pEff, *relE, *aggH, *wbuf;
    int *rr, *rs;
    cudaGetSymbolAddress((void**)&pin_f, g_pin_f);
    cudaGetSymbolAddress((void**)&pEnc,  g_pEnc);
    cudaGetSymbolAddress((void**)&pEff,  g_pEff);
    cudaGetSymbolAddress((void**)&relE,  g_relE);
    cudaGetSymbolAddress((void**)&aggH,  g_aggH);
    cudaGetSymbolAddress((void**)&rr,    g_rr);
    cudaGetSymbolAddress((void**)&rs,    g_rs);
    cudaGetSymbolAddress((void**)&wbuf,  g_wbuf);

    cudaFuncSetAttribute(encmlp_k,  cudaFuncAttributeMaxDynamicSharedMemorySize, ENC_SMEM);
    cudaFuncSetAttribute(relprop_k, cudaFuncAttributeMaxDynamicSharedMemorySize, RP2_SMEM);
    cudaFuncSetAttribute(partprop_k,cudaFuncAttributeMaxDynamicSharedMemorySize, PP2_SMEM);
    cudaFuncSetAttribute(head_k,    cudaFuncAttributeMaxDynamicSharedMemorySize, HD_SMEM);

    WConvArgs wa;
    const float* srcs[10] = {pe_W0, pe_W1, pe_W2, re_W0, re_W1, re_W2,
                             pp_W, rp_W, np_W0, np_W1};
    const int starts[10]  = {WO_PE0, WO_PE1, WO_PE2, WO_RE0, WO_RE1, WO_RE2,
                             WO_PP, WO_RP, WO_NP0, WO_NP1};
    const int srows[10]   = {19, 128, 128, 56, 128, 128, 256, 384, 128, 128};
    for (int i = 0; i < 10; i++) {
        wa.src[i] = srcs[i]; wa.rowStart[i] = starts[i]; wa.srcRows[i] = srows[i];
    }

    // 1) convert weights + build particle features + extract indices
    prep_k<<<4096, 256>>>(Rr, Rs, rr, rs, state, attrs, action, pden, phys,
                          pin_f, wa, wbuf);

    // 2) fused 3-layer encoders with inline feature assembly
    EncArgs ea;
    ea.pf = pin_f; ea.attrs = attrs; ea.pinst = pinst;
    ea.rr = rr; ea.rs = rs; ea.wbuf = wbuf;
    ea.pe_b0 = pe_b0; ea.pe_b1 = pe_b1; ea.pe_b2 = pe_b2;
    ea.re_b0 = re_b0; ea.re_b1 = re_b1; ea.re_b2 = re_b2;
    ea.pEnc = pEnc; ea.pEff = pEff; ea.relE = relE; ea.aggH = aggH;
    encmlp_k<<<320, 256, ENC_SMEM>>>(ea);

    // 3) propagation: 3 steps, fully-resident single-sync GEMMs
    for (int step = 0; step < 3; step++) {
        relprop_k<<<BNR / 128, 512, RP2_SMEM>>>(relE, pEff, wbuf + WO_RP * 128,
                                                rp_b, aggH, rr, rs);
        partprop_k<<<NODES / 32, 256, PP2_SMEM>>>(pEnc, aggH, wbuf + WO_PP * 128,
                                                  pp_b, pEff, aggH);
    }

    // 4) fused head
    head_k<<<NODES / 64, 256, HD_SMEM>>>(pEff, wbuf + WO_NP0 * 128,
                                         wbuf + WO_NP1 * 128, np_b0, np_b1,
                                         np_W2, np_b2, state, out);
}

// round 12
// speedup vs baseline: 1.1494x; 1.0575x over previous
#include <cuda_runtime.h>
#include <cuda_bf16.h>
#include <mma.h>
#include <cstdint>

using namespace nvcuda;

// Problem constants
#define BB 2
#define NN 2048
#define NP 2000
#define NREL 8192
#define BNR 16384
#define NODES 4096
#define NF 128

// ---------------- scratch ---------------------------------------------------
__device__ float          g_pin_f[NODES*19];
__device__ __nv_bfloat16  g_pEnc[NODES*NF];
__device__ __nv_bfloat16  g_pEff[NODES*NF];
__device__ __nv_bfloat16  g_relE[BNR*NF];
__device__ __nv_bfloat16  g_aggH[NODES*NF];
__device__ int            g_rr[BNR];
__device__ int            g_rs[BNR];
__device__ __nv_bfloat16  g_wbuf[1504*128];

// weight row offsets inside g_wbuf
#define WO_PE0 0
#define WO_PE1 32
#define WO_PE2 160
#define WO_RE0 288
#define WO_RE1 352
#define WO_RE2 480
#define WO_PP  608
#define WO_RP  864
#define WO_NP0 1248
#define WO_NP1 1376
#define W_TOTAL_ROWS 1504

// ---------------- helpers ---------------------------------------------------
__device__ __forceinline__ uint32_t pack_bf2(float a, float b) {
    __nv_bfloat162 h = __floats2bfloat162_rn(a, b);
    return *reinterpret_cast<uint32_t*>(&h);
}
__device__ __forceinline__ float2 unpack_bf2(uint32_t u) {
    __nv_bfloat162 h = *reinterpret_cast<__nv_bfloat162*>(&u);
    return make_float2(__bfloat162float(h.x), __bfloat162float(h.y));
}
__device__ __forceinline__ void cpa16(uint32_t d, const void* s) {
    asm volatile("cp.async.cg.shared.global [%0], [%1], 16;" :: "r"(d), "l"(s));
}
__device__ __forceinline__ void cp_commit() {
    asm volatile("cp.async.commit_group;" ::: "memory");
}
__device__ __forceinline__ void cp_wait0() {
    asm volatile("cp.async.wait_group 0;" ::: "memory");
}

// ---------------- weight conversion args ------------------------------------
struct WConvArgs {
    const float* src[10];
    int rowStart[10];
    int srcRows[10];
};

// =====================  prep kernel: convert + build_pin + extract ==========
__global__ void prep_k(const float* __restrict__ Rr, const float* __restrict__ Rs,
                       int* __restrict__ rr, int* __restrict__ rs,
                       const float* __restrict__ state, const float* __restrict__ attrs,
                       const float* __restrict__ action, const float* __restrict__ pden,
                       const float* __restrict__ phys, float* __restrict__ pf,
                       WConvArgs wa, __nv_bfloat16* __restrict__ wbuf) {
    int bid = blockIdx.x, tid = threadIdx.x;

    if (bid < 16) {
        int i = bid * 256 + tid;
        int b = i / NN, n = i - b * NN;
        float o[19];
        o[0] = attrs[i * 2 + 0];
        o[1] = attrs[i * 2 + 1];
        float s[4][3];
#pragma unroll
        for (int t = 0; t < 4; t++)
#pragma unroll
            for (int k = 0; k < 3; k++)
                s[t][k] = state[((size_t)(b * 4 + t) * NN + n) * 3 + k];
#pragma unroll
        for (int t = 0; t < 3; t++)
#pragma unroll
            for (int k = 0; k < 3; k++)
                o[2 + t * 3 + k] = s[t + 1][k] - s[t][k];
#pragma unroll
        for (int k = 0; k < 3; k++) o[11 + k] = s[3][k];
        bool isP = (n < NP);
        o[14] = isP ? phys[b] : 0.f;
#pragma unroll
        for (int k = 0; k < 3; k++) o[15 + k] = action[(size_t)i * 3 + k];
        o[18] = isP ? pden[b] : 0.f;
#pragma unroll
        for (int k = 0; k < 19; k++) pf[(size_t)i * 19 + k] = o[k];
    } else if (bid < 204) {
        int base = (bid - 16) * 1024;
        for (int k = tid; k < 1024; k += 256) {
            int e = base + k;
            int row = e >> 7, col = e & 127;
            int seg = 0;
#pragma unroll
            for (int i = 1; i < 10; i++) if (row >= wa.rowStart[i]) seg = i;
            int r = row - wa.rowStart[seg];
            float v = (r < wa.srcRows[seg]) ? wa.src[seg][r * 128 + col] : 0.f;
            wbuf[row * 128 + col] = __float2bfloat16(v);
        }
    }

    // extract (all 4096 blocks x 8 warps = 32768 row-warps)
    int gw = bid * 8 + (tid >> 5);
    int lane = tid & 31;
    const float* src = (gw < BNR) ? Rr : Rs;
    int row = (gw < BNR) ? gw : gw - BNR;
    const float4* p = reinterpret_cast<const float4*>(src + (size_t)row * NN);
    int found = -1;
    for (int i = 0; i < NN / 128; i++) {
        float4 v = __ldcs(&p[i * 32 + lane]);
        int base = i * 128 + lane * 4;
        if (v.x != 0.f) found = base;
        if (v.y != 0.f) found = base + 1;
        if (v.z != 0.f) found = base + 2;
        if (v.w != 0.f) found = base + 3;
        if (__ballot_sync(0xffffffffu, found >= 0)) break;   // one-hot: done
    }
#pragma unroll
    for (int off = 16; off; off >>= 1)
        found = max(found, __shfl_xor_sync(0xffffffffu, found, off));
    if (lane == 0) {
        int b = row / NREL;
        ((gw < BNR) ? rr : rs)[row] = b * NN + found;
    }
}

// ============  fused 3-layer encoder MLP with inline A build  ===============
#define ENC_WROWS 320
#define ENC_W_BYTES (ENC_WROWS*136*2)              // 87040
#define ENC_BIAS_OFF ENC_W_BYTES
#define ENC_ACT_OFF (ENC_BIAS_OFF + 3*128*4)       // 88576
#define ENC_CS_OFF  (ENC_ACT_OFF + 64*136*2)       // 105984
#define ENC_SMEM    (ENC_CS_OFF + 64*132*4)        // 139776

struct EncArgs {
    const float *pf, *attrs, *pinst;
    const int *rr, *rs;
    const __nv_bfloat16* wbuf;
    const float *pe_b0, *pe_b1, *pe_b2, *re_b0, *re_b1, *re_b2;
    __nv_bfloat16 *pEnc, *pEff, *relE, *aggH;
};

__global__ void __launch_bounds__(256) encmlp_k(EncArgs a) {
    extern __shared__ char sm[];
    __nv_bfloat16* Wsm  = (__nv_bfloat16*)sm;
    float* biasm        = (float*)(sm + ENC_BIAS_OFF);
    __nv_bfloat16* Act  = (__nv_bfloat16*)(sm + ENC_ACT_OFF);
    float* Cs           = (float*)(sm + ENC_CS_OFF);
    int tid = threadIdx.x, wid = tid >> 5;
    int wm = wid & 3, wn = wid >> 2;
    int t = blockIdx.x;
    bool particle = (t < 64);
    int K0 = particle ? 32 : 64;
    int rowBase = particle ? t * 64 : (t - 64) * 64;

    {
        const __nv_bfloat16 *W0, *W1, *W2;
        const float *b0, *b1, *b2;
        if (particle) {
            W0 = a.wbuf + WO_PE0 * 128; W1 = a.wbuf + WO_PE1 * 128; W2 = a.wbuf + WO_PE2 * 128;
            b0 = a.pe_b0; b1 = a.pe_b1; b2 = a.pe_b2;
        } else {
            W0 = a.wbuf + WO_RE0 * 128; W1 = a.wbuf + WO_RE1 * 128; W2 = a.wbuf + WO_RE2 * 128;
            b0 = a.re_b0; b1 = a.re_b1; b2 = a.re_b2;
        }
        for (int idx = tid; idx < (K0 + 256) * 16; idx += 256) {
            int r = idx >> 4, c8 = (idx & 15) * 8;
            const __nv_bfloat16* src;
            if (r < K0)            src = W0 + (size_t)r * 128 + c8;
            else if (r < K0 + 128) src = W1 + (size_t)(r - K0) * 128 + c8;
            else                   src = W2 + (size_t)(r - K0 - 128) * 128 + c8;
            *(uint4*)&Wsm[r * 136 + c8] = *(const uint4*)src;
        }
        for (int i = tid; i < 128; i += 256) {
            biasm[i] = b0[i]; biasm[128 + i] = b1[i]; biasm[256 + i] = b2[i];
        }
    }

    // build A inline into Act
    if (particle) {
        for (int idx = tid; idx < 64 * 32; idx += 256) {
            int r = idx >> 5, k = idx & 31;
            float v = (k < 19) ? a.pf[(size_t)(rowBase + r) * 19 + k] : 0.f;
            Act[r * 136 + k] = __float2bfloat16(v);
        }
    } else {
        for (int idx = tid; idx < 64 * 64; idx += 256) {
            int r = idx >> 6, k = idx & 63;
            int e = rowBase + r;
            int gr = a.rr[e], gs = a.rs[e];
            float v;
            if (k < 19)       v = a.pf[(size_t)gr * 19 + k];
            else if (k < 38)  v = a.pf[(size_t)gs * 19 + (k - 19)];
            else if (k < 40)  v = a.attrs[gr * 2 + (k - 38)];
            else if (k < 42)  v = a.attrs[gs * 2 + (k - 40)];
            else if (k == 42) {
                int b = e / NREL;
                int ir = gr & (NN - 1), is_ = gs & (NN - 1);
                float gd = 0.f;
#pragma unroll
                for (int j = 0; j < 8; j++) {
                    float x = (ir < NP) ? a.pinst[((size_t)b * NP + ir) * 8 + j] : 0.f;
                    float c = (is_ < NP) ? a.pinst[((size_t)b * NP + is_) * 8 + j] : 0.f;
                    gd += fabsf(x - c);
                }
                v = gd;
            }
            else if (k < 55)  v = a.pf[(size_t)gr * 19 + 2 + (k - 43)]
                                - a.pf[(size_t)gs * 19 + 2 + (k - 43)];
            else if (k == 55) v = a.pf[(size_t)gr * 19 + 18] - a.pf[(size_t)gs * 19 + 18];
            else              v = 0.f;
            Act[r * 136 + k] = __float2bfloat16(v);
        }
    }
    __syncthreads();

    for (int L = 0; L < 3; L++) {
        int KL = (L == 0) ? K0 : 128;
        const __nv_bfloat16* WL = Wsm + (size_t)((L == 0) ? 0 : K0 + (L - 1) * 128) * 136;
        wmma::fragment<wmma::accumulator, 16, 16, 16, float> acc[4];
#pragma unroll
        for (int nf = 0; nf < 4; nf++) wmma::fill_fragment(acc[nf], 0.f);
        for (int kc = 0; kc < KL / 16; kc++) {
            wmma::fragment<wmma::matrix_a, 16, 16, 16, __nv_bfloat16, wmma::row_major> af;
            wmma::load_matrix_sync(af, Act + (wm * 16) * 136 + kc * 16, 136);
#pragma unroll
            for (int nf = 0; nf < 4; nf++) {
                wmma::fragment<wmma::matrix_b, 16, 16, 16, __nv_bfloat16, wmma::row_major> bf;
                wmma::load_matrix_sync(bf, WL + (kc * 16) * 136 + wn * 64 + nf * 16, 136);
                wmma::mma_sync(acc[nf], af, bf, acc[nf]);
            }
        }
#pragma unroll
        for (int nf = 0; nf < 4; nf++)
            wmma::store_matrix_sync(Cs + (wm * 16) * 132 + wn * 64 + nf * 16,
                                    acc[nf], 132, wmma::mem_row_major);
        __syncthreads();
        const float* bL = biasm + L * 128;
#pragma unroll
        for (int it = 0; it < 8; it++) {
            int e = tid + it * 256, row = e >> 5, c4 = (e & 31) * 4;
            float4 v = *(float4*)&Cs[row * 132 + c4];
            float4 b = *(const float4*)&bL[c4];
            v.x = fmaxf(v.x + b.x, 0.f); v.y = fmaxf(v.y + b.y, 0.f);
            v.z = fmaxf(v.z + b.z, 0.f); v.w = fmaxf(v.w + b.w, 0.f);
            uint2 o; o.x = pack_bf2(v.x, v.y); o.y = pack_bf2(v.z, v.w);
            if (L < 2) {
                *(uint2*)&Act[row * 136 + c4] = o;
            } else {
                size_t go = (size_t)(rowBase + row) * 128 + c4;
                if (particle) {
                    *(uint2*)&a.pEnc[go] = o;
                    *(uint2*)&a.pEff[go] = o;
                    *(uint2*)&a.aggH[go] = make_uint2(0u, 0u);
                } else {
                    *(uint2*)&a.relE[go] = o;
                }
            }
        }
        __syncthreads();
    }
}

// =============  relation propagator v2: fully-resident (R11-proven) =========
#define RPA_LD 392
#define RP2_W_OFF   (128*RPA_LD*2)                 // 100352
#define RP2_IDX_OFF (RP2_W_OFF + 384*136*2)        // 204800
#define RP2_BIAS_OFF (RP2_IDX_OFF + 256*4)         // 205824
#define RP2_SMEM    (RP2_BIAS_OFF + 128*4)         // 206336

__global__ void __launch_bounds__(512) relprop_k(
    const __nv_bfloat16* __restrict__ relE,
    const __nv_bfloat16* __restrict__ pEff,
    const __nv_bfloat16* __restrict__ W,
    const float* __restrict__ bias,
    __nv_bfloat16* __restrict__ aggH,
    const int* __restrict__ rr, const int* __restrict__ rs)
{
    extern __shared__ char sm[];
    __nv_bfloat16* Asm = (__nv_bfloat16*)sm;
    __nv_bfloat16* Wsm = (__nv_bfloat16*)(sm + RP2_W_OFF);
    int*   idxs        = (int*)(sm + RP2_IDX_OFF);
    float* biasm       = (float*)(sm + RP2_BIAS_OFF);
    float* Cs          = (float*)sm;                 // overlay A post-mainloop

    int tid = threadIdx.x, wid = tid >> 5;
    int wm = wid & 7, wn = wid >> 3;                 // 8 row x 2 col warp groups
    int rowBase = blockIdx.x * 128;

    if (tid < 128)      idxs[tid]       = rr[rowBase + tid];
    else if (tid < 256) idxs[tid]       = rs[rowBase + tid - 128];
    if (tid < 128) biasm[tid] = bias[tid];
    __syncthreads();                                 // idxs visible for gather

    uint32_t asB = (uint32_t)__cvta_generic_to_shared(Asm);
    uint32_t wsB = (uint32_t)__cvta_generic_to_shared(Wsm);

    for (int c = tid; c < 128 * 48; c += 512) {
        int row = c / 48, ch = c % 48;
        int seg = ch >> 4, off = (ch & 15) * 8;
        const __nv_bfloat16* src;
        if (seg == 0)      src = relE + (size_t)(rowBase + row) * 128 + off;
        else if (seg == 1) src = pEff + (size_t)idxs[row] * 128 + off;
        else               src = pEff + (size_t)idxs[128 + row] * 128 + off;
        cpa16(asB + (uint32_t)(row * RPA_LD + seg * 128 + off) * 2, src);
    }
    for (int c = tid; c < 384 * 16; c += 512) {
        int row = c >> 4, c8 = (c & 15) * 8;
        cpa16(wsB + (uint32_t)(row * 136 + c8) * 2, W + (size_t)row * 128 + c8);
    }
    cp_commit(); cp_wait0();
    __syncthreads();

    wmma::fragment<wmma::accumulator, 16, 16, 16, float> acc[4];
#pragma unroll
    for (int nf = 0; nf < 4; nf++) wmma::fill_fragment(acc[nf], 0.f);
    for (int kt = 0; kt < 24; kt++) {
        wmma::fragment<wmma::matrix_a, 16, 16, 16, __nv_bfloat16, wmma::row_major> af;
        wmma::load_matrix_sync(af, Asm + (wm * 16) * RPA_LD + kt * 16, RPA_LD);
#pragma unroll
        for (int nf = 0; nf < 4; nf++) {
            wmma::fragment<wmma::matrix_b, 16, 16, 16, __nv_bfloat16, wmma::row_major> bf;
            wmma::load_matrix_sync(bf, Wsm + (kt * 16) * 136 + wn * 64 + nf * 16, 136);
            wmma::mma_sync(acc[nf], af, bf, acc[nf]);
        }
    }
    __syncthreads();                                 // A reads done before overlay
#pragma unroll
    for (int nf = 0; nf < 4; nf++)
        wmma::store_matrix_sync(Cs + (wm * 16) * 132 + wn * 64 + nf * 16,
                                acc[nf], 132, wmma::mem_row_major);
    __syncthreads();
#pragma unroll
    for (int it = 0; it < 8; it++) {
        int e = tid + it * 512, row = e >> 5, c4 = (e & 31) * 4;
        float4 v = *(float4*)&Cs[row * 132 + c4];
        float4 b = *(const float4*)&biasm[c4];
        __nv_bfloat162* dst =
            (__nv_bfloat162*)(aggH + (size_t)idxs[row] * 128 + c4);
        atomicAdd(dst,     __floats2bfloat162_rn(fmaxf(v.x + b.x, 0.f),
                                                 fmaxf(v.y + b.y, 0.f)));
        atomicAdd(dst + 1, __floats2bfloat162_rn(fmaxf(v.z + b.z, 0.f),
                                                 fmaxf(v.w + b.w, 0.f)));
    }
}

// =============  particle propagator v3: 512 threads, optional fused head ====
// BM=32, grid 128. A = [pEnc | aggH] (32x264), W (256x136) resident.
// 16 warps: 2 row x 8 col groups, 1 wmma frag each.
// DO_HEAD=false: epi relu(acc+bias+pEff) -> pEff; re-zero aggH rows.
// DO_HEAD=true (final step): pEff tile kept in smem; run np0/np1/np2+clamp+add
//                            and write d_out directly. No pEff/agg stores.
#define PPA_LD 264
#define PH_W_OFF    (32*PPA_LD*2)                  // 16896
#define PH_NW_OFF   (PH_W_OFF + 256*136*2)         // 86528
#define PH_BIAS_OFF (PH_NW_OFF + 256*136*2)        // 156160
#define PH_NB0_OFF  (PH_BIAS_OFF + 512)            // 156672
#define PH_NB1_OFF  (PH_NB0_OFF + 512)             // 157184
#define PH_W2_OFF   (PH_NB1_OFF + 512)             // 157696
#define PH_B2_OFF   (PH_W2_OFF + 1536)             // 159232
#define PH_ACT_OFF  (PH_B2_OFF + 16)               // 159248
#define PH_SMEM     (PH_ACT_OFF + 32*136*2)        // 167952
#define PPF_SMEM    (PH_BIAS_OFF + 512)            // 156672 (NW gap unused)

template <bool DO_HEAD>
__global__ void __launch_bounds__(512) partprop_k(
    const __nv_bfloat16* __restrict__ pEnc,
    const __nv_bfloat16* __restrict__ aggIn,
    const __nv_bfloat16* __restrict__ W,
    const float* __restrict__ bias,
    __nv_bfloat16* __restrict__ pEff,
    __nv_bfloat16* __restrict__ aggZ,
    const __nv_bfloat16* __restrict__ npW,   // np_W0|np_W1 stacked (256x128)
    const float* __restrict__ nb0, const float* __restrict__ nb1,
    const float* __restrict__ W2, const float* __restrict__ b2,
    const float* __restrict__ state, float* __restrict__ out)
{
    extern __shared__ char sm[];
    __nv_bfloat16* Asm  = (__nv_bfloat16*)sm;
    __nv_bfloat16* Wsm  = (__nv_bfloat16*)(sm + PH_W_OFF);
    __nv_bfloat16* NWsm = (__nv_bfloat16*)(sm + PH_NW_OFF);
    float* biasm        = (float*)(sm + PH_BIAS_OFF);
    float* nb0s         = (float*)(sm + PH_NB0_OFF);
    float* nb1s         = (float*)(sm + PH_NB1_OFF);
    float* W2s          = (float*)(sm + PH_W2_OFF);
    float* b2s          = (float*)(sm + PH_B2_OFF);
    __nv_bfloat16* Act  = (__nv_bfloat16*)(sm + PH_ACT_OFF);
    float* Cs           = (float*)sm;                // overlays Asm (16896 B both)

    int tid = threadIdx.x, wid = tid >> 5, lane = tid & 31;
    int wm = wid & 1, wn = wid >> 1;                 // 2 row x 8 col warp groups
    int rowBase = blockIdx.x * 32;

    for (int i = tid; i < 128; i += 512) biasm[i] = bias[i];
    if (DO_HEAD) {
        for (int i = tid; i < 128; i += 512) { nb0s[i] = nb0[i]; nb1s[i] = nb1[i]; }
        for (int i = tid; i < 384; i += 512) W2s[i] = W2[i];
        if (tid < 3) b2s[tid] = b2[tid];
    }

    uint32_t asB = (uint32_t)__cvta_generic_to_shared(Asm);
    uint32_t wsB = (uint32_t)__cvta_generic_to_shared(Wsm);
    uint32_t nwB = (uint32_t)__cvta_generic_to_shared(NWsm);

    // stage A: 32 rows x 32 16B-chunks ([pEnc | aggH])
    for (int c = tid; c < 32 * 32; c += 512) {
        int row = c >> 5, off = (c & 31) * 8;
        const __nv_bfloat16* src;
        if (off < 128) src = pEnc  + (size_t)(rowBase + row) * 128 + off;
        else           src = aggIn + (size_t)(rowBase + row) * 128 + (off - 128);
        cpa16(asB + (uint32_t)(row * PPA_LD + off) * 2, src);
    }
    // stage W (and np weights when fusing the head)
    for (int c = tid; c < 256 * 16; c += 512) {
        int row = c >> 4, c8 = (c & 15) * 8;
        cpa16(wsB + (uint32_t)(row * 136 + c8) * 2, W + (size_t)row * 128 + c8);
        if (DO_HEAD)
            cpa16(nwB + (uint32_t)(row * 136 + c8) * 2, npW + (size_t)row * 128 + c8);
    }
    cp_commit(); cp_wait0();
    __syncthreads();

    // ---- propagator GEMM (K=256), 1 frag per warp ----
    wmma::fragment<wmma::accumulator, 16, 16, 16, float> acc;
    wmma::fill_fragment(acc, 0.f);
    for (int kt = 0; kt < 16; kt++) {
        wmma::fragment<wmma::matrix_a, 16, 16, 16, __nv_bfloat16, wmma::row_major> af;
        wmma::load_matrix_sync(af, Asm + (wm * 16) * PPA_LD + kt * 16, PPA_LD);
        wmma::fragment<wmma::matrix_b, 16, 16, 16, __nv_bfloat16, wmma::row_major> bf;
        wmma::load_matrix_sync(bf, Wsm + (kt * 16) * 136 + wn * 16, 136);
        wmma::mma_sync(acc, af, bf, acc);
    }
    __syncthreads();                                 // Asm reads done before overlay
    wmma::store_matrix_sync(Cs + (wm * 16) * 132 + wn * 16, acc, 132,
                            wmma::mem_row_major);
    __syncthreads();

    // ---- propagator epilogue: relu(acc + bias + pEff) ----
#pragma unroll
    for (int it = 0; it < 2; it++) {
        int e = tid + it * 512, row = e >> 5, c4 = (e & 31) * 4;
        size_t go = (size_t)(rowBase + row) * 128 + c4;
        float4 v = *(float4*)&Cs[row * 132 + c4];
        float4 b = *(const float4*)&biasm[c4];
        uint2 rv = *(const uint2*)&pEff[go];
        float2 r0 = unpack_bf2(rv.x), r1 = unpack_bf2(rv.y);
        v.x = fmaxf(v.x + b.x + r0.x, 0.f);
        v.y = fmaxf(v.y + b.y + r0.y, 0.f);
        v.z = fmaxf(v.z + b.z + r1.x, 0.f);
        v.w = fmaxf(v.w + b.w + r1.y, 0.f);
        uint2 o; o.x = pack_bf2(v.x, v.y); o.y = pack_bf2(v.z, v.w);
        if (DO_HEAD) {
            *(uint2*)&Act[row * 136 + c4] = o;       // keep tile in smem only
        } else {
            *(uint2*)&pEff[go] = o;
            *(uint2*)&aggZ[go] = make_uint2(0u, 0u); // re-zero for next step
        }
    }

    if (!DO_HEAD) return;

    // ================= fused head (step 3 only) =================
    __syncthreads();                                 // Act ready; Cs reads done
    // ---- np0: Act(32x128) @ NW[0:128] ----
    {
        wmma::fragment<wmma::accumulator, 16, 16, 16, float> a2;
        wmma::fill_fragment(a2, 0.f);
#pragma unroll
        for (int kt = 0; kt < 8; kt++) {
            wmma::fragment<wmma::matrix_a, 16, 16, 16, __nv_bfloat16, wmma::row_major> af;
            wmma::load_matrix_sync(af, Act + (wm * 16) * 136 + kt * 16, 136);
            wmma::fragment<wmma::matrix_b, 16, 16, 16, __nv_bfloat16, wmma::row_major> bf;
            wmma::load_matrix_sync(bf, NWsm + (kt * 16) * 136 + wn * 16, 136);
            wmma::mma_sync(a2, af, bf, a2);
        }
        __syncthreads();
        wmma::store_matrix_sync(Cs + (wm * 16) * 132 + wn * 16, a2, 132,
                                wmma::mem_row_major);
        __syncthreads();
        // h0 = relu(Cs + nb0) -> Act
#pragma unroll
        for (int it = 0; it < 2; it++) {
            int e = tid + it * 512, row = e >> 5, c4 = (e & 31) * 4;
            float4 v = *(float4*)&Cs[row * 132 + c4];
            float4 b = *(const float4*)&nb0s[c4];
            uint2 o;
            o.x = pack_bf2(fmaxf(v.x + b.x, 0.f), fmaxf(v.y + b.y, 0.f));
            o.y = pack_bf2(fmaxf(v.z + b.z, 0.f), fmaxf(v.w + b.w, 0.f));
            *(uint2*)&Act[row * 136 + c4] = o;
        }
        __syncthreads();
    }
    // ---- np1: Act @ NW[128:256] -> Cs ----
    {
        wmma::fragment<wmma::accumulator, 16, 16, 16, float> a2;
        wmma::fill_fragment(a2, 0.f);
#pragma unroll
        for (int kt = 0; kt < 8; kt++) {
            wmma::fragment<wmma::matrix_a, 16, 16, 16, __nv_bfloat16, wmma::row_major> af;
            wmma::load_matrix_sync(af, Act + (wm * 16) * 136 + kt * 16, 136);
            wmma::fragment<wmma::matrix_b, 16, 16, 16, __nv_bfloat16, wmma::row_major> bf;
            wmma::load_matrix_sync(bf, NWsm + ((128 + kt * 16)) * 136 + wn * 16, 136);
            wmma::mma_sync(a2, af, bf, a2);
        }
        __syncthreads();
        wmma::store_matrix_sync(Cs + (wm * 16) * 132 + wn * 16, a2, 132,
                                wmma::mem_row_major);
        __syncthreads();
    }
    // ---- final: h1 = relu(Cs + nb1); motion = h1 @ W2 + b2; clamp; add ----
#pragma unroll
    for (int i = 0; i < 2; i++) {
        int row = wid * 2 + i;                       // 16 warps x 2 = 32 rows
        int grow = rowBase + row;
        int b = grow >> 11, n = grow & (NN - 1);
        float hv[4];
#pragma unroll
        for (int j = 0; j < 4; j++)
            hv[j] = fmaxf(Cs[row * 132 + lane + 32 * j] + nb1s[lane + 32 * j], 0.f);
#pragma unroll
        for (int k = 0; k < 3; k++) {
            float sacc = 0.f;
#pragma unroll
            for (int j = 0; j < 4; j++)
                sacc += hv[j] * W2s[(lane + 32 * j) * 3 + k];
#pragma unroll
            for (int off = 16; off; off >>= 1)
                sacc += __shfl_xor_sync(0xffffffffu, sacc, off);
            if (lane == 0 && n < NP) {
                float m = fminf(fmaxf(sacc + b2s[k], -100.f), 100.f);
                out[((size_t)b * NP + n) * 3 + k] =
                    state[((size_t)(b * 4 + 3) * NN + n) * 3 + k] + m;
            }
        }
    }
}

// ---------------------------------------------------------------------------
extern "C" void kernel_launch(void* const* d_in, const int* in_sizes, int n_in,
                              void* d_out, int out_size) {
    const float* state  = (const float*)d_in[0];
    const float* attrs  = (const float*)d_in[1];
    const float* Rr     = (const float*)d_in[2];
    const float* Rs     = (const float*)d_in[3];
    const float* pinst  = (const float*)d_in[4];
    const float* action = (const float*)d_in[5];
    const float* pden   = (const float*)d_in[6];
    const float* phys   = (const float*)d_in[7];
    const float* pe_W0 = (const float*)d_in[8],  *pe_b0 = (const float*)d_in[9];
    const float* pe_W1 = (const float*)d_in[10], *pe_b1 = (const float*)d_in[11];
    const float* pe_W2 = (const float*)d_in[12], *pe_b2 = (const float*)d_in[13];
    const float* re_W0 = (const float*)d_in[14], *re_b0 = (const float*)d_in[15];
    const float* re_W1 = (const float*)d_in[16], *re_b1 = (const float*)d_in[17];
    const float* re_W2 = (const float*)d_in[18], *re_b2 = (const float*)d_in[19];
    const float* pp_W  = (const float*)d_in[20], *pp_b  = (const float*)d_in[21];
    const float* rp_W  = (const float*)d_in[22], *rp_b  = (const float*)d_in[23];
    const float* np_W0 = (const float*)d_in[24], *np_b0 = (const float*)d_in[25];
    const float* np_W1 = (const float*)d_in[26], *np_b1 = (const float*)d_in[27];
    const float* np_W2 = (const float*)d_in[28], *np_b2 = (const float*)d_in[29];
    float* out = (float*)d_out;

    float* pin_f;
    __nv_bfloat16 *pEnc, *pEff, *relE, *aggH, *wbuf;
    int *rr, *rs;
    cudaGetSymbolAddress((void**)&pin_f, g_pin_f);
    cudaGetSymbolAddress((void**)&pEnc,  g_pEnc);
    cudaGetSymbolAddress((void**)&pEff,  g_pEff);
    cudaGetSymbolAddress((void**)&relE,  g_relE);
    cudaGetSymbolAddress((void**)&aggH,  g_aggH);
    cudaGetSymbolAddress((void**)&rr,    g_rr);
    cudaGetSymbolAddress((void**)&rs,    g_rs);
    cudaGetSymbolAddress((void**)&wbuf,  g_wbuf);

    cudaFuncSetAttribute(encmlp_k,  cudaFuncAttributeMaxDynamicSharedMemorySize, ENC_SMEM);
    cudaFuncSetAttribute(relprop_k, cudaFuncAttributeMaxDynamicSharedMemorySize, RP2_SMEM);
    cudaFuncSetAttribute(partprop_k<false>, cudaFuncAttributeMaxDynamicSharedMemorySize, PPF_SMEM);
    cudaFuncSetAttribute(partprop_k<true>,  cudaFuncAttributeMaxDynamicSharedMemorySize, PH_SMEM);

    WConvArgs wa;
    const float* srcs[10] = {pe_W0, pe_W1, pe_W2, re_W0, re_W1, re_W2,
                             pp_W, rp_W, np_W0, np_W1};
    const int starts[10]  = {WO_PE0, WO_PE1, WO_PE2, WO_RE0, WO_RE1, WO_RE2,
                             WO_PP, WO_RP, WO_NP0, WO_NP1};
    const int srows[10]   = {19, 128, 128, 56, 128, 128, 256, 384, 128, 128};
    for (int i = 0; i < 10; i++) {
        wa.src[i] = srcs[i]; wa.rowStart[i] = starts[i]; wa.srcRows[i] = srows[i];
    }

    // 1) convert weights + build particle features + extract indices
    prep_k<<<4096, 256>>>(Rr, Rs, rr, rs, state, attrs, action, pden, phys,
                          pin_f, wa, wbuf);

    // 2) fused 3-layer encoders with inline feature assembly
    EncArgs ea;
    ea.pf = pin_f; ea.attrs = attrs; ea.pinst = pinst;
    ea.rr = rr; ea.rs = rs; ea.wbuf = wbuf;
    ea.pe_b0 = pe_b0; ea.pe_b1 = pe_b1; ea.pe_b2 = pe_b2;
    ea.re_b0 = re_b0; ea.re_b1 = re_b1; ea.re_b2 = re_b2;
    ea.pEnc = pEnc; ea.pEff = pEff; ea.relE = relE; ea.aggH = aggH;
    encmlp_k<<<320, 256, ENC_SMEM>>>(ea);

    // 3) propagation: steps 0-1 plain, step 2 with fused head
    const __nv_bfloat16* npW = wbuf + WO_NP0 * 128;   // np_W0|np_W1 contiguous
    for (int step = 0; step < 2; step++) {
        relprop_k<<<BNR / 128, 512, RP2_SMEM>>>(relE, pEff, wbuf + WO_RP * 128,
                                                rp_b, aggH, rr, rs);
        partprop_k<false><<<NODES / 32, 512, PPF_SMEM>>>(
            pEnc, aggH, wbuf + WO_PP * 128, pp_b, pEff, aggH,
            nullptr, nullptr, nullptr, nullptr, nullptr, nullptr, nullptr);
    }
    relprop_k<<<BNR / 128, 512, RP2_SMEM>>>(relE, pEff, wbuf + WO_RP * 128,
                                            rp_b, aggH, rr, rs);
    partprop_k<true><<<NODES / 32, 512, PH_SMEM>>>(
        pEnc, aggH, wbuf + WO_PP * 128, pp_b, pEff, aggH,
        npW, np_b0, np_b1, np_W2, np_b2, state, out);
}

// round 13
// speedup vs baseline: 1.2696x; 1.1045x over previous
#include <cuda_runtime.h>
#include <cuda_bf16.h>
#include <mma.h>
#include <cstdint>

using namespace nvcuda;

// Problem constants
#define BB 2
#define NN 2048
#define NP 2000
#define NREL 8192
#define BNR 16384
#define NODES 4096
#define NF 128

// ---------------- scratch ---------------------------------------------------
__device__ float          g_pin_f[NODES*19];
__device__ __nv_bfloat16  g_pEnc[NODES*NF];
__device__ __nv_bfloat16  g_pEff[NODES*NF];
__device__ __nv_bfloat16  g_relE[BNR*NF];
__device__ __nv_bfloat16  g_aggH[3*NODES*NF];      // 3 rotating buffers
__device__ int            g_rr[BNR];
__device__ int            g_rs[BNR];
__device__ __nv_bfloat16  g_wbuf[1504*128];

// weight row offsets inside g_wbuf
#define WO_PE0 0
#define WO_PE1 32
#define WO_PE2 160
#define WO_RE0 288
#define WO_RE1 352
#define WO_RE2 480
#define WO_PP  608
#define WO_RP  864
#define WO_NP0 1248
#define WO_NP1 1376
#define W_TOTAL_ROWS 1504

// ---------------- helpers ---------------------------------------------------
__device__ __forceinline__ uint32_t pack_bf2(float a, float b) {
    __nv_bfloat162 h = __floats2bfloat162_rn(a, b);
    return *reinterpret_cast<uint32_t*>(&h);
}
__device__ __forceinline__ float2 unpack_bf2(uint32_t u) {
    __nv_bfloat162 h = *reinterpret_cast<__nv_bfloat162*>(&u);
    return make_float2(__bfloat162float(h.x), __bfloat162float(h.y));
}
__device__ __forceinline__ void cpa16(uint32_t d, const void* s) {
    asm volatile("cp.async.cg.shared.global [%0], [%1], 16;" :: "r"(d), "l"(s));
}
__device__ __forceinline__ void cp_commit() {
    asm volatile("cp.async.commit_group;" ::: "memory");
}
__device__ __forceinline__ void cp_wait0() {
    asm volatile("cp.async.wait_group 0;" ::: "memory");
}

// ---------------- weight conversion args ------------------------------------
struct WConvArgs {
    const float* src[10];
    int rowStart[10];
    int srcRows[10];
};

// =====================  prep kernel: convert + build_pin + extract ==========
__global__ void prep_k(const float* __restrict__ Rr, const float* __restrict__ Rs,
                       int* __restrict__ rr, int* __restrict__ rs,
                       const float* __restrict__ state, const float* __restrict__ attrs,
                       const float* __restrict__ action, const float* __restrict__ pden,
                       const float* __restrict__ phys, float* __restrict__ pf,
                       WConvArgs wa, __nv_bfloat16* __restrict__ wbuf) {
    int bid = blockIdx.x, tid = threadIdx.x;

    if (bid < 16) {
        int i = bid * 256 + tid;
        int b = i / NN, n = i - b * NN;
        float o[19];
        o[0] = attrs[i * 2 + 0];
        o[1] = attrs[i * 2 + 1];
        float s[4][3];
#pragma unroll
        for (int t = 0; t < 4; t++)
#pragma unroll
            for (int k = 0; k < 3; k++)
                s[t][k] = state[((size_t)(b * 4 + t) * NN + n) * 3 + k];
#pragma unroll
        for (int t = 0; t < 3; t++)
#pragma unroll
            for (int k = 0; k < 3; k++)
                o[2 + t * 3 + k] = s[t + 1][k] - s[t][k];
#pragma unroll
        for (int k = 0; k < 3; k++) o[11 + k] = s[3][k];
        bool isP = (n < NP);
        o[14] = isP ? phys[b] : 0.f;
#pragma unroll
        for (int k = 0; k < 3; k++) o[15 + k] = action[(size_t)i * 3 + k];
        o[18] = isP ? pden[b] : 0.f;
#pragma unroll
        for (int k = 0; k < 19; k++) pf[(size_t)i * 19 + k] = o[k];
    } else if (bid < 204) {
        int base = (bid - 16) * 1024;
        for (int k = tid; k < 1024; k += 256) {
            int e = base + k;
            int row = e >> 7, col = e & 127;
            int seg = 0;
#pragma unroll
            for (int i = 1; i < 10; i++) if (row >= wa.rowStart[i]) seg = i;
            int r = row - wa.rowStart[seg];
            float v = (r < wa.srcRows[seg]) ? wa.src[seg][r * 128 + col] : 0.f;
            wbuf[row * 128 + col] = __float2bfloat16(v);
        }
    }

    // extract (all 4096 blocks x 8 warps = 32768 row-warps)
    int gw = bid * 8 + (tid >> 5);
    int lane = tid & 31;
    const float* src = (gw < BNR) ? Rr : Rs;
    int row = (gw < BNR) ? gw : gw - BNR;
    const float4* p = reinterpret_cast<const float4*>(src + (size_t)row * NN);
    int found = -1;
    for (int i = 0; i < NN / 128; i++) {
        float4 v = __ldcs(&p[i * 32 + lane]);
        int base = i * 128 + lane * 4;
        if (v.x != 0.f) found = base;
        if (v.y != 0.f) found = base + 1;
        if (v.z != 0.f) found = base + 2;
        if (v.w != 0.f) found = base + 3;
        if (__ballot_sync(0xffffffffu, found >= 0)) break;   // one-hot: done
    }
#pragma unroll
    for (int off = 16; off; off >>= 1)
        found = max(found, __shfl_xor_sync(0xffffffffu, found, off));
    if (lane == 0) {
        int b = row / NREL;
        ((gw < BNR) ? rr : rs)[row] = b * NN + found;
    }
}

// ============  fused 3-layer encoder MLP v2: BM=128, node-cache build  ======
// grid 160: tiles 0..31 particle (K0=32, 128 rows), 32..159 relation (K0=64).
// Relation features built from a smem node cache (coalesced gathers).
#define E2_W_OFF    0                              // 320*136*2 = 87040
#define E2_BIAS_OFF 87040                          // 3*128*4 -> 88576
#define E2_ACT_OFF  88576                          // 128*136*2 -> 123392
#define E2_CS_OFF   123392                         // 128*132*4 -> 190976
#define E2_SMEM     190976

struct EncArgs {
    const float *pf, *attrs, *pinst;
    const int *rr, *rs;
    const __nv_bfloat16* wbuf;
    const float *pe_b0, *pe_b1, *pe_b2, *re_b0, *re_b1, *re_b2;
    __nv_bfloat16 *pEnc, *pEff, *relE, *agg;       // agg: 3 bufs stacked
};

__global__ void __launch_bounds__(512) encmlp_k(EncArgs a) {
    extern __shared__ char sm[];
    __nv_bfloat16* Wsm  = (__nv_bfloat16*)(sm + E2_W_OFF);
    float* biasm        = (float*)(sm + E2_BIAS_OFF);
    __nv_bfloat16* Act  = (__nv_bfloat16*)(sm + E2_ACT_OFF);
    float* Cs           = (float*)(sm + E2_CS_OFF);
    int tid = threadIdx.x, wid = tid >> 5;
    int wm = wid & 7, wn = wid >> 3;               // 8 row x 2 col warp groups
    int t = blockIdx.x;
    bool particle = (t < 32);
    int K0 = particle ? 32 : 64;
    int rowBase = particle ? t * 128 : (t - 32) * 128;

    {
        const __nv_bfloat16 *W0, *W1, *W2;
        const float *b0, *b1, *b2;
        if (particle) {
            W0 = a.wbuf + WO_PE0 * 128; W1 = a.wbuf + WO_PE1 * 128; W2 = a.wbuf + WO_PE2 * 128;
            b0 = a.pe_b0; b1 = a.pe_b1; b2 = a.pe_b2;
        } else {
            W0 = a.wbuf + WO_RE0 * 128; W1 = a.wbuf + WO_RE1 * 128; W2 = a.wbuf + WO_RE2 * 128;
            b0 = a.re_b0; b1 = a.re_b1; b2 = a.re_b2;
        }
        for (int idx = tid; idx < (K0 + 256) * 16; idx += 512) {
            int r = idx >> 4, c8 = (idx & 15) * 8;
            const __nv_bfloat16* src;
            if (r < K0)            src = W0 + (size_t)r * 128 + c8;
            else if (r < K0 + 128) src = W1 + (size_t)(r - K0) * 128 + c8;
            else                   src = W2 + (size_t)(r - K0 - 128) * 128 + c8;
            *(uint4*)&Wsm[r * 136 + c8] = *(const uint4*)src;
        }
        for (int i = tid; i < 128; i += 512) {
            biasm[i] = b0[i]; biasm[128 + i] = b1[i]; biasm[256 + i] = b2[i];
        }
    }

    if (particle) {
        for (int idx = tid; idx < 128 * 32; idx += 512) {
            int r = idx >> 5, k = idx & 31;
            float v = (k < 19) ? a.pf[(size_t)(rowBase + r) * 19 + k] : 0.f;
            Act[r * 136 + k] = __float2bfloat16(v);
        }
    } else {
        // stage node cache in (dead) Cs region: 256 slots x 30 floats
        // slot s<128: receiver of edge s; s>=128: sender of edge s-128.
        // layout: [0:19) pf, [19:21) attrs, [21:29) pinst (0 if scene node)
        float* cache = Cs;
        for (int idx = tid; idx < 256 * 30; idx += 512) {
            int s = idx / 30, k2 = idx - s * 30;
            int node = (s < 128) ? a.rr[rowBase + s] : a.rs[rowBase + s - 128];
            float v = 0.f;
            if (k2 < 19)      v = a.pf[(size_t)node * 19 + k2];
            else if (k2 < 21) v = a.attrs[node * 2 + (k2 - 19)];
            else if (k2 < 29) {
                int b = node >> 11, n = node & (NN - 1);
                v = (n < NP) ? a.pinst[((size_t)b * NP + n) * 8 + (k2 - 21)] : 0.f;
            }
            cache[s * 30 + k2] = v;
        }
        __syncthreads();
        for (int idx = tid; idx < 128 * 64; idx += 512) {
            int r = idx >> 6, k = idx & 63;
            const float* cr = cache + r * 30;
            const float* cse = cache + (128 + r) * 30;
            float v;
            if (k < 19)       v = cr[k];
            else if (k < 38)  v = cse[k - 19];
            else if (k < 40)  v = cr[19 + (k - 38)];
            else if (k < 42)  v = cse[19 + (k - 40)];
            else if (k == 42) {
                float gd = 0.f;
#pragma unroll
                for (int j = 0; j < 8; j++) gd += fabsf(cr[21 + j] - cse[21 + j]);
                v = gd;
            }
            else if (k < 55)  v = cr[2 + (k - 43)] - cse[2 + (k - 43)];
            else if (k == 55) v = cr[18] - cse[18];
            else              v = 0.f;
            Act[r * 136 + k] = __float2bfloat16(v);
        }
    }
    __syncthreads();

    for (int L = 0; L < 3; L++) {
        int KL = (L == 0) ? K0 : 128;
        const __nv_bfloat16* WL = Wsm + (size_t)((L == 0) ? 0 : K0 + (L - 1) * 128) * 136;
        wmma::fragment<wmma::accumulator, 16, 16, 16, float> acc[4];
#pragma unroll
        for (int nf = 0; nf < 4; nf++) wmma::fill_fragment(acc[nf], 0.f);
        for (int kc = 0; kc < KL / 16; kc++) {
            wmma::fragment<wmma::matrix_a, 16, 16, 16, __nv_bfloat16, wmma::row_major> af;
            wmma::load_matrix_sync(af, Act + (wm * 16) * 136 + kc * 16, 136);
#pragma unroll
            for (int nf = 0; nf < 4; nf++) {
                wmma::fragment<wmma::matrix_b, 16, 16, 16, __nv_bfloat16, wmma::row_major> bf;
                wmma::load_matrix_sync(bf, WL + (kc * 16) * 136 + wn * 64 + nf * 16, 136);
                wmma::mma_sync(acc[nf], af, bf, acc[nf]);
            }
        }
        __syncthreads();                          // cache/Cs dead; Act reads done
#pragma unroll
        for (int nf = 0; nf < 4; nf++)
            wmma::store_matrix_sync(Cs + (wm * 16) * 132 + wn * 64 + nf * 16,
                                    acc[nf], 132, wmma::mem_row_major);
        __syncthreads();
        const float* bL = biasm + L * 128;
#pragma unroll
        for (int it = 0; it < 8; it++) {
            int e = tid + it * 512, row = e >> 5, c4 = (e & 31) * 4;
            float4 v = *(float4*)&Cs[row * 132 + c4];
            float4 b = *(const float4*)&bL[c4];
            v.x = fmaxf(v.x + b.x, 0.f); v.y = fmaxf(v.y + b.y, 0.f);
            v.z = fmaxf(v.z + b.z, 0.f); v.w = fmaxf(v.w + b.w, 0.f);
            uint2 o; o.x = pack_bf2(v.x, v.y); o.y = pack_bf2(v.z, v.w);
            if (L < 2) {
                *(uint2*)&Act[row * 136 + c4] = o;
            } else {
                size_t go = (size_t)(rowBase + row) * 128 + c4;
                if (particle) {
                    *(uint2*)&a.pEnc[go] = o;
                    *(uint2*)&a.pEff[go] = o;
                    uint2 z = make_uint2(0u, 0u);
                    *(uint2*)&a.agg[go] = z;
                    *(uint2*)&a.agg[go + (size_t)NODES * NF] = z;
                    *(uint2*)&a.agg[go + (size_t)2 * NODES * NF] = z;
                } else {
                    *(uint2*)&a.relE[go] = o;
                }
            }
        }
        __syncthreads();
    }
}

// =============  relation propagator v2: fully-resident (R11-proven) =========
#define RPA_LD 392
#define RP2_W_OFF   (128*RPA_LD*2)                 // 100352
#define RP2_IDX_OFF (RP2_W_OFF + 384*136*2)        // 204800
#define RP2_BIAS_OFF (RP2_IDX_OFF + 256*4)         // 205824
#define RP2_SMEM    (RP2_BIAS_OFF + 128*4)         // 206336

__global__ void __launch_bounds__(512) relprop_k(
    const __nv_bfloat16* __restrict__ relE,
    const __nv_bfloat16* __restrict__ pEff,
    const __nv_bfloat16* __restrict__ W,
    const float* __restrict__ bias,
    __nv_bfloat16* __restrict__ aggH,
    const int* __restrict__ rr, const int* __restrict__ rs)
{
    extern __shared__ char sm[];
    __nv_bfloat16* Asm = (__nv_bfloat16*)sm;
    __nv_bfloat16* Wsm = (__nv_bfloat16*)(sm + RP2_W_OFF);
    int*   idxs        = (int*)(sm + RP2_IDX_OFF);
    float* biasm       = (float*)(sm + RP2_BIAS_OFF);
    float* Cs          = (float*)sm;                 // overlay A post-mainloop

    int tid = threadIdx.x, wid = tid >> 5;
    int wm = wid & 7, wn = wid >> 3;                 // 8 row x 2 col warp groups
    int rowBase = blockIdx.x * 128;

    if (tid < 128)      idxs[tid]       = rr[rowBase + tid];
    else if (tid < 256) idxs[tid]       = rs[rowBase + tid - 128];
    if (tid < 128) biasm[tid] = bias[tid];
    __syncthreads();                                 // idxs visible for gather

    uint32_t asB = (uint32_t)__cvta_generic_to_shared(Asm);
    uint32_t wsB = (uint32_t)__cvta_generic_to_shared(Wsm);

    for (int c = tid; c < 128 * 48; c += 512) {
        int row = c / 48, ch = c % 48;
        int seg = ch >> 4, off = (ch & 15) * 8;
        const __nv_bfloat16* src;
        if (seg == 0)      src = relE + (size_t)(rowBase + row) * 128 + off;
        else if (seg == 1) src = pEff + (size_t)idxs[row] * 128 + off;
        else               src = pEff + (size_t)idxs[128 + row] * 128 + off;
        cpa16(asB + (uint32_t)(row * RPA_LD + seg * 128 + off) * 2, src);
    }
    for (int c = tid; c < 384 * 16; c += 512) {
        int row = c >> 4, c8 = (c & 15) * 8;
        cpa16(wsB + (uint32_t)(row * 136 + c8) * 2, W + (size_t)row * 128 + c8);
    }
    cp_commit(); cp_wait0();
    __syncthreads();

    wmma::fragment<wmma::accumulator, 16, 16, 16, float> acc[4];
#pragma unroll
    for (int nf = 0; nf < 4; nf++) wmma::fill_fragment(acc[nf], 0.f);
    for (int kt = 0; kt < 24; kt++) {
        wmma::fragment<wmma::matrix_a, 16, 16, 16, __nv_bfloat16, wmma::row_major> af;
        wmma::load_matrix_sync(af, Asm + (wm * 16) * RPA_LD + kt * 16, RPA_LD);
#pragma unroll
        for (int nf = 0; nf < 4; nf++) {
            wmma::fragment<wmma::matrix_b, 16, 16, 16, __nv_bfloat16, wmma::row_major> bf;
            wmma::load_matrix_sync(bf, Wsm + (kt * 16) * 136 + wn * 64 + nf * 16, 136);
            wmma::mma_sync(acc[nf], af, bf, acc[nf]);
        }
    }
    __syncthreads();                                 // A reads done before overlay
#pragma unroll
    for (int nf = 0; nf < 4; nf++)
        wmma::store_matrix_sync(Cs + (wm * 16) * 132 + wn * 64 + nf * 16,
                                acc[nf], 132, wmma::mem_row_major);
    __syncthreads();
#pragma unroll
    for (int it = 0; it < 8; it++) {
        int e = tid + it * 512, row = e >> 5, c4 = (e & 31) * 4;
        float4 v = *(float4*)&Cs[row * 132 + c4];
        float4 b = *(const float4*)&biasm[c4];
        __nv_bfloat162* dst =
            (__nv_bfloat162*)(aggH + (size_t)idxs[row] * 128 + c4);
        atomicAdd(dst,     __floats2bfloat162_rn(fmaxf(v.x + b.x, 0.f),
                                                 fmaxf(v.y + b.y, 0.f)));
        atomicAdd(dst + 1, __floats2bfloat162_rn(fmaxf(v.z + b.z, 0.f),
                                                 fmaxf(v.w + b.w, 0.f)));
    }
}

// =============  particle propagator v4: N-split, zero-free, resid prefetch ==
// BM=32 x 64 cols; grid 256 (t = bx>>1, half = bx&1); 256 threads, ~57KB smem.
// A = [pEnc | aggIn] (32x264, read-only); W half (256x72); resid pEff half.
// NO aggH writes (3-buffer rotation makes aggIn strictly read-only).
#define PPA_LD 264
#define P4_W_OFF    (32*PPA_LD*2)                  // 16896
#define P4_RES_OFF  (P4_W_OFF + 256*72*2)          // 53760
#define P4_BIAS_OFF (P4_RES_OFF + 32*80*2)         // 58880
#define P4_SMEM     (P4_BIAS_OFF + 256)            // 59136

__global__ void __launch_bounds__(256) partprop_k(
    const __nv_bfloat16* __restrict__ pEnc,
    const __nv_bfloat16* __restrict__ aggIn,
    const __nv_bfloat16* __restrict__ W,
    const float* __restrict__ bias,
    __nv_bfloat16* __restrict__ pEff)
{
    extern __shared__ char sm[];
    __nv_bfloat16* Asm  = (__nv_bfloat16*)sm;
    __nv_bfloat16* Wsm  = (__nv_bfloat16*)(sm + P4_W_OFF);
    __nv_bfloat16* Res  = (__nv_bfloat16*)(sm + P4_RES_OFF);
    float* biasm        = (float*)(sm + P4_BIAS_OFF);
    float* Cs           = (float*)sm;                // overlays Asm post-mainloop

    int tid = threadIdx.x, wid = tid >> 5;
    int wm = wid & 1, wn = wid >> 1;                 // 2 row x 4 col warp groups
    int t = blockIdx.x >> 1, half = blockIdx.x & 1;
    int rowBase = t * 32;
    int colBase = half * 64;

    if (tid < 64) biasm[tid] = bias[colBase + tid];

    uint32_t asB = (uint32_t)__cvta_generic_to_shared(Asm);
    uint32_t wsB = (uint32_t)__cvta_generic_to_shared(Wsm);
    uint32_t reB = (uint32_t)__cvta_generic_to_shared(Res);

    // A: 32 rows x 32 chunks ([pEnc | aggIn], full K=256)
    for (int c = tid; c < 32 * 32; c += 256) {
        int row = c >> 5, off = (c & 31) * 8;
        const __nv_bfloat16* src;
        if (off < 128) src = pEnc  + (size_t)(rowBase + row) * 128 + off;
        else           src = aggIn + (size_t)(rowBase + row) * 128 + (off - 128);
        cpa16(asB + (uint32_t)(row * PPA_LD + off) * 2, src);
    }
    // W half: 256 rows x 8 chunks (stride 72)
    for (int c = tid; c < 256 * 8; c += 256) {
        int row = c >> 3, c8 = (c & 7) * 8;
        cpa16(wsB + (uint32_t)(row * 72 + c8) * 2,
              W + (size_t)row * 128 + colBase + c8);
    }
    // resid: pEff half, 32 rows x 8 chunks (stride 80, 16B-aligned rows)
    for (int c = tid; c < 32 * 8; c += 256) {
        int row = c >> 3, c8 = (c & 7) * 8;
        cpa16(reB + (uint32_t)(row * 80 + c8) * 2,
              pEff + (size_t)(rowBase + row) * 128 + colBase + c8);
    }
    cp_commit(); cp_wait0();
    __syncthreads();

    wmma::fragment<wmma::accumulator, 16, 16, 16, float> acc;
    wmma::fill_fragment(acc, 0.f);
    for (int kt = 0; kt < 16; kt++) {
        wmma::fragment<wmma::matrix_a, 16, 16, 16, __nv_bfloat16, wmma::row_major> af;
        wmma::load_matrix_sync(af, Asm + (wm * 16) * PPA_LD + kt * 16, PPA_LD);
        wmma::fragment<wmma::matrix_b, 16, 16, 16, __nv_bfloat16, wmma::row_major> bf;
        wmma::load_matrix_sync(bf, Wsm + (kt * 16) * 72 + wn * 16, 72);
        wmma::mma_sync(acc, af, bf, acc);
    }
    __syncthreads();                                 // Asm reads done before overlay
    wmma::store_matrix_sync(Cs + (wm * 16) * 68 + wn * 16, acc, 68,
                            wmma::mem_row_major);
    __syncthreads();
#pragma unroll
    for (int it = 0; it < 2; it++) {
        int e = tid + it * 256, row = e >> 4, c4 = (e & 15) * 4;
        float4 v = *(float4*)&Cs[row * 68 + c4];
        float4 b = *(const float4*)&biasm[c4];
        uint2 rv = *(const uint2*)&Res[row * 80 + c4];
        float2 r0 = unpack_bf2(rv.x), r1 = unpack_bf2(rv.y);
        v.x = fmaxf(v.x + b.x + r0.x, 0.f);
        v.y = fmaxf(v.y + b.y + r0.y, 0.f);
        v.z = fmaxf(v.z + b.z + r1.x, 0.f);
        v.w = fmaxf(v.w + b.w + r1.y, 0.f);
        uint2 o; o.x = pack_bf2(v.x, v.y); o.y = pack_bf2(v.z, v.w);
        *(uint2*)&pEff[(size_t)(rowBase + row) * 128 + colBase + c4] = o;
    }
}

// =============  final particle propagator with fused head (R12-proven) ======
#define PH_W_OFF    (32*PPA_LD*2)                  // 16896
#define PH_NW_OFF   (PH_W_OFF + 256*136*2)         // 86528
#define PH_BIAS_OFF (PH_NW_OFF + 256*136*2)        // 156160
#define PH_NB0_OFF  (PH_BIAS_OFF + 512)            // 156672
#define PH_NB1_OFF  (PH_NB0_OFF + 512)             // 157184
#define PH_W2_OFF   (PH_NB1_OFF + 512)             // 157696
#define PH_B2_OFF   (PH_W2_OFF + 1536)             // 159232
#define PH_ACT_OFF  (PH_B2_OFF + 16)               // 159248
#define PH_SMEM     (PH_ACT_OFF + 32*136*2)        // 167952

__global__ void __launch_bounds__(512) partproph_k(
    const __nv_bfloat16* __restrict__ pEnc,
    const __nv_bfloat16* __restrict__ aggIn,
    const __nv_bfloat16* __restrict__ W,
    const float* __restrict__ bias,
    const __nv_bfloat16* __restrict__ pEff,
    const __nv_bfloat16* __restrict__ npW,
    const float* __restrict__ nb0, const float* __restrict__ nb1,
    const float* __restrict__ W2, const float* __restrict__ b2,
    const float* __restrict__ state, float* __restrict__ out)
{
    extern __shared__ char sm[];
    __nv_bfloat16* Asm  = (__nv_bfloat16*)sm;
    __nv_bfloat16* Wsm  = (__nv_bfloat16*)(sm + PH_W_OFF);
    __nv_bfloat16* NWsm = (__nv_bfloat16*)(sm + PH_NW_OFF);
    float* biasm        = (float*)(sm + PH_BIAS_OFF);
    float* nb0s         = (float*)(sm + PH_NB0_OFF);
    float* nb1s         = (float*)(sm + PH_NB1_OFF);
    float* W2s          = (float*)(sm + PH_W2_OFF);
    float* b2s          = (float*)(sm + PH_B2_OFF);
    __nv_bfloat16* Act  = (__nv_bfloat16*)(sm + PH_ACT_OFF);
    float* Cs           = (float*)sm;

    int tid = threadIdx.x, wid = tid >> 5, lane = tid & 31;
    int wm = wid & 1, wn = wid >> 1;                 // 2 row x 8 col warp groups
    int rowBase = blockIdx.x * 32;

    for (int i = tid; i < 128; i += 512) {
        biasm[i] = bias[i]; nb0s[i] = nb0[i]; nb1s[i] = nb1[i];
    }
    for (int i = tid; i < 384; i += 512) W2s[i] = W2[i];
    if (tid < 3) b2s[tid] = b2[tid];

    uint32_t asB = (uint32_t)__cvta_generic_to_shared(Asm);
    uint32_t wsB = (uint32_t)__cvta_generic_to_shared(Wsm);
    uint32_t nwB = (uint32_t)__cvta_generic_to_shared(NWsm);

    for (int c = tid; c < 32 * 32; c += 512) {
        int row = c >> 5, off = (c & 31) * 8;
        const __nv_bfloat16* src;
        if (off < 128) src = pEnc  + (size_t)(rowBase + row) * 128 + off;
        else           src = aggIn + (size_t)(rowBase + row) * 128 + (off - 128);
        cpa16(asB + (uint32_t)(row * PPA_LD + off) * 2, src);
    }
    for (int c = tid; c < 256 * 16; c += 512) {
        int row = c >> 4, c8 = (c & 15) * 8;
        cpa16(wsB + (uint32_t)(row * 136 + c8) * 2, W + (size_t)row * 128 + c8);
        cpa16(nwB + (uint32_t)(row * 136 + c8) * 2, npW + (size_t)row * 128 + c8);
    }
    cp_commit(); cp_wait0();
    __syncthreads();

    // propagator GEMM (K=256)
    wmma::fragment<wmma::accumulator, 16, 16, 16, float> acc;
    wmma::fill_fragment(acc, 0.f);
    for (int kt = 0; kt < 16; kt++) {
        wmma::fragment<wmma::matrix_a, 16, 16, 16, __nv_bfloat16, wmma::row_major> af;
        wmma::load_matrix_sync(af, Asm + (wm * 16) * PPA_LD + kt * 16, PPA_LD);
        wmma::fragment<wmma::matrix_b, 16, 16, 16, __nv_bfloat16, wmma::row_major> bf;
        wmma::load_matrix_sync(bf, Wsm + (kt * 16) * 136 + wn * 16, 136);
        wmma::mma_sync(acc, af, bf, acc);
    }
    __syncthreads();
    wmma::store_matrix_sync(Cs + (wm * 16) * 132 + wn * 16, acc, 132,
                            wmma::mem_row_major);
    __syncthreads();
#pragma unroll
    for (int it = 0; it < 2; it++) {
        int e = tid + it * 512, row = e >> 5, c4 = (e & 31) * 4;
        size_t go = (size_t)(rowBase + row) * 128 + c4;
        float4 v = *(float4*)&Cs[row * 132 + c4];
        float4 b = *(const float4*)&biasm[c4];
        uint2 rv = *(const uint2*)&pEff[go];
        float2 r0 = unpack_bf2(rv.x), r1 = unpack_bf2(rv.y);
        v.x = fmaxf(v.x + b.x + r0.x, 0.f);
        v.y = fmaxf(v.y + b.y + r0.y, 0.f);
        v.z = fmaxf(v.z + b.z + r1.x, 0.f);
        v.w = fmaxf(v.w + b.w + r1.y, 0.f);
        uint2 o; o.x = pack_bf2(v.x, v.y); o.y = pack_bf2(v.z, v.w);
        *(uint2*)&Act[row * 136 + c4] = o;           // smem only
    }
    __syncthreads();

    // np0
    {
        wmma::fragment<wmma::accumulator, 16, 16, 16, float> a2;
        wmma::fill_fragment(a2, 0.f);
#pragma unroll
        for (int kt = 0; kt < 8; kt++) {
            wmma::fragment<wmma::matrix_a, 16, 16, 16, __nv_bfloat16, wmma::row_major> af;
            wmma::load_matrix_sync(af, Act + (wm * 16) * 136 + kt * 16, 136);
            wmma::fragment<wmma::matrix_b, 16, 16, 16, __nv_bfloat16, wmma::row_major> bf;
            wmma::load_matrix_sync(bf, NWsm + (kt * 16) * 136 + wn * 16, 136);
            wmma::mma_sync(a2, af, bf, a2);
        }
        __syncthreads();
        wmma::store_matrix_sync(Cs + (wm * 16) * 132 + wn * 16, a2, 132,
                                wmma::mem_row_major);
        __syncthreads();
#pragma unroll
        for (int it = 0; it < 2; it++) {
            int e = tid + it * 512, row = e >> 5, c4 = (e & 31) * 4;
            float4 v = *(float4*)&Cs[row * 132 + c4];
            float4 b = *(const float4*)&nb0s[c4];
            uint2 o;
            o.x = pack_bf2(fmaxf(v.x + b.x, 0.f), fmaxf(v.y + b.y, 0.f));
            o.y = pack_bf2(fmaxf(v.z + b.z, 0.f), fmaxf(v.w + b.w, 0.f));
            *(uint2*)&Act[row * 136 + c4] = o;
        }
        __syncthreads();
    }
    // np1
    {
        wmma::fragment<wmma::accumulator, 16, 16, 16, float> a2;
        wmma::fill_fragment(a2, 0.f);
#pragma unroll
        for (int kt = 0; kt < 8; kt++) {
            wmma::fragment<wmma::matrix_a, 16, 16, 16, __nv_bfloat16, wmma::row_major> af;
            wmma::load_matrix_sync(af, Act + (wm * 16) * 136 + kt * 16, 136);
            wmma::fragment<wmma::matrix_b, 16, 16, 16, __nv_bfloat16, wmma::row_major> bf;
            wmma::load_matrix_sync(bf, NWsm + ((128 + kt * 16)) * 136 + wn * 16, 136);
            wmma::mma_sync(a2, af, bf, a2);
        }
        __syncthreads();
        wmma::store_matrix_sync(Cs + (wm * 16) * 132 + wn * 16, a2, 132,
                                wmma::mem_row_major);
        __syncthreads();
    }
    // final: h1 = relu(Cs + nb1); motion = h1 @ W2 + b2; clamp; add
#pragma unroll
    for (int i = 0; i < 2; i++) {
        int row = wid * 2 + i;
        int grow = rowBase + row;
        int b = grow >> 11, n = grow & (NN - 1);
        float hv[4];
#pragma unroll
        for (int j = 0; j < 4; j++)
            hv[j] = fmaxf(Cs[row * 132 + lane + 32 * j] + nb1s[lane + 32 * j], 0.f);
#pragma unroll
        for (int k = 0; k < 3; k++) {
            float sacc = 0.f;
#pragma unroll
            for (int j = 0; j < 4; j++)
                sacc += hv[j] * W2s[(lane + 32 * j) * 3 + k];
#pragma unroll
            for (int off = 16; off; off >>= 1)
                sacc += __shfl_xor_sync(0xffffffffu, sacc, off);
            if (lane == 0 && n < NP) {
                float m = fminf(fmaxf(sacc + b2s[k], -100.f), 100.f);
                out[((size_t)b * NP + n) * 3 + k] =
                    state[((size_t)(b * 4 + 3) * NN + n) * 3 + k] + m;
            }
        }
    }
}

// ---------------------------------------------------------------------------
extern "C" void kernel_launch(void* const* d_in, const int* in_sizes, int n_in,
                              void* d_out, int out_size) {
    const float* state  = (const float*)d_in[0];
    const float* attrs  = (const float*)d_in[1];
    const float* Rr     = (const float*)d_in[2];
    const float* Rs     = (const float*)d_in[3];
    const float* pinst  = (const float*)d_in[4];
    const float* action = (const float*)d_in[5];
    const float* pden   = (const float*)d_in[6];
    const float* phys   = (const float*)d_in[7];
    const float* pe_W0 = (const float*)d_in[8],  *pe_b0 = (const float*)d_in[9];
    const float* pe_W1 = (const float*)d_in[10], *pe_b1 = (const float*)d_in[11];
    const float* pe_W2 = (const float*)d_in[12], *pe_b2 = (const float*)d_in[13];
    const float* re_W0 = (const float*)d_in[14], *re_b0 = (const float*)d_in[15];
    const float* re_W1 = (const float*)d_in[16], *re_b1 = (const float*)d_in[17];
    const float* re_W2 = (const float*)d_in[18], *re_b2 = (const float*)d_in[19];
    const float* pp_W  = (const float*)d_in[20], *pp_b  = (const float*)d_in[21];
    const float* rp_W  = (const float*)d_in[22], *rp_b  = (const float*)d_in[23];
    const float* np_W0 = (const float*)d_in[24], *np_b0 = (const float*)d_in[25];
    const float* np_W1 = (const float*)d_in[26], *np_b1 = (const float*)d_in[27];
    const float* np_W2 = (const float*)d_in[28], *np_b2 = (const float*)d_in[29];
    float* out = (float*)d_out;

    float* pin_f;
    __nv_bfloat16 *pEnc, *pEff, *relE, *aggH, *wbuf;
    int *rr, *rs;
    cudaGetSymbolAddress((void**)&pin_f, g_pin_f);
    cudaGetSymbolAddress((void**)&pEnc,  g_pEnc);
    cudaGetSymbolAddress((void**)&pEff,  g_pEff);
    cudaGetSymbolAddress((void**)&relE,  g_relE);
    cudaGetSymbolAddress((void**)&aggH,  g_aggH);
    cudaGetSymbolAddress((void**)&rr,    g_rr);
    cudaGetSymbolAddress((void**)&rs,    g_rs);
    cudaGetSymbolAddress((void**)&wbuf,  g_wbuf);

    cudaFuncSetAttribute(encmlp_k,   cudaFuncAttributeMaxDynamicSharedMemorySize, E2_SMEM);
    cudaFuncSetAttribute(relprop_k,  cudaFuncAttributeMaxDynamicSharedMemorySize, RP2_SMEM);
    cudaFuncSetAttribute(partprop_k, cudaFuncAttributeMaxDynamicSharedMemorySize, P4_SMEM);
    cudaFuncSetAttribute(partproph_k,cudaFuncAttributeMaxDynamicSharedMemorySize, PH_SMEM);

    WConvArgs wa;
    const float* srcs[10] = {pe_W0, pe_W1, pe_W2, re_W0, re_W1, re_W2,
                             pp_W, rp_W, np_W0, np_W1};
    const int starts[10]  = {WO_PE0, WO_PE1, WO_PE2, WO_RE0, WO_RE1, WO_RE2,
                             WO_PP, WO_RP, WO_NP0, WO_NP1};
    const int srows[10]   = {19, 128, 128, 56, 128, 128, 256, 384, 128, 128};
    for (int i = 0; i < 10; i++) {
        wa.src[i] = srcs[i]; wa.rowStart[i] = starts[i]; wa.srcRows[i] = srows[i];
    }

    // 1) convert weights + build particle features + extract indices
    prep_k<<<4096, 256>>>(Rr, Rs, rr, rs, state, attrs, action, pden, phys,
                          pin_f, wa, wbuf);

    // 2) fused 3-layer encoders (BM=128); zeroes all 3 agg buffers
    EncArgs ea;
    ea.pf = pin_f; ea.attrs = attrs; ea.pinst = pinst;
    ea.rr = rr; ea.rs = rs; ea.wbuf = wbuf;
    ea.pe_b0 = pe_b0; ea.pe_b1 = pe_b1; ea.pe_b2 = pe_b2;
    ea.re_b0 = re_b0; ea.re_b1 = re_b1; ea.re_b2 = re_b2;
    ea.pEnc = pEnc; ea.pEff = pEff; ea.relE = relE; ea.agg = aggH;
    encmlp_k<<<160, 512, E2_SMEM>>>(ea);

    // 3) propagation: rotating agg buffers (never re-zeroed mid-run)
    const __nv_bfloat16* npW = wbuf + WO_NP0 * 128;
    for (int step = 0; step < 2; step++) {
        __nv_bfloat16* buf = aggH + (size_t)step * NODES * NF;
        relprop_k<<<BNR / 128, 512, RP2_SMEM>>>(relE, pEff, wbuf + WO_RP * 128,
                                                rp_b, buf, rr, rs);
        partprop_k<<<(NODES / 32) * 2, 256, P4_SMEM>>>(
            pEnc, buf, wbuf + WO_PP * 128, pp_b, pEff);
    }
    __nv_bfloat16* buf2 = aggH + (size_t)2 * NODES * NF;
    relprop_k<<<BNR / 128, 512, RP2_SMEM>>>(relE, pEff, wbuf + WO_RP * 128,
                                            rp_b, buf2, rr, rs);
    partproph_k<<<NODES / 32, 512, PH_SMEM>>>(
        pEnc, buf2, wbuf + WO_PP * 128, pp_b, pEff,
        npW, np_b0, np_b1, np_W2, np_b2, state, out);
}

// round 14
// speedup vs baseline: 1.3303x; 1.0478x over previous
#include <cuda_runtime.h>
#include <cuda_bf16.h>
#include <mma.h>
#include <cstdint>

using namespace nvcuda;

// Problem constants
#define BB 2
#define NN 2048
#define NP 2000
#define NREL 8192
#define BNR 16384
#define NODES 4096
#define NF 128

// ---------------- scratch ---------------------------------------------------
__device__ float          g_pin_f[NODES*19];
__device__ __nv_bfloat16  g_pEnc[NODES*NF];
__device__ __nv_bfloat16  g_pEff[NODES*NF];
__device__ __nv_bfloat16  g_relE[BNR*NF];
__device__ float          g_relBase[BNR*NF];       // relE @ rpW0 + rp_b (f32)
__device__ __nv_bfloat16  g_aggH[3*NODES*NF];      // 3 rotating buffers
__device__ int            g_rr[BNR];
__device__ int            g_rs[BNR];
__device__ __nv_bfloat16  g_wbuf[1504*128];

// weight row offsets inside g_wbuf
#define WO_PE0 0
#define WO_PE1 32
#define WO_PE2 160
#define WO_RE0 288
#define WO_RE1 352
#define WO_RE2 480
#define WO_PP  608
#define WO_RP  864
#define WO_NP0 1248
#define WO_NP1 1376
#define W_TOTAL_ROWS 1504

// ---------------- helpers ---------------------------------------------------
__device__ __forceinline__ uint32_t pack_bf2(float a, float b) {
    __nv_bfloat162 h = __floats2bfloat162_rn(a, b);
    return *reinterpret_cast<uint32_t*>(&h);
}
__device__ __forceinline__ float2 unpack_bf2(uint32_t u) {
    __nv_bfloat162 h = *reinterpret_cast<__nv_bfloat162*>(&u);
    return make_float2(__bfloat162float(h.x), __bfloat162float(h.y));
}
__device__ __forceinline__ void cpa16(uint32_t d, const void* s) {
    asm volatile("cp.async.cg.shared.global [%0], [%1], 16;" :: "r"(d), "l"(s));
}
__device__ __forceinline__ void cp_commit() {
    asm volatile("cp.async.commit_group;" ::: "memory");
}
__device__ __forceinline__ void cp_wait0() {
    asm volatile("cp.async.wait_group 0;" ::: "memory");
}

// ---------------- weight conversion args ------------------------------------
struct WConvArgs {
    const float* src[10];
    int rowStart[10];
    int srcRows[10];
};

// =====================  prep kernel: convert + build_pin + extract ==========
__global__ void prep_k(const float* __restrict__ Rr, const float* __restrict__ Rs,
                       int* __restrict__ rr, int* __restrict__ rs,
                       const float* __restrict__ state, const float* __restrict__ attrs,
                       const float* __restrict__ action, const float* __restrict__ pden,
                       const float* __restrict__ phys, float* __restrict__ pf,
                       WConvArgs wa, __nv_bfloat16* __restrict__ wbuf) {
    int bid = blockIdx.x, tid = threadIdx.x;

    if (bid < 16) {
        int i = bid * 256 + tid;
        int b = i / NN, n = i - b * NN;
        float o[19];
        o[0] = attrs[i * 2 + 0];
        o[1] = attrs[i * 2 + 1];
        float s[4][3];
#pragma unroll
        for (int t = 0; t < 4; t++)
#pragma unroll
            for (int k = 0; k < 3; k++)
                s[t][k] = state[((size_t)(b * 4 + t) * NN + n) * 3 + k];
#pragma unroll
        for (int t = 0; t < 3; t++)
#pragma unroll
            for (int k = 0; k < 3; k++)
                o[2 + t * 3 + k] = s[t + 1][k] - s[t][k];
#pragma unroll
        for (int k = 0; k < 3; k++) o[11 + k] = s[3][k];
        bool isP = (n < NP);
        o[14] = isP ? phys[b] : 0.f;
#pragma unroll
        for (int k = 0; k < 3; k++) o[15 + k] = action[(size_t)i * 3 + k];
        o[18] = isP ? pden[b] : 0.f;
#pragma unroll
        for (int k = 0; k < 19; k++) pf[(size_t)i * 19 + k] = o[k];
    } else if (bid < 204) {
        int base = (bid - 16) * 1024;
        for (int k = tid; k < 1024; k += 256) {
            int e = base + k;
            int row = e >> 7, col = e & 127;
            int seg = 0;
#pragma unroll
            for (int i = 1; i < 10; i++) if (row >= wa.rowStart[i]) seg = i;
            int r = row - wa.rowStart[seg];
            float v = (r < wa.srcRows[seg]) ? wa.src[seg][r * 128 + col] : 0.f;
            wbuf[row * 128 + col] = __float2bfloat16(v);
        }
    }

    // extract (all 4096 blocks x 8 warps = 32768 row-warps)
    int gw = bid * 8 + (tid >> 5);
    int lane = tid & 31;
    const float* src = (gw < BNR) ? Rr : Rs;
    int row = (gw < BNR) ? gw : gw - BNR;
    const float4* p = reinterpret_cast<const float4*>(src + (size_t)row * NN);
    int found = -1;
    for (int i = 0; i < NN / 128; i++) {
        float4 v = __ldcs(&p[i * 32 + lane]);
        int base = i * 128 + lane * 4;
        if (v.x != 0.f) found = base;
        if (v.y != 0.f) found = base + 1;
        if (v.z != 0.f) found = base + 2;
        if (v.w != 0.f) found = base + 3;
        if (__ballot_sync(0xffffffffu, found >= 0)) break;   // one-hot: done
    }
#pragma unroll
    for (int off = 16; off; off >>= 1)
        found = max(found, __shfl_xor_sync(0xffffffffu, found, off));
    if (lane == 0) {
        int b = row / NREL;
        ((gw < BNR) ? rr : rs)[row] = b * NN + found;
    }
}

// ============  fused 3-layer encoder MLP + relBase precompute  ==============
// grid 160: tiles 0..31 particle (128 rows), 32..159 relation.
// Relation tiles also compute relBase = relE @ rpW0 + rp_b (layer 4, f32 out).
#define E2_W_OFF    0                              // 320*136*2 = 87040
#define E2_BIAS_OFF 87040                          // 4*128*4 -> 89088
#define E2_ACT_OFF  89088                          // 128*136*2 -> 123904
#define E2_CS_OFF   123904                         // 128*132*4 -> 191488
#define E2_RPW_OFF  191488                         // 128*136*2 -> 226304
#define E2_SMEM     226304

struct EncArgs {
    const float *pf, *attrs, *pinst;
    const int *rr, *rs;
    const __nv_bfloat16* wbuf;
    const float *pe_b0, *pe_b1, *pe_b2, *re_b0, *re_b1, *re_b2, *rp_b;
    __nv_bfloat16 *pEnc, *pEff, *relE, *agg;
    float* relBase;
};

__global__ void __launch_bounds__(512) encmlp_k(EncArgs a) {
    extern __shared__ char sm[];
    __nv_bfloat16* Wsm  = (__nv_bfloat16*)(sm + E2_W_OFF);
    float* biasm        = (float*)(sm + E2_BIAS_OFF);
    __nv_bfloat16* Act  = (__nv_bfloat16*)(sm + E2_ACT_OFF);
    float* Cs           = (float*)(sm + E2_CS_OFF);
    __nv_bfloat16* RPW  = (__nv_bfloat16*)(sm + E2_RPW_OFF);
    int tid = threadIdx.x, wid = tid >> 5;
    int wm = wid & 7, wn = wid >> 3;               // 8 row x 2 col warp groups
    int t = blockIdx.x;
    bool particle = (t < 32);
    int K0 = particle ? 32 : 64;
    int rowBase = particle ? t * 128 : (t - 32) * 128;

    {
        const __nv_bfloat16 *W0, *W1, *W2;
        const float *b0, *b1, *b2;
        if (particle) {
            W0 = a.wbuf + WO_PE0 * 128; W1 = a.wbuf + WO_PE1 * 128; W2 = a.wbuf + WO_PE2 * 128;
            b0 = a.pe_b0; b1 = a.pe_b1; b2 = a.pe_b2;
        } else {
            W0 = a.wbuf + WO_RE0 * 128; W1 = a.wbuf + WO_RE1 * 128; W2 = a.wbuf + WO_RE2 * 128;
            b0 = a.re_b0; b1 = a.re_b1; b2 = a.re_b2;
        }
        for (int idx = tid; idx < (K0 + 256) * 16; idx += 512) {
            int r = idx >> 4, c8 = (idx & 15) * 8;
            const __nv_bfloat16* src;
            if (r < K0)            src = W0 + (size_t)r * 128 + c8;
            else if (r < K0 + 128) src = W1 + (size_t)(r - K0) * 128 + c8;
            else                   src = W2 + (size_t)(r - K0 - 128) * 128 + c8;
            *(uint4*)&Wsm[r * 136 + c8] = *(const uint4*)src;
        }
        for (int i = tid; i < 128; i += 512) {
            biasm[i] = b0[i]; biasm[128 + i] = b1[i]; biasm[256 + i] = b2[i];
        }
        if (!particle) {
            const __nv_bfloat16* Wr = a.wbuf + WO_RP * 128;   // rp_W rows 0..127
            for (int idx = tid; idx < 128 * 16; idx += 512) {
                int r = idx >> 4, c8 = (idx & 15) * 8;
                *(uint4*)&RPW[r * 136 + c8] = *(const uint4*)(Wr + (size_t)r * 128 + c8);
            }
            for (int i = tid; i < 128; i += 512) biasm[384 + i] = a.rp_b[i];
        }
    }

    if (particle) {
        for (int idx = tid; idx < 128 * 32; idx += 512) {
            int r = idx >> 5, k = idx & 31;
            float v = (k < 19) ? a.pf[(size_t)(rowBase + r) * 19 + k] : 0.f;
            Act[r * 136 + k] = __float2bfloat16(v);
        }
    } else {
        // node cache in dead Cs: 256 slots x 30 floats
        float* cache = Cs;
        for (int idx = tid; idx < 256 * 30; idx += 512) {
            int s = idx / 30, k2 = idx - s * 30;
            int node = (s < 128) ? a.rr[rowBase + s] : a.rs[rowBase + s - 128];
            float v = 0.f;
            if (k2 < 19)      v = a.pf[(size_t)node * 19 + k2];
            else if (k2 < 21) v = a.attrs[node * 2 + (k2 - 19)];
            else if (k2 < 29) {
                int b = node >> 11, n = node & (NN - 1);
                v = (n < NP) ? a.pinst[((size_t)b * NP + n) * 8 + (k2 - 21)] : 0.f;
            }
            cache[s * 30 + k2] = v;
        }
        __syncthreads();
        for (int idx = tid; idx < 128 * 64; idx += 512) {
            int r = idx >> 6, k = idx & 63;
            const float* cr = cache + r * 30;
            const float* cse = cache + (128 + r) * 30;
            float v;
            if (k < 19)       v = cr[k];
            else if (k < 38)  v = cse[k - 19];
            else if (k < 40)  v = cr[19 + (k - 38)];
            else if (k < 42)  v = cse[19 + (k - 40)];
            else if (k == 42) {
                float gd = 0.f;
#pragma unroll
                for (int j = 0; j < 8; j++) gd += fabsf(cr[21 + j] - cse[21 + j]);
                v = gd;
            }
            else if (k < 55)  v = cr[2 + (k - 43)] - cse[2 + (k - 43)];
            else if (k == 55) v = cr[18] - cse[18];
            else              v = 0.f;
            Act[r * 136 + k] = __float2bfloat16(v);
        }
    }
    __syncthreads();

    for (int L = 0; L < 3; L++) {
        int KL = (L == 0) ? K0 : 128;
        const __nv_bfloat16* WL = Wsm + (size_t)((L == 0) ? 0 : K0 + (L - 1) * 128) * 136;
        wmma::fragment<wmma::accumulator, 16, 16, 16, float> acc[4];
#pragma unroll
        for (int nf = 0; nf < 4; nf++) wmma::fill_fragment(acc[nf], 0.f);
        for (int kc = 0; kc < KL / 16; kc++) {
            wmma::fragment<wmma::matrix_a, 16, 16, 16, __nv_bfloat16, wmma::row_major> af;
            wmma::load_matrix_sync(af, Act + (wm * 16) * 136 + kc * 16, 136);
#pragma unroll
            for (int nf = 0; nf < 4; nf++) {
                wmma::fragment<wmma::matrix_b, 16, 16, 16, __nv_bfloat16, wmma::row_major> bf;
                wmma::load_matrix_sync(bf, WL + (kc * 16) * 136 + wn * 64 + nf * 16, 136);
                wmma::mma_sync(acc[nf], af, bf, acc[nf]);
            }
        }
        __syncthreads();                          // cache/Cs dead; Act reads done
#pragma unroll
        for (int nf = 0; nf < 4; nf++)
            wmma::store_matrix_sync(Cs + (wm * 16) * 132 + wn * 64 + nf * 16,
                                    acc[nf], 132, wmma::mem_row_major);
        __syncthreads();
        const float* bL = biasm + L * 128;
#pragma unroll
        for (int it = 0; it < 8; it++) {
            int e = tid + it * 512, row = e >> 5, c4 = (e & 31) * 4;
            float4 v = *(float4*)&Cs[row * 132 + c4];
            float4 b = *(const float4*)&bL[c4];
            v.x = fmaxf(v.x + b.x, 0.f); v.y = fmaxf(v.y + b.y, 0.f);
            v.z = fmaxf(v.z + b.z, 0.f); v.w = fmaxf(v.w + b.w, 0.f);
            uint2 o; o.x = pack_bf2(v.x, v.y); o.y = pack_bf2(v.z, v.w);
            if (L < 2) {
                *(uint2*)&Act[row * 136 + c4] = o;
            } else {
                size_t go = (size_t)(rowBase + row) * 128 + c4;
                if (particle) {
                    *(uint2*)&a.pEnc[go] = o;
                    *(uint2*)&a.pEff[go] = o;
                    uint2 z = make_uint2(0u, 0u);
                    *(uint2*)&a.agg[go] = z;
                    *(uint2*)&a.agg[go + (size_t)NODES * NF] = z;
                    *(uint2*)&a.agg[go + (size_t)2 * NODES * NF] = z;
                } else {
                    *(uint2*)&a.relE[go] = o;
                    *(uint2*)&Act[row * 136 + c4] = o;   // keep relE for layer 4
                }
            }
        }
        __syncthreads();
    }

    // ---- layer 4 (relation tiles only): relBase = relE @ rpW0 + rp_b (f32) -
    if (!particle) {
        wmma::fragment<wmma::accumulator, 16, 16, 16, float> acc[4];
#pragma unroll
        for (int nf = 0; nf < 4; nf++) wmma::fill_fragment(acc[nf], 0.f);
#pragma unroll
        for (int kc = 0; kc < 8; kc++) {
            wmma::fragment<wmma::matrix_a, 16, 16, 16, __nv_bfloat16, wmma::row_major> af;
            wmma::load_matrix_sync(af, Act + (wm * 16) * 136 + kc * 16, 136);
#pragma unroll
            for (int nf = 0; nf < 4; nf++) {
                wmma::fragment<wmma::matrix_b, 16, 16, 16, __nv_bfloat16, wmma::row_major> bf;
                wmma::load_matrix_sync(bf, RPW + (kc * 16) * 136 + wn * 64 + nf * 16, 136);
                wmma::mma_sync(acc[nf], af, bf, acc[nf]);
            }
        }
        __syncthreads();
#pragma unroll
        for (int nf = 0; nf < 4; nf++)
            wmma::store_matrix_sync(Cs + (wm * 16) * 132 + wn * 64 + nf * 16,
                                    acc[nf], 132, wmma::mem_row_major);
        __syncthreads();
        const float* bR = biasm + 384;
#pragma unroll
        for (int it = 0; it < 8; it++) {
            int e = tid + it * 512, row = e >> 5, c4 = (e & 31) * 4;
            float4 v = *(float4*)&Cs[row * 132 + c4];
            float4 b = *(const float4*)&bR[c4];
            v.x += b.x; v.y += b.y; v.z += b.z; v.w += b.w;   // NO relu (partial)
            *(float4*)&a.relBase[(size_t)(rowBase + row) * 128 + c4] = v;
        }
    }
}

// =============  relation propagator v3: K=256, acc init from relBase ========
// A = [pEff[rr] | pEff[rs]] (128 x 264); W = rp_W rows 128..384 resident.
// acc loaded from relBase (f32, bias folded); epi = relu -> atomic scatter.
#define R3A_LD 264
#define R3_W_OFF   (128*R3A_LD*2)                  // 67584
#define R3_IDX_OFF (R3_W_OFF + 256*136*2)          // 137216
#define R3_SMEM    (R3_IDX_OFF + 256*4)            // 138240

__global__ void __launch_bounds__(512) relprop_k(
    const __nv_bfloat16* __restrict__ pEff,
    const __nv_bfloat16* __restrict__ W,
    const float* __restrict__ relBase,
    __nv_bfloat16* __restrict__ aggH,
    const int* __restrict__ rr, const int* __restrict__ rs)
{
    extern __shared__ char sm[];
    __nv_bfloat16* Asm = (__nv_bfloat16*)sm;
    __nv_bfloat16* Wsm = (__nv_bfloat16*)(sm + R3_W_OFF);
    int*   idxs        = (int*)(sm + R3_IDX_OFF);
    float* Cs          = (float*)sm;                 // overlay A post-mainloop

    int tid = threadIdx.x, wid = tid >> 5;
    int wm = wid & 7, wn = wid >> 3;                 // 8 row x 2 col warp groups
    int rowBase = blockIdx.x * 128;

    if (tid < 128)      idxs[tid] = rr[rowBase + tid];
    else if (tid < 256) idxs[tid] = rs[rowBase + tid - 128];
    __syncthreads();                                 // idxs visible for gather

    uint32_t asB = (uint32_t)__cvta_generic_to_shared(Asm);
    uint32_t wsB = (uint32_t)__cvta_generic_to_shared(Wsm);

    // stage A: 128 rows x 32 chunks ([pEff[rr] | pEff[rs]])
    for (int c = tid; c < 128 * 32; c += 512) {
        int row = c >> 5, ch = c & 31;
        int seg = ch >> 4, off = (ch & 15) * 8;
        const __nv_bfloat16* src = (seg == 0)
            ? pEff + (size_t)idxs[row] * 128 + off
            : pEff + (size_t)idxs[128 + row] * 128 + off;
        cpa16(asB + (uint32_t)(row * R3A_LD + seg * 128 + off) * 2, src);
    }
    // stage W: 256 rows x 16 chunks (stride 136)
    for (int c = tid; c < 256 * 16; c += 512) {
        int row = c >> 4, c8 = (c & 15) * 8;
        cpa16(wsB + (uint32_t)(row * 136 + c8) * 2, W + (size_t)row * 128 + c8);
    }
    cp_commit();

    // accumulator init from global relBase (bias already folded)
    wmma::fragment<wmma::accumulator, 16, 16, 16, float> acc[4];
#pragma unroll
    for (int nf = 0; nf < 4; nf++)
        wmma::load_matrix_sync(acc[nf],
            relBase + (size_t)(rowBase + wm * 16) * 128 + wn * 64 + nf * 16,
            128, wmma::mem_row_major);

    cp_wait0();
    __syncthreads();

    for (int kt = 0; kt < 16; kt++) {
        wmma::fragment<wmma::matrix_a, 16, 16, 16, __nv_bfloat16, wmma::row_major> af;
        wmma::load_matrix_sync(af, Asm + (wm * 16) * R3A_LD + kt * 16, R3A_LD);
#pragma unroll
        for (int nf = 0; nf < 4; nf++) {
            wmma::fragment<wmma::matrix_b, 16, 16, 16, __nv_bfloat16, wmma::row_major> bf;
            wmma::load_matrix_sync(bf, Wsm + (kt * 16) * 136 + wn * 64 + nf * 16, 136);
            wmma::mma_sync(acc[nf], af, bf, acc[nf]);
        }
    }
    __syncthreads();                                 // A reads done before overlay
#pragma unroll
    for (int nf = 0; nf < 4; nf++)
        wmma::store_matrix_sync(Cs + (wm * 16) * 132 + wn * 64 + nf * 16,
                                acc[nf], 132, wmma::mem_row_major);
    __syncthreads();
#pragma unroll
    for (int it = 0; it < 8; it++) {
        int e = tid + it * 512, row = e >> 5, c4 = (e & 31) * 4;
        float4 v = *(float4*)&Cs[row * 132 + c4];
        __nv_bfloat162* dst =
            (__nv_bfloat162*)(aggH + (size_t)idxs[row] * 128 + c4);
        atomicAdd(dst,     __floats2bfloat162_rn(fmaxf(v.x, 0.f), fmaxf(v.y, 0.f)));
        atomicAdd(dst + 1, __floats2bfloat162_rn(fmaxf(v.z, 0.f), fmaxf(v.w, 0.f)));
    }
}

// =============  particle propagator v4 (R13-proven): N-split, zero-free =====
#define PPA_LD 264
#define P4_W_OFF    (32*PPA_LD*2)                  // 16896
#define P4_RES_OFF  (P4_W_OFF + 256*72*2)          // 53760
#define P4_BIAS_OFF (P4_RES_OFF + 32*80*2)         // 58880
#define P4_SMEM     (P4_BIAS_OFF + 256)            // 59136

__global__ void __launch_bounds__(256) partprop_k(
    const __nv_bfloat16* __restrict__ pEnc,
    const __nv_bfloat16* __restrict__ aggIn,
    const __nv_bfloat16* __restrict__ W,
    const float* __restrict__ bias,
    __nv_bfloat16* __restrict__ pEff)
{
    extern __shared__ char sm[];
    __nv_bfloat16* Asm  = (__nv_bfloat16*)sm;
    __nv_bfloat16* Wsm  = (__nv_bfloat16*)(sm + P4_W_OFF);
    __nv_bfloat16* Res  = (__nv_bfloat16*)(sm + P4_RES_OFF);
    float* biasm        = (float*)(sm + P4_BIAS_OFF);
    float* Cs           = (float*)sm;                // overlays Asm post-mainloop

    int tid = threadIdx.x, wid = tid >> 5;
    int wm = wid & 1, wn = wid >> 1;                 // 2 row x 4 col warp groups
    int t = blockIdx.x >> 1, half = blockIdx.x & 1;
    int rowBase = t * 32;
    int colBase = half * 64;

    if (tid < 64) biasm[tid] = bias[colBase + tid];

    uint32_t asB = (uint32_t)__cvta_generic_to_shared(Asm);
    uint32_t wsB = (uint32_t)__cvta_generic_to_shared(Wsm);
    uint32_t reB = (uint32_t)__cvta_generic_to_shared(Res);

    for (int c = tid; c < 32 * 32; c += 256) {
        int row = c >> 5, off = (c & 31) * 8;
        const __nv_bfloat16* src;
        if (off < 128) src = pEnc  + (size_t)(rowBase + row) * 128 + off;
        else           src = aggIn + (size_t)(rowBase + row) * 128 + (off - 128);
        cpa16(asB + (uint32_t)(row * PPA_LD + off) * 2, src);
    }
    for (int c = tid; c < 256 * 8; c += 256) {
        int row = c >> 3, c8 = (c & 7) * 8;
        cpa16(wsB + (uint32_t)(row * 72 + c8) * 2,
              W + (size_t)row * 128 + colBase + c8);
    }
    for (int c = tid; c < 32 * 8; c += 256) {
        int row = c >> 3, c8 = (c & 7) * 8;
        cpa16(reB + (uint32_t)(row * 80 + c8) * 2,
              pEff + (size_t)(rowBase + row) * 128 + colBase + c8);
    }
    cp_commit(); cp_wait0();
    __syncthreads();

    wmma::fragment<wmma::accumulator, 16, 16, 16, float> acc;
    wmma::fill_fragment(acc, 0.f);
    for (int kt = 0; kt < 16; kt++) {
        wmma::fragment<wmma::matrix_a, 16, 16, 16, __nv_bfloat16, wmma::row_major> af;
        wmma::load_matrix_sync(af, Asm + (wm * 16) * PPA_LD + kt * 16, PPA_LD);
        wmma::fragment<wmma::matrix_b, 16, 16, 16, __nv_bfloat16, wmma::row_major> bf;
        wmma::load_matrix_sync(bf, Wsm + (kt * 16) * 72 + wn * 16, 72);
        wmma::mma_sync(acc, af, bf, acc);
    }
    __syncthreads();
    wmma::store_matrix_sync(Cs + (wm * 16) * 68 + wn * 16, acc, 68,
                            wmma::mem_row_major);
    __syncthreads();
#pragma unroll
    for (int it = 0; it < 2; it++) {
        int e = tid + it * 256, row = e >> 4, c4 = (e & 15) * 4;
        float4 v = *(float4*)&Cs[row * 68 + c4];
        float4 b = *(const float4*)&biasm[c4];
        uint2 rv = *(const uint2*)&Res[row * 80 + c4];
        float2 r0 = unpack_bf2(rv.x), r1 = unpack_bf2(rv.y);
        v.x = fmaxf(v.x + b.x + r0.x, 0.f);
        v.y = fmaxf(v.y + b.y + r0.y, 0.f);
        v.z = fmaxf(v.z + b.z + r1.x, 0.f);
        v.w = fmaxf(v.w + b.w + r1.y, 0.f);
        uint2 o; o.x = pack_bf2(v.x, v.y); o.y = pack_bf2(v.z, v.w);
        *(uint2*)&pEff[(size_t)(rowBase + row) * 128 + colBase + c4] = o;
    }
}

// =============  final particle propagator with fused head (R12-proven) ======
#define PH_W_OFF    (32*PPA_LD*2)                  // 16896
#define PH_NW_OFF   (PH_W_OFF + 256*136*2)         // 86528
#define PH_BIAS_OFF (PH_NW_OFF + 256*136*2)        // 156160
#define PH_NB0_OFF  (PH_BIAS_OFF + 512)            // 156672
#define PH_NB1_OFF  (PH_NB0_OFF + 512)             // 157184
#define PH_W2_OFF   (PH_NB1_OFF + 512)             // 157696
#define PH_B2_OFF   (PH_W2_OFF + 1536)             // 159232
#define PH_ACT_OFF  (PH_B2_OFF + 16)               // 159248
#define PH_SMEM     (PH_ACT_OFF + 32*136*2)        // 167952

__global__ void __launch_bounds__(512) partproph_k(
    const __nv_bfloat16* __restrict__ pEnc,
    const __nv_bfloat16* __restrict__ aggIn,
    const __nv_bfloat16* __restrict__ W,
    const float* __restrict__ bias,
    const __nv_bfloat16* __restrict__ pEff,
    const __nv_bfloat16* __restrict__ npW,
    const float* __restrict__ nb0, const float* __restrict__ nb1,
    const float* __restrict__ W2, const float* __restrict__ b2,
    const float* __restrict__ state, float* __restrict__ out)
{
    extern __shared__ char sm[];
    __nv_bfloat16* Asm  = (__nv_bfloat16*)sm;
    __nv_bfloat16* Wsm  = (__nv_bfloat16*)(sm + PH_W_OFF);
    __nv_bfloat16* NWsm = (__nv_bfloat16*)(sm + PH_NW_OFF);
    float* biasm        = (float*)(sm + PH_BIAS_OFF);
    float* nb0s         = (float*)(sm + PH_NB0_OFF);
    float* nb1s         = (float*)(sm + PH_NB1_OFF);
    float* W2s          = (float*)(sm + PH_W2_OFF);
    float* b2s          = (float*)(sm + PH_B2_OFF);
    __nv_bfloat16* Act  = (__nv_bfloat16*)(sm + PH_ACT_OFF);
    float* Cs           = (float*)sm;

    int tid = threadIdx.x, wid = tid >> 5, lane = tid & 31;
    int wm = wid & 1, wn = wid >> 1;                 // 2 row x 8 col warp groups
    int rowBase = blockIdx.x * 32;

    for (int i = tid; i < 128; i += 512) {
        biasm[i] = bias[i]; nb0s[i] = nb0[i]; nb1s[i] = nb1[i];
    }
    for (int i = tid; i < 384; i += 512) W2s[i] = W2[i];
    if (tid < 3) b2s[tid] = b2[tid];

    uint32_t asB = (uint32_t)__cvta_generic_to_shared(Asm);
    uint32_t wsB = (uint32_t)__cvta_generic_to_shared(Wsm);
    uint32_t nwB = (uint32_t)__cvta_generic_to_shared(NWsm);

    for (int c = tid; c < 32 * 32; c += 512) {
        int row = c >> 5, off = (c & 31) * 8;
        const __nv_bfloat16* src;
        if (off < 128) src = pEnc  + (size_t)(rowBase + row) * 128 + off;
        else           src = aggIn + (size_t)(rowBase + row) * 128 + (off - 128);
        cpa16(asB + (uint32_t)(row * PPA_LD + off) * 2, src);
    }
    for (int c = tid; c < 256 * 16; c += 512) {
        int row = c >> 4, c8 = (c & 15) * 8;
        cpa16(wsB + (uint32_t)(row * 136 + c8) * 2, W + (size_t)row * 128 + c8);
        cpa16(nwB + (uint32_t)(row * 136 + c8) * 2, npW + (size_t)row * 128 + c8);
    }
    cp_commit(); cp_wait0();
    __syncthreads();

    wmma::fragment<wmma::accumulator, 16, 16, 16, float> acc;
    wmma::fill_fragment(acc, 0.f);
    for (int kt = 0; kt < 16; kt++) {
        wmma::fragment<wmma::matrix_a, 16, 16, 16, __nv_bfloat16, wmma::row_major> af;
        wmma::load_matrix_sync(af, Asm + (wm * 16) * PPA_LD + kt * 16, PPA_LD);
        wmma::fragment<wmma::matrix_b, 16, 16, 16, __nv_bfloat16, wmma::row_major> bf;
        wmma::load_matrix_sync(bf, Wsm + (kt * 16) * 136 + wn * 16, 136);
        wmma::mma_sync(acc, af, bf, acc);
    }
    __syncthreads();
    wmma::store_matrix_sync(Cs + (wm * 16) * 132 + wn * 16, acc, 132,
                            wmma::mem_row_major);
    __syncthreads();
#pragma unroll
    for (int it = 0; it < 2; it++) {
        int e = tid + it * 512, row = e >> 5, c4 = (e & 31) * 4;
        size_t go = (size_t)(rowBase + row) * 128 + c4;
        float4 v = *(float4*)&Cs[row * 132 + c4];
        float4 b = *(const float4*)&biasm[c4];
        uint2 rv = *(const uint2*)&pEff[go];
        float2 r0 = unpack_bf2(rv.x), r1 = unpack_bf2(rv.y);
        v.x = fmaxf(v.x + b.x + r0.x, 0.f);
        v.y = fmaxf(v.y + b.y + r0.y, 0.f);
        v.z = fmaxf(v.z + b.z + r1.x, 0.f);
        v.w = fmaxf(v.w + b.w + r1.y, 0.f);
        uint2 o; o.x = pack_bf2(v.x, v.y); o.y = pack_bf2(v.z, v.w);
        *(uint2*)&Act[row * 136 + c4] = o;           // smem only
    }
    __syncthreads();

    // np0
    {
        wmma::fragment<wmma::accumulator, 16, 16, 16, float> a2;
        wmma::fill_fragment(a2, 0.f);
#pragma unroll
        for (int kt = 0; kt < 8; kt++) {
            wmma::fragment<wmma::matrix_a, 16, 16, 16, __nv_bfloat16, wmma::row_major> af;
            wmma::load_matrix_sync(af, Act + (wm * 16) * 136 + kt * 16, 136);
            wmma::fragment<wmma::matrix_b, 16, 16, 16, __nv_bfloat16, wmma::row_major> bf;
            wmma::load_matrix_sync(bf, NWsm + (kt * 16) * 136 + wn * 16, 136);
            wmma::mma_sync(a2, af, bf, a2);
        }
        __syncthreads();
        wmma::store_matrix_sync(Cs + (wm * 16) * 132 + wn * 16, a2, 132,
                                wmma::mem_row_major);
        __syncthreads();
#pragma unroll
        for (int it = 0; it < 2; it++) {
            int e = tid + it * 512, row = e >> 5, c4 = (e & 31) * 4;
            float4 v = *(float4*)&Cs[row * 132 + c4];
            float4 b = *(const float4*)&nb0s[c4];
            uint2 o;
            o.x = pack_bf2(fmaxf(v.x + b.x, 0.f), fmaxf(v.y + b.y, 0.f));
            o.y = pack_bf2(fmaxf(v.z + b.z, 0.f), fmaxf(v.w + b.w, 0.f));
            *(uint2*)&Act[row * 136 + c4] = o;
        }
        __syncthreads();
    }
    // np1
    {
        wmma::fragment<wmma::accumulator, 16, 16, 16, float> a2;
        wmma::fill_fragment(a2, 0.f);
#pragma unroll
        for (int kt = 0; kt < 8; kt++) {
            wmma::fragment<wmma::matrix_a, 16, 16, 16, __nv_bfloat16, wmma::row_major> af;
            wmma::load_matrix_sync(af, Act + (wm * 16) * 136 + kt * 16, 136);
            wmma::fragment<wmma::matrix_b, 16, 16, 16, __nv_bfloat16, wmma::row_major> bf;
            wmma::load_matrix_sync(bf, NWsm + ((128 + kt * 16)) * 136 + wn * 16, 136);
            wmma::mma_sync(a2, af, bf, a2);
        }
        __syncthreads();
        wmma::store_matrix_sync(Cs + (wm * 16) * 132 + wn * 16, a2, 132,
                                wmma::mem_row_major);
        __syncthreads();
    }
    // final: h1 = relu(Cs + nb1); motion = h1 @ W2 + b2; clamp; add
#pragma unroll
    for (int i = 0; i < 2; i++) {
        int row = wid * 2 + i;
        int grow = rowBase + row;
        int b = grow >> 11, n = grow & (NN - 1);
        float hv[4];
#pragma unroll
        for (int j = 0; j < 4; j++)
            hv[j] = fmaxf(Cs[row * 132 + lane + 32 * j] + nb1s[lane + 32 * j], 0.f);
#pragma unroll
        for (int k = 0; k < 3; k++) {
            float sacc = 0.f;
#pragma unroll
            for (int j = 0; j < 4; j++)
                sacc += hv[j] * W2s[(lane + 32 * j) * 3 + k];
#pragma unroll
            for (int off = 16; off; off >>= 1)
                sacc += __shfl_xor_sync(0xffffffffu, sacc, off);
            if (lane == 0 && n < NP) {
                float m = fminf(fmaxf(sacc + b2s[k], -100.f), 100.f);
                out[((size_t)b * NP + n) * 3 + k] =
                    state[((size_t)(b * 4 + 3) * NN + n) * 3 + k] + m;
            }
        }
    }
}

// ---------------------------------------------------------------------------
extern "C" void kernel_launch(void* const* d_in, const int* in_sizes, int n_in,
                              void* d_out, int out_size) {
    const float* state  = (const float*)d_in[0];
    const float* attrs  = (const float*)d_in[1];
    const float* Rr     = (const float*)d_in[2];
    const float* Rs     = (const float*)d_in[3];
    const float* pinst  = (const float*)d_in[4];
    const float* action = (const float*)d_in[5];
    const float* pden   = (const float*)d_in[6];
    const float* phys   = (const float*)d_in[7];
    const float* pe_W0 = (const float*)d_in[8],  *pe_b0 = (const float*)d_in[9];
    const float* pe_W1 = (const float*)d_in[10], *pe_b1 = (const float*)d_in[11];
    const float* pe_W2 = (const float*)d_in[12], *pe_b2 = (const float*)d_in[13];
    const float* re_W0 = (const float*)d_in[14], *re_b0 = (const float*)d_in[15];
    const float* re_W1 = (const float*)d_in[16], *re_b1 = (const float*)d_in[17];
    const float* re_W2 = (const float*)d_in[18], *re_b2 = (const float*)d_in[19];
    const float* pp_W  = (const float*)d_in[20], *pp_b  = (const float*)d_in[21];
    const float* rp_W  = (const float*)d_in[22], *rp_b  = (const float*)d_in[23];
    const float* np_W0 = (const float*)d_in[24], *np_b0 = (const float*)d_in[25];
    const float* np_W1 = (const float*)d_in[26], *np_b1 = (const float*)d_in[27];
    const float* np_W2 = (const float*)d_in[28], *np_b2 = (const float*)d_in[29];
    float* out = (float*)d_out;

    float *pin_f, *relBase;
    __nv_bfloat16 *pEnc, *pEff, *relE, *aggH, *wbuf;
    int *rr, *rs;
    cudaGetSymbolAddress((void**)&pin_f,   g_pin_f);
    cudaGetSymbolAddress((void**)&pEnc,    g_pEnc);
    cudaGetSymbolAddress((void**)&pEff,    g_pEff);
    cudaGetSymbolAddress((void**)&relE,    g_relE);
    cudaGetSymbolAddress((void**)&relBase, g_relBase);
    cudaGetSymbolAddress((void**)&aggH,    g_aggH);
    cudaGetSymbolAddress((void**)&rr,      g_rr);
    cudaGetSymbolAddress((void**)&rs,      g_rs);
    cudaGetSymbolAddress((void**)&wbuf,    g_wbuf);

    cudaFuncSetAttribute(encmlp_k,   cudaFuncAttributeMaxDynamicSharedMemorySize, E2_SMEM);
    cudaFuncSetAttribute(relprop_k,  cudaFuncAttributeMaxDynamicSharedMemorySize, R3_SMEM);
    cudaFuncSetAttribute(partprop_k, cudaFuncAttributeMaxDynamicSharedMemorySize, P4_SMEM);
    cudaFuncSetAttribute(partproph_k,cudaFuncAttributeMaxDynamicSharedMemorySize, PH_SMEM);

    WConvArgs wa;
    const float* srcs[10] = {pe_W0, pe_W1, pe_W2, re_W0, re_W1, re_W2,
                             pp_W, rp_W, np_W0, np_W1};
    const int starts[10]  = {WO_PE0, WO_PE1, WO_PE2, WO_RE0, WO_RE1, WO_RE2,
                             WO_PP, WO_RP, WO_NP0, WO_NP1};
    const int srows[10]   = {19, 128, 128, 56, 128, 128, 256, 384, 128, 128};
    for (int i = 0; i < 10; i++) {
        wa.src[i] = srcs[i]; wa.rowStart[i] = starts[i]; wa.srcRows[i] = srows[i];
    }

    // 1) convert weights + build particle features + extract indices
    prep_k<<<4096, 256>>>(Rr, Rs, rr, rs, state, attrs, action, pden, phys,
                          pin_f, wa, wbuf);

    // 2) fused encoders (+ relBase precompute on relation tiles)
    EncArgs ea;
    ea.pf = pin_f; ea.attrs = attrs; ea.pinst = pinst;
    ea.rr = rr; ea.rs = rs; ea.wbuf = wbuf;
    ea.pe_b0 = pe_b0; ea.pe_b1 = pe_b1; ea.pe_b2 = pe_b2;
    ea.re_b0 = re_b0; ea.re_b1 = re_b1; ea.re_b2 = re_b2; ea.rp_b = rp_b;
    ea.pEnc = pEnc; ea.pEff = pEff; ea.relE = relE; ea.agg = aggH;
    ea.relBase = relBase;
    encmlp_k<<<160, 512, E2_SMEM>>>(ea);

    // 3) propagation: rotating agg buffers; relprop K=256 w/ relBase acc-init
    const __nv_bfloat16* npW = wbuf + WO_NP0 * 128;
    const __nv_bfloat16* rpW2 = wbuf + (WO_RP + 128) * 128;   // rp_W rows 128..384
    for (int step = 0; step < 2; step++) {
        __nv_bfloat16* buf = aggH + (size_t)step * NODES * NF;
        relprop_k<<<BNR / 128, 512, R3_SMEM>>>(pEff, rpW2, relBase, buf, rr, rs);
        partprop_k<<<(NODES / 32) * 2, 256, P4_SMEM>>>(
            pEnc, buf, wbuf + WO_PP * 128, pp_b, pEff);
    }
    __nv_bfloat16* buf2 = aggH + (size_t)2 * NODES * NF;
    relprop_k<<<BNR / 128, 512, R3_SMEM>>>(pEff, rpW2, relBase, buf2, rr, rs);
    partproph_k<<<NODES / 32, 512, PH_SMEM>>>(
        pEnc, buf2, wbuf + WO_PP * 128, pp_b, pEff,
        npW, np_b0, np_b1, np_W2, np_b2, state, out);
}

// round 15
// speedup vs baseline: 1.3511x; 1.0156x over previous
#include <cuda_runtime.h>
#include <cuda_bf16.h>
#include <mma.h>
#include <cstdint>

using namespace nvcuda;

// Problem constants
#define BB 2
#define NN 2048
#define NP 2000
#define NREL 8192
#define BNR 16384
#define NODES 4096
#define NF 128

// ---------------- scratch ---------------------------------------------------
__device__ float          g_pin_f[NODES*19];
__device__ __nv_bfloat16  g_pEnc[NODES*NF];
__device__ __nv_bfloat16  g_pEff[NODES*NF];
__device__ float          g_F[NODES*NF];           // pin@Wf + re_b0 (f32)
__device__ float          g_G[NODES*NF];           // pin@Wg (f32)
__device__ float          g_relBase[BNR*NF];       // relE @ rpW0 + rp_b (f32)
__device__ __nv_bfloat16  g_aggH[3*NODES*NF];      // 3 rotating buffers
__device__ int            g_rr[BNR];
__device__ int            g_rs[BNR];
__device__ __nv_bfloat16  g_wbuf[1504*128];

// weight row offsets inside g_wbuf
#define WO_PE0 0
#define WO_PE1 32
#define WO_PE2 160
#define WO_RE0 288
#define WO_RE1 352
#define WO_RE2 480
#define WO_PP  608
#define WO_RP  864
#define WO_NP0 1248
#define WO_NP1 1376
#define W_TOTAL_ROWS 1504

// ---------------- helpers ---------------------------------------------------
__device__ __forceinline__ uint32_t pack_bf2(float a, float b) {
    __nv_bfloat162 h = __floats2bfloat162_rn(a, b);
    return *reinterpret_cast<uint32_t*>(&h);
}
__device__ __forceinline__ float2 unpack_bf2(uint32_t u) {
    __nv_bfloat162 h = *reinterpret_cast<__nv_bfloat162*>(&u);
    return make_float2(__bfloat162float(h.x), __bfloat162float(h.y));
}
__device__ __forceinline__ void cpa16(uint32_t d, const void* s) {
    asm volatile("cp.async.cg.shared.global [%0], [%1], 16;" :: "r"(d), "l"(s));
}
__device__ __forceinline__ void cp_commit() {
    asm volatile("cp.async.commit_group;" ::: "memory");
}
__device__ __forceinline__ void cp_wait0() {
    asm volatile("cp.async.wait_group 0;" ::: "memory");
}

// ---------------- weight conversion args ------------------------------------
struct WConvArgs {
    const float* src[10];
    int rowStart[10];
    int srcRows[10];
};

// =====================  prep kernel: convert + build_pin + F/G + extract ====
// blocks 0..15: build_pin + F/G (scalar f32); 16..203: convert; ALL: extract.
__global__ void prep_k(const float* __restrict__ Rr, const float* __restrict__ Rs,
                       int* __restrict__ rr, int* __restrict__ rs,
                       const float* __restrict__ state, const float* __restrict__ attrs,
                       const float* __restrict__ action, const float* __restrict__ pden,
                       const float* __restrict__ phys, float* __restrict__ pf,
                       WConvArgs wa, __nv_bfloat16* __restrict__ wbuf,
                       const float* __restrict__ reW0f, const float* __restrict__ reb0,
                       float* __restrict__ Fg, float* __restrict__ Gg) {
    __shared__ float pinS[256 * 20];
    int bid = blockIdx.x, tid = threadIdx.x;

    if (bid < 16) {
        int i = bid * 256 + tid;
        int b = i / NN, n = i - b * NN;
        float o[19];
        o[0] = attrs[i * 2 + 0];
        o[1] = attrs[i * 2 + 1];
        float s[4][3];
#pragma unroll
        for (int t = 0; t < 4; t++)
#pragma unroll
            for (int k = 0; k < 3; k++)
                s[t][k] = state[((size_t)(b * 4 + t) * NN + n) * 3 + k];
#pragma unroll
        for (int t = 0; t < 3; t++)
#pragma unroll
            for (int k = 0; k < 3; k++)
                o[2 + t * 3 + k] = s[t + 1][k] - s[t][k];
#pragma unroll
        for (int k = 0; k < 3; k++) o[11 + k] = s[3][k];
        bool isP = (n < NP);
        o[14] = isP ? phys[b] : 0.f;
#pragma unroll
        for (int k = 0; k < 3; k++) o[15 + k] = action[(size_t)i * 3 + k];
        o[18] = isP ? pden[b] : 0.f;
#pragma unroll
        for (int k = 0; k < 19; k++) pf[(size_t)i * 19 + k] = o[k];
#pragma unroll
        for (int k = 0; k < 19; k++) pinS[tid * 20 + k] = o[k];
        __syncthreads();

        // F (tid<128) / G (tid>=128), one column per thread, fp32.
        int col = tid & 127;
        bool doG = tid >= 128;
        float wcol[19], bias0 = 0.f;
        if (!doG) {
            wcol[0] = reW0f[0 * 128 + col] + reW0f[38 * 128 + col];
            wcol[1] = reW0f[1 * 128 + col] + reW0f[39 * 128 + col];
#pragma unroll
            for (int k = 2; k < 14; k++)
                wcol[k] = reW0f[k * 128 + col] + reW0f[(41 + k) * 128 + col];
#pragma unroll
            for (int k = 14; k < 18; k++) wcol[k] = reW0f[k * 128 + col];
            wcol[18] = reW0f[18 * 128 + col] + reW0f[55 * 128 + col];
            bias0 = reb0[col];
        } else {
            wcol[0] = reW0f[19 * 128 + col] + reW0f[40 * 128 + col];
            wcol[1] = reW0f[20 * 128 + col] + reW0f[41 * 128 + col];
#pragma unroll
            for (int k = 2; k < 14; k++)
                wcol[k] = reW0f[(19 + k) * 128 + col] - reW0f[(41 + k) * 128 + col];
#pragma unroll
            for (int k = 14; k < 18; k++) wcol[k] = reW0f[(19 + k) * 128 + col];
            wcol[18] = reW0f[37 * 128 + col] - reW0f[55 * 128 + col];
        }
        float* dst = doG ? Gg : Fg;
        int nodeBase = bid * 256;
        for (int nl = 0; nl < 256; nl++) {
            const float* p = &pinS[nl * 20];
            float acc = bias0;
#pragma unroll
            for (int k = 0; k < 19; k++) acc += p[k] * wcol[k];
            dst[(size_t)(nodeBase + nl) * 128 + col] = acc;
        }
    } else if (bid < 204) {
        int base = (bid - 16) * 1024;
        for (int k = tid; k < 1024; k += 256) {
            int e = base + k;
            int row = e >> 7, col = e & 127;
            int seg = 0;
#pragma unroll
            for (int i = 1; i < 10; i++) if (row >= wa.rowStart[i]) seg = i;
            int r = row - wa.rowStart[seg];
            float v = (r < wa.srcRows[seg]) ? wa.src[seg][r * 128 + col] : 0.f;
            wbuf[row * 128 + col] = __float2bfloat16(v);
        }
    }

    // extract (all 4096 blocks x 8 warps = 32768 row-warps)
    int gw = bid * 8 + (tid >> 5);
    int lane = tid & 31;
    const float* src = (gw < BNR) ? Rr : Rs;
    int row = (gw < BNR) ? gw : gw - BNR;
    const float4* p = reinterpret_cast<const float4*>(src + (size_t)row * NN);
    int found = -1;
    for (int i = 0; i < NN / 128; i++) {
        float4 v = __ldcs(&p[i * 32 + lane]);
        int base = i * 128 + lane * 4;
        if (v.x != 0.f) found = base;
        if (v.y != 0.f) found = base + 1;
        if (v.z != 0.f) found = base + 2;
        if (v.w != 0.f) found = base + 3;
        if (__ballot_sync(0xffffffffu, found >= 0)) break;   // one-hot: done
    }
#pragma unroll
    for (int off = 16; off; off >>= 1)
        found = max(found, __shfl_xor_sync(0xffffffffu, found, off));
    if (lane == 0) {
        int b = row / NREL;
        ((gw < BNR) ? rr : rs)[row] = b * NN + found;
    }
}

// ============  fused encoder: particle MLP | relation (F/G-based)  ==========
// grid 160: tiles 0..31 particle (128 rows, K0=32), 32..159 relation.
// Relation: rel0 = relu(F[rr]+G[rs]+gd*w42) -> L1 -> L2 -> L4(relBase).
#define E3_W_OFF    0                              // 384*136*2 = 104448
#define E3_BIAS_OFF 104448                         // 640*4 -> 107008
#define E3_ACT_OFF  107008                         // 128*136*2 -> 141824
#define E3_AUX_OFF  141824                         // idx 1024 + gd 512 -> 143360
#define E3_CS_OFF   143360                         // 128*132*4 -> 210944
#define E3_SMEM     210944

struct EncArgs {
    const float *pf, *pinst, *reW0f, *F, *G;
    const int *rr, *rs;
    const __nv_bfloat16* wbuf;
    const float *pe_b0, *pe_b1, *pe_b2, *re_b1, *re_b2, *rp_b;
    __nv_bfloat16 *pEnc, *pEff, *agg;
    float* relBase;
};

__global__ void __launch_bounds__(512) encmlp_k(EncArgs a) {
    extern __shared__ char sm[];
    __nv_bfloat16* Wsm  = (__nv_bfloat16*)(sm + E3_W_OFF);
    float* biasm        = (float*)(sm + E3_BIAS_OFF);
    __nv_bfloat16* Act  = (__nv_bfloat16*)(sm + E3_ACT_OFF);
    int*   idxs         = (int*)(sm + E3_AUX_OFF);
    float* gdm          = (float*)(sm + E3_AUX_OFF + 1024);
    float* Cs           = (float*)(sm + E3_CS_OFF);
    int tid = threadIdx.x, wid = tid >> 5;
    int wm = wid & 7, wn = wid >> 3;               // 8 row x 2 col warp groups
    int t = blockIdx.x;
    bool particle = (t < 32);
    int rowBase = particle ? t * 128 : (t - 32) * 128;

    if (particle) {
        // W stack: pe_W0(32) | pe_W1(128) | pe_W2(128) = 288 rows
        for (int idx = tid; idx < 288 * 16; idx += 512) {
            int r = idx >> 4, c8 = (idx & 15) * 8;
            const __nv_bfloat16* src;
            if (r < 32)       src = a.wbuf + (size_t)(WO_PE0 + r) * 128 + c8;
            else if (r < 160) src = a.wbuf + (size_t)(WO_PE1 + r - 32) * 128 + c8;
            else              src = a.wbuf + (size_t)(WO_PE2 + r - 160) * 128 + c8;
            *(uint4*)&Wsm[r * 136 + c8] = *(const uint4*)src;
        }
        for (int i = tid; i < 128; i += 512) {
            biasm[i] = a.pe_b0[i]; biasm[128 + i] = a.pe_b1[i]; biasm[256 + i] = a.pe_b2[i];
        }
        for (int idx = tid; idx < 128 * 32; idx += 512) {
            int r = idx >> 5, k = idx & 31;
            float v = (k < 19) ? a.pf[(size_t)(rowBase + r) * 19 + k] : 0.f;
            Act[r * 136 + k] = __float2bfloat16(v);
        }
        __syncthreads();

        for (int L = 0; L < 3; L++) {
            int KL = (L == 0) ? 32 : 128;
            const __nv_bfloat16* WL = Wsm + (size_t)((L == 0) ? 0 : 32 + (L - 1) * 128) * 136;
            wmma::fragment<wmma::accumulator, 16, 16, 16, float> acc[4];
#pragma unroll
            for (int nf = 0; nf < 4; nf++) wmma::fill_fragment(acc[nf], 0.f);
            for (int kc = 0; kc < KL / 16; kc++) {
                wmma::fragment<wmma::matrix_a, 16, 16, 16, __nv_bfloat16, wmma::row_major> af;
                wmma::load_matrix_sync(af, Act + (wm * 16) * 136 + kc * 16, 136);
#pragma unroll
                for (int nf = 0; nf < 4; nf++) {
                    wmma::fragment<wmma::matrix_b, 16, 16, 16, __nv_bfloat16, wmma::row_major> bf;
                    wmma::load_matrix_sync(bf, WL + (kc * 16) * 136 + wn * 64 + nf * 16, 136);
                    wmma::mma_sync(acc[nf], af, bf, acc[nf]);
                }
            }
            __syncthreads();
#pragma unroll
            for (int nf = 0; nf < 4; nf++)
                wmma::store_matrix_sync(Cs + (wm * 16) * 132 + wn * 64 + nf * 16,
                                        acc[nf], 132, wmma::mem_row_major);
            __syncthreads();
            const float* bL = biasm + L * 128;
#pragma unroll
            for (int it = 0; it < 8; it++) {
                int e = tid + it * 512, row = e >> 5, c4 = (e & 31) * 4;
                float4 v = *(float4*)&Cs[row * 132 + c4];
                float4 b = *(const float4*)&bL[c4];
                v.x = fmaxf(v.x + b.x, 0.f); v.y = fmaxf(v.y + b.y, 0.f);
                v.z = fmaxf(v.z + b.z, 0.f); v.w = fmaxf(v.w + b.w, 0.f);
                uint2 o; o.x = pack_bf2(v.x, v.y); o.y = pack_bf2(v.z, v.w);
                if (L < 2) {
                    *(uint2*)&Act[row * 136 + c4] = o;
                } else {
                    size_t go = (size_t)(rowBase + row) * 128 + c4;
                    *(uint2*)&a.pEnc[go] = o;
                    *(uint2*)&a.pEff[go] = o;
                    uint2 z = make_uint2(0u, 0u);
                    *(uint2*)&a.agg[go] = z;
                    *(uint2*)&a.agg[go + (size_t)NODES * NF] = z;
                    *(uint2*)&a.agg[go + (size_t)2 * NODES * NF] = z;
                }
            }
            __syncthreads();
        }
        return;
    }

    // ---------------- relation branch ----------------
    // W stack: re_W1(128) | re_W2(128) | rpW0(128) = 384 rows
    for (int idx = tid; idx < 384 * 16; idx += 512) {
        int r = idx >> 4, c8 = (idx & 15) * 8;
        const __nv_bfloat16* src;
        if (r < 128)      src = a.wbuf + (size_t)(WO_RE1 + r) * 128 + c8;
        else if (r < 256) src = a.wbuf + (size_t)(WO_RE2 + r - 128) * 128 + c8;
        else              src = a.wbuf + (size_t)(WO_RP + r - 256) * 128 + c8;
        *(uint4*)&Wsm[r * 136 + c8] = *(const uint4*)src;
    }
    for (int i = tid; i < 128; i += 512) {
        biasm[128 + i] = a.re_b1[i];
        biasm[256 + i] = a.re_b2[i];
        biasm[384 + i] = a.rp_b[i];
        biasm[512 + i] = a.reW0f[42 * 128 + i];      // w42 (f32)
    }
    if (tid < 128)      idxs[tid]       = a.rr[rowBase + tid];
    else if (tid < 256) idxs[tid]       = a.rs[rowBase + tid - 128];
    __syncthreads();

    if (tid < 128) {                                  // gdiff per edge
        int gr = idxs[tid], gs = idxs[128 + tid];
        int br = gr >> 11, ir = gr & (NN - 1), is_ = gs & (NN - 1);
        float acc = 0.f;
#pragma unroll
        for (int j = 0; j < 8; j++) {
            float x = (ir < NP) ? a.pinst[((size_t)br * NP + ir) * 8 + j] : 0.f;
            float c = (is_ < NP) ? a.pinst[((size_t)br * NP + is_) * 8 + j] : 0.f;
            acc += fabsf(x - c);
        }
        gdm[tid] = acc;
    }
    __syncthreads();

    // rel0 = relu(F[rr] + G[rs] + gd*w42)  (re_b0 folded into F)
#pragma unroll
    for (int it = 0; it < 8; it++) {
        int e = tid + it * 512, row = e >> 5, c4 = (e & 31) * 4;
        int gr = idxs[row], gs = idxs[128 + row];
        float4 f = *(const float4*)&a.F[(size_t)gr * 128 + c4];
        float4 g = *(const float4*)&a.G[(size_t)gs * 128 + c4];
        float gd = gdm[row];
        float4 w = *(const float4*)&biasm[512 + c4];
        float4 v;
        v.x = fmaxf(f.x + g.x + gd * w.x, 0.f);
        v.y = fmaxf(f.y + g.y + gd * w.y, 0.f);
        v.z = fmaxf(f.z + g.z + gd * w.z, 0.f);
        v.w = fmaxf(f.w + g.w + gd * w.w, 0.f);
        uint2 o; o.x = pack_bf2(v.x, v.y); o.y = pack_bf2(v.z, v.w);
        *(uint2*)&Act[row * 136 + c4] = o;
    }
    __syncthreads();

    // L1, L2 (relu, Act-resident), L4 (relBase, no relu)
    for (int L = 1; L <= 3; L++) {
        const __nv_bfloat16* WL = Wsm + (size_t)((L - 1) * 128) * 136;
        wmma::fragment<wmma::accumulator, 16, 16, 16, float> acc[4];
#pragma unroll
        for (int nf = 0; nf < 4; nf++) wmma::fill_fragment(acc[nf], 0.f);
#pragma unroll
        for (int kc = 0; kc < 8; kc++) {
            wmma::fragment<wmma::matrix_a, 16, 16, 16, __nv_bfloat16, wmma::row_major> af;
            wmma::load_matrix_sync(af, Act + (wm * 16) * 136 + kc * 16, 136);
#pragma unroll
            for (int nf = 0; nf < 4; nf++) {
                wmma::fragment<wmma::matrix_b, 16, 16, 16, __nv_bfloat16, wmma::row_major> bf;
                wmma::load_matrix_sync(bf, WL + (kc * 16) * 136 + wn * 64 + nf * 16, 136);
                wmma::mma_sync(acc[nf], af, bf, acc[nf]);
            }
        }
        __syncthreads();
#pragma unroll
        for (int nf = 0; nf < 4; nf++)
            wmma::store_matrix_sync(Cs + (wm * 16) * 132 + wn * 64 + nf * 16,
                                    acc[nf], 132, wmma::mem_row_major);
        __syncthreads();
        if (L < 3) {
            const float* bL = biasm + L * 128;
#pragma unroll
            for (int it = 0; it < 8; it++) {
                int e = tid + it * 512, row = e >> 5, c4 = (e & 31) * 4;
                float4 v = *(float4*)&Cs[row * 132 + c4];
                float4 b = *(const float4*)&bL[c4];
                uint2 o;
                o.x = pack_bf2(fmaxf(v.x + b.x, 0.f), fmaxf(v.y + b.y, 0.f));
                o.y = pack_bf2(fmaxf(v.z + b.z, 0.f), fmaxf(v.w + b.w, 0.f));
                *(uint2*)&Act[row * 136 + c4] = o;
            }
        } else {
            const float* bR = biasm + 384;
#pragma unroll
            for (int it = 0; it < 8; it++) {
                int e = tid + it * 512, row = e >> 5, c4 = (e & 31) * 4;
                float4 v = *(float4*)&Cs[row * 132 + c4];
                float4 b = *(const float4*)&bR[c4];
                v.x += b.x; v.y += b.y; v.z += b.z; v.w += b.w;  // NO relu
                *(float4*)&a.relBase[(size_t)(rowBase + row) * 128 + c4] = v;
            }
        }
        __syncthreads();
    }
}

// =============  relation propagator v3 (R14-proven): K=256, relBase init ====
#define R3A_LD 264
#define R3_W_OFF   (128*R3A_LD*2)                  // 67584
#define R3_IDX_OFF (R3_W_OFF + 256*136*2)          // 137216
#define R3_SMEM    (R3_IDX_OFF + 256*4)            // 138240

__global__ void __launch_bounds__(512) relprop_k(
    const __nv_bfloat16* __restrict__ pEff,
    const __nv_bfloat16* __restrict__ W,
    const float* __restrict__ relBase,
    __nv_bfloat16* __restrict__ aggH,
    const int* __restrict__ rr, const int* __restrict__ rs)
{
    extern __shared__ char sm[];
    __nv_bfloat16* Asm = (__nv_bfloat16*)sm;
    __nv_bfloat16* Wsm = (__nv_bfloat16*)(sm + R3_W_OFF);
    int*   idxs        = (int*)(sm + R3_IDX_OFF);
    float* Cs          = (float*)sm;                 // overlay A post-mainloop

    int tid = threadIdx.x, wid = tid >> 5;
    int wm = wid & 7, wn = wid >> 3;                 // 8 row x 2 col warp groups
    int rowBase = blockIdx.x * 128;

    if (tid < 128)      idxs[tid] = rr[rowBase + tid];
    else if (tid < 256) idxs[tid] = rs[rowBase + tid - 128];
    __syncthreads();                                 // idxs visible for gather

    uint32_t asB = (uint32_t)__cvta_generic_to_shared(Asm);
    uint32_t wsB = (uint32_t)__cvta_generic_to_shared(Wsm);

    for (int c = tid; c < 128 * 32; c += 512) {
        int row = c >> 5, ch = c & 31;
        int seg = ch >> 4, off = (ch & 15) * 8;
        const __nv_bfloat16* src = (seg == 0)
            ? pEff + (size_t)idxs[row] * 128 + off
            : pEff + (size_t)idxs[128 + row] * 128 + off;
        cpa16(asB + (uint32_t)(row * R3A_LD + seg * 128 + off) * 2, src);
    }
    for (int c = tid; c < 256 * 16; c += 512) {
        int row = c >> 4, c8 = (c & 15) * 8;
        cpa16(wsB + (uint32_t)(row * 136 + c8) * 2, W + (size_t)row * 128 + c8);
    }
    cp_commit();

    wmma::fragment<wmma::accumulator, 16, 16, 16, float> acc[4];
#pragma unroll
    for (int nf = 0; nf < 4; nf++)
        wmma::load_matrix_sync(acc[nf],
            relBase + (size_t)(rowBase + wm * 16) * 128 + wn * 64 + nf * 16,
            128, wmma::mem_row_major);

    cp_wait0();
    __syncthreads();

    for (int kt = 0; kt < 16; kt++) {
        wmma::fragment<wmma::matrix_a, 16, 16, 16, __nv_bfloat16, wmma::row_major> af;
        wmma::load_matrix_sync(af, Asm + (wm * 16) * R3A_LD + kt * 16, R3A_LD);
#pragma unroll
        for (int nf = 0; nf < 4; nf++) {
            wmma::fragment<wmma::matrix_b, 16, 16, 16, __nv_bfloat16, wmma::row_major> bf;
            wmma::load_matrix_sync(bf, Wsm + (kt * 16) * 136 + wn * 64 + nf * 16, 136);
            wmma::mma_sync(acc[nf], af, bf, acc[nf]);
        }
    }
    __syncthreads();                                 // A reads done before overlay
#pragma unroll
    for (int nf = 0; nf < 4; nf++)
        wmma::store_matrix_sync(Cs + (wm * 16) * 132 + wn * 64 + nf * 16,
                                acc[nf], 132, wmma::mem_row_major);
    __syncthreads();
#pragma unroll
    for (int it = 0; it < 8; it++) {
        int e = tid + it * 512, row = e >> 5, c4 = (e & 31) * 4;
        float4 v = *(float4*)&Cs[row * 132 + c4];
        __nv_bfloat162* dst =
            (__nv_bfloat162*)(aggH + (size_t)idxs[row] * 128 + c4);
        atomicAdd(dst,     __floats2bfloat162_rn(fmaxf(v.x, 0.f), fmaxf(v.y, 0.f)));
        atomicAdd(dst + 1, __floats2bfloat162_rn(fmaxf(v.z, 0.f), fmaxf(v.w, 0.f)));
    }
}

// =============  particle propagator v4 (R13-proven): N-split, zero-free =====
#define PPA_LD 264
#define P4_W_OFF    (32*PPA_LD*2)                  // 16896
#define P4_RES_OFF  (P4_W_OFF + 256*72*2)          // 53760
#define P4_BIAS_OFF (P4_RES_OFF + 32*80*2)         // 58880
#define P4_SMEM     (P4_BIAS_OFF + 256)            // 59136

__global__ void __launch_bounds__(256) partprop_k(
    const __nv_bfloat16* __restrict__ pEnc,
    const __nv_bfloat16* __restrict__ aggIn,
    const __nv_bfloat16* __restrict__ W,
    const float* __restrict__ bias,
    __nv_bfloat16* __restrict__ pEff)
{
    extern __shared__ char sm[];
    __nv_bfloat16* Asm  = (__nv_bfloat16*)sm;
    __nv_bfloat16* Wsm  = (__nv_bfloat16*)(sm + P4_W_OFF);
    __nv_bfloat16* Res  = (__nv_bfloat16*)(sm + P4_RES_OFF);
    float* biasm        = (float*)(sm + P4_BIAS_OFF);
    float* Cs           = (float*)sm;                // overlays Asm post-mainloop

    int tid = threadIdx.x, wid = tid >> 5;
    int wm = wid & 1, wn = wid >> 1;                 // 2 row x 4 col warp groups
    int t = blockIdx.x >> 1, half = blockIdx.x & 1;
    int rowBase = t * 32;
    int colBase = half * 64;

    if (tid < 64) biasm[tid] = bias[colBase + tid];

    uint32_t asB = (uint32_t)__cvta_generic_to_shared(Asm);
    uint32_t wsB = (uint32_t)__cvta_generic_to_shared(Wsm);
    uint32_t reB = (uint32_t)__cvta_generic_to_shared(Res);

    for (int c = tid; c < 32 * 32; c += 256) {
        int row = c >> 5, off = (c & 31) * 8;
        const __nv_bfloat16* src;
        if (off < 128) src = pEnc  + (size_t)(rowBase + row) * 128 + off;
        else           src = aggIn + (size_t)(rowBase + row) * 128 + (off - 128);
        cpa16(asB + (uint32_t)(row * PPA_LD + off) * 2, src);
    }
    for (int c = tid; c < 256 * 8; c += 256) {
        int row = c >> 3, c8 = (c & 7) * 8;
        cpa16(wsB + (uint32_t)(row * 72 + c8) * 2,
              W + (size_t)row * 128 + colBase + c8);
    }
    for (int c = tid; c < 32 * 8; c += 256) {
        int row = c >> 3, c8 = (c & 7) * 8;
        cpa16(reB + (uint32_t)(row * 80 + c8) * 2,
              pEff + (size_t)(rowBase + row) * 128 + colBase + c8);
    }
    cp_commit(); cp_wait0();
    __syncthreads();

    wmma::fragment<wmma::accumulator, 16, 16, 16, float> acc;
    wmma::fill_fragment(acc, 0.f);
    for (int kt = 0; kt < 16; kt++) {
        wmma::fragment<wmma::matrix_a, 16, 16, 16, __nv_bfloat16, wmma::row_major> af;
        wmma::load_matrix_sync(af, Asm + (wm * 16) * PPA_LD + kt * 16, PPA_LD);
        wmma::fragment<wmma::matrix_b, 16, 16, 16, __nv_bfloat16, wmma::row_major> bf;
        wmma::load_matrix_sync(bf, Wsm + (kt * 16) * 72 + wn * 16, 72);
        wmma::mma_sync(acc, af, bf, acc);
    }
    __syncthreads();
    wmma::store_matrix_sync(Cs + (wm * 16) * 68 + wn * 16, acc, 68,
                            wmma::mem_row_major);
    __syncthreads();
#pragma unroll
    for (int it = 0; it < 2; it++) {
        int e = tid + it * 256, row = e >> 4, c4 = (e & 15) * 4;
        float4 v = *(float4*)&Cs[row * 68 + c4];
        float4 b = *(const float4*)&biasm[c4];
        uint2 rv = *(const uint2*)&Res[row * 80 + c4];
        float2 r0 = unpack_bf2(rv.x), r1 = unpack_bf2(rv.y);
        v.x = fmaxf(v.x + b.x + r0.x, 0.f);
        v.y = fmaxf(v.y + b.y + r0.y, 0.f);
        v.z = fmaxf(v.z + b.z + r1.x, 0.f);
        v.w = fmaxf(v.w + b.w + r1.y, 0.f);
        uint2 o; o.x = pack_bf2(v.x, v.y); o.y = pack_bf2(v.z, v.w);
        *(uint2*)&pEff[(size_t)(rowBase + row) * 128 + colBase + c4] = o;
    }
}

// =============  final particle propagator with fused head (R12-proven) ======
#define PH_W_OFF    (32*PPA_LD*2)                  // 16896
#define PH_NW_OFF   (PH_W_OFF + 256*136*2)         // 86528
#define PH_BIAS_OFF (PH_NW_OFF + 256*136*2)        // 156160
#define PH_NB0_OFF  (PH_BIAS_OFF + 512)            // 156672
#define PH_NB1_OFF  (PH_NB0_OFF + 512)             // 157184
#define PH_W2_OFF   (PH_NB1_OFF + 512)             // 157696
#define PH_B2_OFF   (PH_W2_OFF + 1536)             // 159232
#define PH_ACT_OFF  (PH_B2_OFF + 16)               // 159248
#define PH_SMEM     (PH_ACT_OFF + 32*136*2)        // 167952

__global__ void __launch_bounds__(512) partproph_k(
    const __nv_bfloat16* __restrict__ pEnc,
    const __nv_bfloat16* __restrict__ aggIn,
    const __nv_bfloat16* __restrict__ W,
    const float* __restrict__ bias,
    const __nv_bfloat16* __restrict__ pEff,
    const __nv_bfloat16* __restrict__ npW,
    const float* __restrict__ nb0, const float* __restrict__ nb1,
    const float* __restrict__ W2, const float* __restrict__ b2,
    const float* __restrict__ state, float* __restrict__ out)
{
    extern __shared__ char sm[];
    __nv_bfloat16* Asm  = (__nv_bfloat16*)sm;
    __nv_bfloat16* Wsm  = (__nv_bfloat16*)(sm + PH_W_OFF);
    __nv_bfloat16* NWsm = (__nv_bfloat16*)(sm + PH_NW_OFF);
    float* biasm        = (float*)(sm + PH_BIAS_OFF);
    float* nb0s         = (float*)(sm + PH_NB0_OFF);
    float* nb1s         = (float*)(sm + PH_NB1_OFF);
    float* W2s          = (float*)(sm + PH_W2_OFF);
    float* b2s          = (float*)(sm + PH_B2_OFF);
    __nv_bfloat16* Act  = (__nv_bfloat16*)(sm + PH_ACT_OFF);
    float* Cs           = (float*)sm;

    int tid = threadIdx.x, wid = tid >> 5, lane = tid & 31;
    int wm = wid & 1, wn = wid >> 1;                 // 2 row x 8 col warp groups
    int rowBase = blockIdx.x * 32;

    for (int i = tid; i < 128; i += 512) {
        biasm[i] = bias[i]; nb0s[i] = nb0[i]; nb1s[i] = nb1[i];
    }
    for (int i = tid; i < 384; i += 512) W2s[i] = W2[i];
    if (tid < 3) b2s[tid] = b2[tid];

    uint32_t asB = (uint32_t)__cvta_generic_to_shared(Asm);
    uint32_t wsB = (uint32_t)__cvta_generic_to_shared(Wsm);
    uint32_t nwB = (uint32_t)__cvta_generic_to_shared(NWsm);

    for (int c = tid; c < 32 * 32; c += 512) {
        int row = c >> 5, off = (c & 31) * 8;
        const __nv_bfloat16* src;
        if (off < 128) src = pEnc  + (size_t)(rowBase + row) * 128 + off;
        else           src = aggIn + (size_t)(rowBase + row) * 128 + (off - 128);
        cpa16(asB + (uint32_t)(row * PPA_LD + off) * 2, src);
    }
    for (int c = tid; c < 256 * 16; c += 512) {
        int row = c >> 4, c8 = (c & 15) * 8;
        cpa16(wsB + (uint32_t)(row * 136 + c8) * 2, W + (size_t)row * 128 + c8);
        cpa16(nwB + (uint32_t)(row * 136 + c8) * 2, npW + (size_t)row * 128 + c8);
    }
    cp_commit(); cp_wait0();
    __syncthreads();

    wmma::fragment<wmma::accumulator, 16, 16, 16, float> acc;
    wmma::fill_fragment(acc, 0.f);
    for (int kt = 0; kt < 16; kt++) {
        wmma::fragment<wmma::matrix_a, 16, 16, 16, __nv_bfloat16, wmma::row_major> af;
        wmma::load_matrix_sync(af, Asm + (wm * 16) * PPA_LD + kt * 16, PPA_LD);
        wmma::fragment<wmma::matrix_b, 16, 16, 16, __nv_bfloat16, wmma::row_major> bf;
        wmma::load_matrix_sync(bf, Wsm + (kt * 16) * 136 + wn * 16, 136);
        wmma::mma_sync(acc, af, bf, acc);
    }
    __syncthreads();
    wmma::store_matrix_sync(Cs + (wm * 16) * 132 + wn * 16, acc, 132,
                            wmma::mem_row_major);
    __syncthreads();
#pragma unroll
    for (int it = 0; it < 2; it++) {
        int e = tid + it * 512, row = e >> 5, c4 = (e & 31) * 4;
        size_t go = (size_t)(rowBase + row) * 128 + c4;
        float4 v = *(float4*)&Cs[row * 132 + c4];
        float4 b = *(const float4*)&biasm[c4];
        uint2 rv = *(const uint2*)&pEff[go];
        float2 r0 = unpack_bf2(rv.x), r1 = unpack_bf2(rv.y);
        v.x = fmaxf(v.x + b.x + r0.x, 0.f);
        v.y = fmaxf(v.y + b.y + r0.y, 0.f);
        v.z = fmaxf(v.z + b.z + r1.x, 0.f);
        v.w = fmaxf(v.w + b.w + r1.y, 0.f);
        uint2 o; o.x = pack_bf2(v.x, v.y); o.y = pack_bf2(v.z, v.w);
        *(uint2*)&Act[row * 136 + c4] = o;           // smem only
    }
    __syncthreads();

    // np0
    {
        wmma::fragment<wmma::accumulator, 16, 16, 16, float> a2;
        wmma::fill_fragment(a2, 0.f);
#pragma unroll
        for (int kt = 0; kt < 8; kt++) {
            wmma::fragment<wmma::matrix_a, 16, 16, 16, __nv_bfloat16, wmma::row_major> af;
            wmma::load_matrix_sync(af, Act + (wm * 16) * 136 + kt * 16, 136);
            wmma::fragment<wmma::matrix_b, 16, 16, 16, __nv_bfloat16, wmma::row_major> bf;
            wmma::load_matrix_sync(bf, NWsm + (kt * 16) * 136 + wn * 16, 136);
            wmma::mma_sync(a2, af, bf, a2);
        }
        __syncthreads();
        wmma::store_matrix_sync(Cs + (wm * 16) * 132 + wn * 16, a2, 132,
                                wmma::mem_row_major);
        __syncthreads();
#pragma unroll
        for (int it = 0; it < 2; it++) {
            int e = tid + it * 512, row = e >> 5, c4 = (e & 31) * 4;
            float4 v = *(float4*)&Cs[row * 132 + c4];
            float4 b = *(const float4*)&nb0s[c4];
            uint2 o;
            o.x = pack_bf2(fmaxf(v.x + b.x, 0.f), fmaxf(v.y + b.y, 0.f));
            o.y = pack_bf2(fmaxf(v.z + b.z, 0.f), fmaxf(v.w + b.w, 0.f));
            *(uint2*)&Act[row * 136 + c4] = o;
        }
        __syncthreads();
    }
    // np1
    {
        wmma::fragment<wmma::accumulator, 16, 16, 16, float> a2;
        wmma::fill_fragment(a2, 0.f);
#pragma unroll
        for (int kt = 0; kt < 8; kt++) {
            wmma::fragment<wmma::matrix_a, 16, 16, 16, __nv_bfloat16, wmma::row_major> af;
            wmma::load_matrix_sync(af, Act + (wm * 16) * 136 + kt * 16, 136);
            wmma::fragment<wmma::matrix_b, 16, 16, 16, __nv_bfloat16, wmma::row_major> bf;
            wmma::load_matrix_sync(bf, NWsm + ((128 + kt * 16)) * 136 + wn * 16, 136);
            wmma::mma_sync(a2, af, bf, a2);
        }
        __syncthreads();
        wmma::store_matrix_sync(Cs + (wm * 16) * 132 + wn * 16, a2, 132,
                                wmma::mem_row_major);
        __syncthreads();
    }
    // final: h1 = relu(Cs + nb1); motion = h1 @ W2 + b2; clamp; add
#pragma unroll
    for (int i = 0; i < 2; i++) {
        int row = wid * 2 + i;
        int grow = rowBase + row;
        int b = grow >> 11, n = grow & (NN - 1);
        float hv[4];
#pragma unroll
        for (int j = 0; j < 4; j++)
            hv[j] = fmaxf(Cs[row * 132 + lane + 32 * j] + nb1s[lane + 32 * j], 0.f);
#pragma unroll
        for (int k = 0; k < 3; k++) {
            float sacc = 0.f;
#pragma unroll
            for (int j = 0; j < 4; j++)
                sacc += hv[j] * W2s[(lane + 32 * j) * 3 + k];
#pragma unroll
            for (int off = 16; off; off >>= 1)
                sacc += __shfl_xor_sync(0xffffffffu, sacc, off);
            if (lane == 0 && n < NP) {
                float m = fminf(fmaxf(sacc + b2s[k], -100.f), 100.f);
                out[((size_t)b * NP + n) * 3 + k] =
                    state[((size_t)(b * 4 + 3) * NN + n) * 3 + k] + m;
            }
        }
    }
}

// ---------------------------------------------------------------------------
extern "C" void kernel_launch(void* const* d_in, const int* in_sizes, int n_in,
                              void* d_out, int out_size) {
    const float* state  = (const float*)d_in[0];
    const float* attrs  = (const float*)d_in[1];
    const float* Rr     = (const float*)d_in[2];
    const float* Rs     = (const float*)d_in[3];
    const float* pinst  = (const float*)d_in[4];
    const float* action = (const float*)d_in[5];
    const float* pden   = (const float*)d_in[6];
    const float* phys   = (const float*)d_in[7];
    const float* pe_W0 = (const float*)d_in[8],  *pe_b0 = (const float*)d_in[9];
    const float* pe_W1 = (const float*)d_in[10], *pe_b1 = (const float*)d_in[11];
    const float* pe_W2 = (const float*)d_in[12], *pe_b2 = (const float*)d_in[13];
    const float* re_W0 = (const float*)d_in[14], *re_b0 = (const float*)d_in[15];
    const float* re_W1 = (const float*)d_in[16], *re_b1 = (const float*)d_in[17];
    const float* re_W2 = (const float*)d_in[18], *re_b2 = (const float*)d_in[19];
    const float* pp_W  = (const float*)d_in[20], *pp_b  = (const float*)d_in[21];
    const float* rp_W  = (const float*)d_in[22], *rp_b  = (const float*)d_in[23];
    const float* np_W0 = (const float*)d_in[24], *np_b0 = (const float*)d_in[25];
    const float* np_W1 = (const float*)d_in[26], *np_b1 = (const float*)d_in[27];
    const float* np_W2 = (const float*)d_in[28], *np_b2 = (const float*)d_in[29];
    float* out = (float*)d_out;

    float *pin_f, *relBase, *Fg, *Gg;
    __nv_bfloat16 *pEnc, *pEff, *aggH, *wbuf;
    int *rr, *rs;
    cudaGetSymbolAddress((void**)&pin_f,   g_pin_f);
    cudaGetSymbolAddress((void**)&pEnc,    g_pEnc);
    cudaGetSymbolAddress((void**)&pEff,    g_pEff);
    cudaGetSymbolAddress((void**)&Fg,      g_F);
    cudaGetSymbolAddress((void**)&Gg,      g_G);
    cudaGetSymbolAddress((void**)&relBase, g_relBase);
    cudaGetSymbolAddress((void**)&aggH,    g_aggH);
    cudaGetSymbolAddress((void**)&rr,      g_rr);
    cudaGetSymbolAddress((void**)&rs,      g_rs);
    cudaGetSymbolAddress((void**)&wbuf,    g_wbuf);

    cudaFuncSetAttribute(encmlp_k,   cudaFuncAttributeMaxDynamicSharedMemorySize, E3_SMEM);
    cudaFuncSetAttribute(relprop_k,  cudaFuncAttributeMaxDynamicSharedMemorySize, R3_SMEM);
    cudaFuncSetAttribute(partprop_k, cudaFuncAttributeMaxDynamicSharedMemorySize, P4_SMEM);
    cudaFuncSetAttribute(partproph_k,cudaFuncAttributeMaxDynamicSharedMemorySize, PH_SMEM);

    WConvArgs wa;
    const float* srcs[10] = {pe_W0, pe_W1, pe_W2, re_W0, re_W1, re_W2,
                             pp_W, rp_W, np_W0, np_W1};
    const int starts[10]  = {WO_PE0, WO_PE1, WO_PE2, WO_RE0, WO_RE1, WO_RE2,
                             WO_PP, WO_RP, WO_NP0, WO_NP1};
    const int srows[10]   = {19, 128, 128, 56, 128, 128, 256, 384, 128, 128};
    for (int i = 0; i < 10; i++) {
        wa.src[i] = srcs[i]; wa.rowStart[i] = starts[i]; wa.srcRows[i] = srows[i];
    }

    // 1) convert weights + build pin + F/G + extract indices
    prep_k<<<4096, 256>>>(Rr, Rs, rr, rs, state, attrs, action, pden, phys,
                          pin_f, wa, wbuf, re_W0, re_b0, Fg, Gg);

    // 2) fused encoders (relation branch uses F/G; produces relBase)
    EncArgs ea;
    ea.pf = pin_f; ea.pinst = pinst; ea.reW0f = re_W0; ea.F = Fg; ea.G = Gg;
    ea.rr = rr; ea.rs = rs; ea.wbuf = wbuf;
    ea.pe_b0 = pe_b0; ea.pe_b1 = pe_b1; ea.pe_b2 = pe_b2;
    ea.re_b1 = re_b1; ea.re_b2 = re_b2; ea.rp_b = rp_b;
    ea.pEnc = pEnc; ea.pEff = pEff; ea.agg = aggH;
    ea.relBase = relBase;
    encmlp_k<<<160, 512, E3_SMEM>>>(ea);

    // 3) propagation: rotating agg buffers; relprop K=256 w/ relBase acc-init
    const __nv_bfloat16* npW = wbuf + WO_NP0 * 128;
    const __nv_bfloat16* rpW2 = wbuf + (WO_RP + 128) * 128;   // rp_W rows 128..384
    for (int step = 0; step < 2; step++) {
        __nv_bfloat16* buf = aggH + (size_t)step * NODES * NF;
        relprop_k<<<BNR / 128, 512, R3_SMEM>>>(pEff, rpW2, relBase, buf, rr, rs);
        partprop_k<<<(NODES / 32) * 2, 256, P4_SMEM>>>(
            pEnc, buf, wbuf + WO_PP * 128, pp_b, pEff);
    }
    __nv_bfloat16* buf2 = aggH + (size_t)2 * NODES * NF;
    relprop_k<<<BNR / 128, 512, R3_SMEM>>>(pEff, rpW2, relBase, buf2, rr, rs);
    partproph_k<<<NODES / 32, 512, PH_SMEM>>>(
        pEnc, buf2, wbuf + WO_PP * 128, pp_b, pEff,
        npW, np_b0, np_b1, np_W2, np_b2, state, out);
}